// round 1
// baseline (speedup 1.0000x reference)
#include <cuda_runtime.h>
#include <math.h>

#define S_LEN  4096
#define DMODEL 2048
#define NHEADS 16
#define HDIM   128
#define WIN    512

// Scratch (allocation-free rule: __device__ globals)
__device__ float g_q[S_LEN * DMODEL];
__device__ float g_k[S_LEN * DMODEL];
__device__ float g_v[S_LEN * DMODEL];
__device__ float g_att[S_LEN * DMODEL];

// ---------------------------------------------------------------------------
// SGEMM: C[M,N] = A[M,K] @ B[N,K]^T   (all row-major, M,N,K multiples of 128/8)
// 128x128 block tile, BK=8, 256 threads, 8x8 per-thread micro-tile.
// ---------------------------------------------------------------------------
__global__ __launch_bounds__(256) void sgemm_nt(const float* __restrict__ A,
                                                const float* __restrict__ B,
                                                float* __restrict__ C,
                                                int M, int N, int K) {
    __shared__ float As[8][128];
    __shared__ float Bs[8][128];

    const int tid = threadIdx.x;
    const int m0 = blockIdx.y * 128;
    const int n0 = blockIdx.x * 128;
    const int ty = tid >> 4;       // 0..15
    const int tx = tid & 15;       // 0..15
    const int lrow = tid >> 1;     // 0..127
    const int lk4  = (tid & 1) << 2; // 0 or 4

    const float* Ap = A + (size_t)(m0 + lrow) * K + lk4;
    const float* Bp = B + (size_t)(n0 + lrow) * K + lk4;

    float acc[8][8];
#pragma unroll
    for (int i = 0; i < 8; i++)
#pragma unroll
        for (int j = 0; j < 8; j++) acc[i][j] = 0.f;

    for (int k0 = 0; k0 < K; k0 += 8) {
        float4 va = *(const float4*)(Ap + k0);
        float4 vb = *(const float4*)(Bp + k0);
        As[lk4 + 0][lrow] = va.x; As[lk4 + 1][lrow] = va.y;
        As[lk4 + 2][lrow] = va.z; As[lk4 + 3][lrow] = va.w;
        Bs[lk4 + 0][lrow] = vb.x; Bs[lk4 + 1][lrow] = vb.y;
        Bs[lk4 + 2][lrow] = vb.z; Bs[lk4 + 3][lrow] = vb.w;
        __syncthreads();

#pragma unroll
        for (int kk = 0; kk < 8; kk++) {
            float a[8], b[8];
            *(float4*)&a[0] = *(const float4*)&As[kk][ty * 8];
            *(float4*)&a[4] = *(const float4*)&As[kk][ty * 8 + 4];
            *(float4*)&b[0] = *(const float4*)&Bs[kk][tx * 8];
            *(float4*)&b[4] = *(const float4*)&Bs[kk][tx * 8 + 4];
#pragma unroll
            for (int i = 0; i < 8; i++)
#pragma unroll
                for (int j = 0; j < 8; j++)
                    acc[i][j] = fmaf(a[i], b[j], acc[i][j]);
        }
        __syncthreads();
    }

#pragma unroll
    for (int i = 0; i < 8; i++) {
        float* cp = C + (size_t)(m0 + ty * 8 + i) * N + n0 + tx * 8;
        *(float4*)cp       = make_float4(acc[i][0], acc[i][1], acc[i][2], acc[i][3]);
        *(float4*)(cp + 4) = make_float4(acc[i][4], acc[i][5], acc[i][6], acc[i][7]);
    }
}

// ---------------------------------------------------------------------------
// RoPE in place on Q and K. One thread per (s, h, t) pair (t = 0..63).
// inv_freq = 10000^(-t/64) computed via exp2f (accurate to ~1-2 ulp).
// ---------------------------------------------------------------------------
__global__ __launch_bounds__(256) void rope_kernel(float* __restrict__ q,
                                                   float* __restrict__ k) {
    int idx = blockIdx.x * blockDim.x + threadIdx.x;
    if (idx >= S_LEN * NHEADS * 64) return;
    int t = idx & 63;
    int h = (idx >> 6) & (NHEADS - 1);
    int s = idx >> 10;

    // log2(10000)/64 = 0.207620505930457...
    float inv_freq = exp2f(-(float)t * 0.20762050593045702f);
    float ang = (float)s * inv_freq;
    float sn, cs;
    sincosf(ang, &sn, &cs);

    int base = s * DMODEL + h * HDIM + 2 * t;
    float x1 = q[base], x2 = q[base + 1];
    q[base]     = x1 * cs - x2 * sn;
    q[base + 1] = x1 * sn + x2 * cs;
    x1 = k[base]; x2 = k[base + 1];
    k[base]     = x1 * cs - x2 * sn;
    k[base + 1] = x1 * sn + x2 * cs;
}

// ---------------------------------------------------------------------------
// Sliding-window attention, flash-style online softmax.
// Block = (16 queries) x (1 head), 16 warps, warp-per-query.
// K/V staged through shared memory in 32-key chunks.
// ---------------------------------------------------------------------------
__global__ __launch_bounds__(512) void attn_kernel(const float* __restrict__ q,
                                                   const float* __restrict__ k,
                                                   const float* __restrict__ v,
                                                   float* __restrict__ out) {
    __shared__ float Ks[32][HDIM];
    __shared__ float Vs[32][HDIM];

    const int h    = blockIdx.y;
    const int q0   = blockIdx.x * 16;
    const int w    = threadIdx.x >> 5;
    const int lane = threadIdx.x & 31;
    const int qi   = q0 + w;
    const float SCALE = 0.088388347648318447f; // 1/sqrt(128)

    float qreg[4];
#pragma unroll
    for (int r = 0; r < 4; r++)
        qreg[r] = q[(size_t)qi * DMODEL + h * HDIM + lane + 32 * r];

    float m = -INFINITY, l = 0.f;
    float o[4] = {0.f, 0.f, 0.f, 0.f};

    int cbeg = max(0, q0 - (WIN - 1)) & ~31;
    int cend = q0 + 15;

    for (int c = cbeg; c <= cend; c += 32) {
        // Cooperative load of 32 keys/values (512 threads x 8 floats each)
        {
            int row = threadIdx.x >> 4;          // 0..31
            int col = (threadIdx.x & 15) * 8;    // 0..120
            int gk = c + row;
            if (gk < S_LEN) {
                const float* kp = k + (size_t)gk * DMODEL + h * HDIM + col;
                const float* vp = v + (size_t)gk * DMODEL + h * HDIM + col;
                *(float4*)&Ks[row][col]     = *(const float4*)kp;
                *(float4*)&Ks[row][col + 4] = *(const float4*)(kp + 4);
                *(float4*)&Vs[row][col]     = *(const float4*)vp;
                *(float4*)&Vs[row][col + 4] = *(const float4*)(vp + 4);
            }
        }
        __syncthreads();

        int jlo = max(c, qi - (WIN - 1));
        int jhi = min(c + 31, qi);
        for (int j = jlo - c; j <= jhi - c; j++) {
            float s_ = 0.f;
#pragma unroll
            for (int r = 0; r < 4; r++)
                s_ = fmaf(qreg[r], Ks[j][lane + 32 * r], s_);
#pragma unroll
            for (int off = 16; off > 0; off >>= 1)
                s_ += __shfl_xor_sync(0xffffffffu, s_, off);
            s_ *= SCALE;

            float mn   = fmaxf(m, s_);
            float corr = __expf(m - mn);
            float p    = __expf(s_ - mn);
            l = l * corr + p;
#pragma unroll
            for (int r = 0; r < 4; r++)
                o[r] = o[r] * corr + p * Vs[j][lane + 32 * r];
            m = mn;
        }
        __syncthreads();
    }

    float inv = 1.f / l;
#pragma unroll
    for (int r = 0; r < 4; r++)
        out[(size_t)qi * DMODEL + h * HDIM + lane + 32 * r] = o[r] * inv;
}

// ---------------------------------------------------------------------------
// Launch: Q/K/V proj -> RoPE -> attention -> out proj
// ---------------------------------------------------------------------------
extern "C" void kernel_launch(void* const* d_in, const int* in_sizes, int n_in,
                              void* d_out, int out_size) {
    const float* x  = (const float*)d_in[0];
    const float* Wq = (const float*)d_in[1];
    const float* Wk = (const float*)d_in[2];
    const float* Wv = (const float*)d_in[3];
    const float* Wo = (const float*)d_in[4];
    float* out = (float*)d_out;

    float *qp, *kp, *vp, *ap;
    cudaGetSymbolAddress((void**)&qp, g_q);
    cudaGetSymbolAddress((void**)&kp, g_k);
    cudaGetSymbolAddress((void**)&vp, g_v);
    cudaGetSymbolAddress((void**)&ap, g_att);

    dim3 gg(DMODEL / 128, S_LEN / 128);
    sgemm_nt<<<gg, 256>>>(x, Wq, qp, S_LEN, DMODEL, DMODEL);
    sgemm_nt<<<gg, 256>>>(x, Wk, kp, S_LEN, DMODEL, DMODEL);
    sgemm_nt<<<gg, 256>>>(x, Wv, vp, S_LEN, DMODEL, DMODEL);

    rope_kernel<<<(S_LEN * NHEADS * 64 + 255) / 256, 256>>>(qp, kp);

    attn_kernel<<<dim3(S_LEN / 16, NHEADS), 512>>>(qp, kp, vp, ap);

    sgemm_nt<<<gg, 256>>>(ap, Wo, out, S_LEN, DMODEL, DMODEL);
}

// round 3
// speedup vs baseline: 1.6200x; 1.6200x over previous
#include <cuda_runtime.h>
#include <cuda_bf16.h>
#include <math.h>
#include <stdint.h>

#define S_LEN  4096
#define DMODEL 2048
#define NHEADS 16
#define HDIM   128
#define WIN    512

// ---------------------------------------------------------------------------
// Scratch (__device__ globals: allocation-free rule)
// ---------------------------------------------------------------------------
__device__ float g_q[S_LEN * DMODEL];
__device__ float g_k[S_LEN * DMODEL];
__device__ float g_v[S_LEN * DMODEL];
__device__ float g_att[S_LEN * DMODEL];

__device__ __nv_bfloat16 g_x_hi[S_LEN * DMODEL];
__device__ __nv_bfloat16 g_x_lo[S_LEN * DMODEL];
__device__ __nv_bfloat16 g_a_hi[S_LEN * DMODEL];
__device__ __nv_bfloat16 g_a_lo[S_LEN * DMODEL];
__device__ __nv_bfloat16 g_wq_hi[DMODEL * DMODEL];
__device__ __nv_bfloat16 g_wq_lo[DMODEL * DMODEL];
__device__ __nv_bfloat16 g_wk_hi[DMODEL * DMODEL];
__device__ __nv_bfloat16 g_wk_lo[DMODEL * DMODEL];
__device__ __nv_bfloat16 g_wv_hi[DMODEL * DMODEL];
__device__ __nv_bfloat16 g_wv_lo[DMODEL * DMODEL];
__device__ __nv_bfloat16 g_wo_hi[DMODEL * DMODEL];
__device__ __nv_bfloat16 g_wo_lo[DMODEL * DMODEL];

// ---------------------------------------------------------------------------
// PTX primitives (all baseline sm_80+ — compile for plain sm_103)
// ---------------------------------------------------------------------------
__device__ __forceinline__ uint32_t smem_to_u32(const void* p) {
    uint32_t a;
    asm("{ .reg .u64 t; cvta.to.shared.u64 t, %1; cvt.u32.u64 %0, t; }"
        : "=r"(a) : "l"(p));
    return a;
}

#define CP_ASYNC16(dst, src) \
    asm volatile("cp.async.cg.shared.global [%0], [%1], 16;" \
        :: "r"(dst), "l"(src) : "memory")
#define CP_COMMIT() asm volatile("cp.async.commit_group;" ::: "memory")
#define CP_WAIT1()  asm volatile("cp.async.wait_group 1;" ::: "memory")
#define CP_WAIT0()  asm volatile("cp.async.wait_group 0;" ::: "memory")

#define LDM_X4(r, addr) \
    asm volatile("ldmatrix.sync.aligned.m8n8.x4.shared.b16 {%0,%1,%2,%3}, [%4];" \
        : "=r"((r)[0]), "=r"((r)[1]), "=r"((r)[2]), "=r"((r)[3]) : "r"(addr))

#define MMA_BF16(c, a, b0, b1) \
    asm volatile("mma.sync.aligned.m16n8k16.row.col.f32.bf16.bf16.f32 " \
        "{%0,%1,%2,%3}, {%4,%5,%6,%7}, {%8,%9}, {%0,%1,%2,%3};" \
        : "+f"((c)[0]), "+f"((c)[1]), "+f"((c)[2]), "+f"((c)[3]) \
        : "r"((a)[0]), "r"((a)[1]), "r"((a)[2]), "r"((a)[3]), "r"(b0), "r"(b1))

// ---------------------------------------------------------------------------
// fp32 -> (bf16 hi, bf16 lo) split conversion, 8 elems/thread
// ---------------------------------------------------------------------------
__global__ __launch_bounds__(256) void cvt_hilo(const float* __restrict__ src,
                                                __nv_bfloat16* __restrict__ hi,
                                                __nv_bfloat16* __restrict__ lo,
                                                int n8) {
    int i = blockIdx.x * blockDim.x + threadIdx.x;
    if (i >= n8) return;
    const float4* s4 = (const float4*)src + 2 * (size_t)i;
    float4 a = s4[0], b = s4[1];
    float v[8] = {a.x, a.y, a.z, a.w, b.x, b.y, b.z, b.w};
    __align__(16) __nv_bfloat16 h[8];
    __align__(16) __nv_bfloat16 l[8];
#pragma unroll
    for (int j = 0; j < 8; j++) {
        h[j] = __float2bfloat16_rn(v[j]);
        l[j] = __float2bfloat16_rn(v[j] - __bfloat162float(h[j]));
    }
    ((uint4*)hi)[i] = *(const uint4*)h;
    ((uint4*)lo)[i] = *(const uint4*)l;
}

// ---------------------------------------------------------------------------
// HMMA GEMM:  C[M,2048] = A @ B^T, A/B given as bf16 (hi,lo) pairs.
// 128x128 tile/CTA, BK=32, 2-stage cp.async pipeline, 8 warps (64x32 each),
// 3 MMAs per fragment pair (AhBh + AhBl + AlBh).
// Row-major A [M,K]; B [N,K] row-major == col-major [K,N] for mma row.col.
// ---------------------------------------------------------------------------
#define GK DMODEL
#define PAD_ROW_B 80                 // 32 bf16 + 8 pad = 40 bf16 = 80 bytes
#define TILE_B (128 * PAD_ROW_B)     // 10240
#define STAGE_B (4 * TILE_B)         // Ahi, Alo, Bhi, Blo = 40960
#define GEMM_SMEM (2 * STAGE_B)      // 81920

__global__ __launch_bounds__(256, 1) void gemm_hmma3(
    const __nv_bfloat16* __restrict__ Ahi, const __nv_bfloat16* __restrict__ Alo,
    const __nv_bfloat16* __restrict__ Bhi, const __nv_bfloat16* __restrict__ Blo,
    float* __restrict__ C) {
    extern __shared__ char smem[];
    const uint32_t sbase = smem_to_u32(smem);
    const int tid  = threadIdx.x;
    const int wid  = tid >> 5;
    const int lane = tid & 31;
    const int wm   = wid & 1;        // 2 m-blocks of 64
    const int wn   = wid >> 1;       // 4 n-blocks of 32
    const int m0   = blockIdx.y * 128;
    const int n0   = blockIdx.x * 128;

    const __nv_bfloat16* gsrc[4] = {
        Ahi + (size_t)m0 * GK, Alo + (size_t)m0 * GK,
        Bhi + (size_t)n0 * GK, Blo + (size_t)n0 * GK};

    // Per-thread load mapping (8 x 16B chunks per stage)
    int l_tile[8], l_row[8], l_c16[8];
#pragma unroll
    for (int t = 0; t < 8; t++) {
        int linear = t * 256 + tid;
        l_tile[t] = linear >> 9;          // 512 chunks per tile
        int within = linear & 511;
        l_row[t] = within >> 2;
        l_c16[t] = within & 3;
    }

    // Prologue: stage 0
#pragma unroll
    for (int t = 0; t < 8; t++) {
        const __nv_bfloat16* src =
            gsrc[l_tile[t]] + (size_t)l_row[t] * GK + l_c16[t] * 8;
        uint32_t dst = sbase + l_tile[t] * TILE_B + l_row[t] * PAD_ROW_B + l_c16[t] * 16;
        CP_ASYNC16(dst, src);
    }
    CP_COMMIT();

    float acc[4][4][4];
#pragma unroll
    for (int i = 0; i < 4; i++)
#pragma unroll
        for (int j = 0; j < 4; j++)
#pragma unroll
            for (int r = 0; r < 4; r++) acc[i][j][r] = 0.f;

    // ldmatrix lane addressing: row = lane&15, col-halfbytes = (lane>>4)*16
    const int lrow = lane & 15;
    const int lcol = (lane >> 4) * 16;

    for (int i = 0; i < GK / 32; i++) {
        // Issue next stage
        if (i + 1 < GK / 32) {
            const int k0n = (i + 1) * 32;
            const uint32_t sb = sbase + ((i + 1) & 1) * STAGE_B;
#pragma unroll
            for (int t = 0; t < 8; t++) {
                const __nv_bfloat16* src =
                    gsrc[l_tile[t]] + (size_t)l_row[t] * GK + k0n + l_c16[t] * 8;
                uint32_t dst = sb + l_tile[t] * TILE_B + l_row[t] * PAD_ROW_B + l_c16[t] * 16;
                CP_ASYNC16(dst, src);
            }
            CP_COMMIT();
            CP_WAIT1();
        } else {
            CP_WAIT0();
        }
        __syncthreads();

        const uint32_t sA = sbase + (i & 1) * STAGE_B;
#pragma unroll
        for (int ks = 0; ks < 2; ks++) {
            const uint32_t kb = ks * 32;   // 16 bf16 = 32 bytes
            uint32_t ah[4][4], al[4][4], bh[4][2], bl[4][2];
#pragma unroll
            for (int mt = 0; mt < 4; mt++) {
                uint32_t ad = sA + (wm * 64 + mt * 16 + lrow) * PAD_ROW_B + kb + lcol;
                LDM_X4(ah[mt], ad);
                LDM_X4(al[mt], ad + TILE_B);
            }
#pragma unroll
            for (int j = 0; j < 2; j++) {
                uint32_t bd = sA + 2 * TILE_B +
                              (wn * 32 + j * 16 + lrow) * PAD_ROW_B + kb + lcol;
                uint32_t r[4];
                LDM_X4(r, bd);
                bh[2 * j][0] = r[0]; bh[2 * j + 1][0] = r[1];
                bh[2 * j][1] = r[2]; bh[2 * j + 1][1] = r[3];
                LDM_X4(r, bd + TILE_B);
                bl[2 * j][0] = r[0]; bl[2 * j + 1][0] = r[1];
                bl[2 * j][1] = r[2]; bl[2 * j + 1][1] = r[3];
            }
#pragma unroll
            for (int mt = 0; mt < 4; mt++)
#pragma unroll
                for (int nt = 0; nt < 4; nt++) {
                    MMA_BF16(acc[mt][nt], ah[mt], bh[nt][0], bh[nt][1]);
                    MMA_BF16(acc[mt][nt], ah[mt], bl[nt][0], bl[nt][1]);
                    MMA_BF16(acc[mt][nt], al[mt], bh[nt][0], bh[nt][1]);
                }
        }
        __syncthreads();
    }

    // Epilogue: fragment layout c0,c1 -> (row, col..col+1); c2,c3 -> row+8
#pragma unroll
    for (int mt = 0; mt < 4; mt++) {
        const int r = m0 + wm * 64 + mt * 16 + (lane >> 2);
#pragma unroll
        for (int nt = 0; nt < 4; nt++) {
            const int c = n0 + wn * 32 + nt * 8 + (lane & 3) * 2;
            *(float2*)(C + (size_t)r * DMODEL + c) =
                make_float2(acc[mt][nt][0], acc[mt][nt][1]);
            *(float2*)(C + (size_t)(r + 8) * DMODEL + c) =
                make_float2(acc[mt][nt][2], acc[mt][nt][3]);
        }
    }
}

// ---------------------------------------------------------------------------
// RoPE in place on Q and K
// ---------------------------------------------------------------------------
__global__ __launch_bounds__(256) void rope_kernel(float* __restrict__ q,
                                                   float* __restrict__ k) {
    int idx = blockIdx.x * blockDim.x + threadIdx.x;
    if (idx >= S_LEN * NHEADS * 64) return;
    int t = idx & 63;
    int h = (idx >> 6) & (NHEADS - 1);
    int s = idx >> 10;

    float inv_freq = exp2f(-(float)t * 0.20762050593045702f);
    float ang = (float)s * inv_freq;
    float sn, cs;
    sincosf(ang, &sn, &cs);

    int base = s * DMODEL + h * HDIM + 2 * t;
    float x1 = q[base], x2 = q[base + 1];
    q[base]     = x1 * cs - x2 * sn;
    q[base + 1] = x1 * sn + x2 * cs;
    x1 = k[base]; x2 = k[base + 1];
    k[base]     = x1 * cs - x2 * sn;
    k[base + 1] = x1 * sn + x2 * cs;
}

// ---------------------------------------------------------------------------
// Sliding-window attention, flash-style online softmax (unchanged this round)
// ---------------------------------------------------------------------------
__global__ __launch_bounds__(512) void attn_kernel(const float* __restrict__ q,
                                                   const float* __restrict__ k,
                                                   const float* __restrict__ v,
                                                   float* __restrict__ out) {
    __shared__ float Ks[32][HDIM];
    __shared__ float Vs[32][HDIM];

    const int h    = blockIdx.y;
    const int q0   = blockIdx.x * 16;
    const int w    = threadIdx.x >> 5;
    const int lane = threadIdx.x & 31;
    const int qi   = q0 + w;
    const float SCALE = 0.088388347648318447f; // 1/sqrt(128)

    float qreg[4];
#pragma unroll
    for (int r = 0; r < 4; r++)
        qreg[r] = q[(size_t)qi * DMODEL + h * HDIM + lane + 32 * r];

    float m = -INFINITY, l = 0.f;
    float o[4] = {0.f, 0.f, 0.f, 0.f};

    int cbeg = max(0, q0 - (WIN - 1)) & ~31;
    int cend = q0 + 15;

    for (int c = cbeg; c <= cend; c += 32) {
        {
            int row = threadIdx.x >> 4;
            int col = (threadIdx.x & 15) * 8;
            int gk = c + row;
            if (gk < S_LEN) {
                const float* kp = k + (size_t)gk * DMODEL + h * HDIM + col;
                const float* vp = v + (size_t)gk * DMODEL + h * HDIM + col;
                *(float4*)&Ks[row][col]     = *(const float4*)kp;
                *(float4*)&Ks[row][col + 4] = *(const float4*)(kp + 4);
                *(float4*)&Vs[row][col]     = *(const float4*)vp;
                *(float4*)&Vs[row][col + 4] = *(const float4*)(vp + 4);
            }
        }
        __syncthreads();

        int jlo = max(c, qi - (WIN - 1));
        int jhi = min(c + 31, qi);
        for (int j = jlo - c; j <= jhi - c; j++) {
            float s_ = 0.f;
#pragma unroll
            for (int r = 0; r < 4; r++)
                s_ = fmaf(qreg[r], Ks[j][lane + 32 * r], s_);
#pragma unroll
            for (int off = 16; off > 0; off >>= 1)
                s_ += __shfl_xor_sync(0xffffffffu, s_, off);
            s_ *= SCALE;

            float mn   = fmaxf(m, s_);
            float corr = __expf(m - mn);
            float p    = __expf(s_ - mn);
            l = l * corr + p;
#pragma unroll
            for (int r = 0; r < 4; r++)
                o[r] = o[r] * corr + p * Vs[j][lane + 32 * r];
            m = mn;
        }
        __syncthreads();
    }

    float inv = 1.f / l;
#pragma unroll
    for (int r = 0; r < 4; r++)
        out[(size_t)qi * DMODEL + h * HDIM + lane + 32 * r] = o[r] * inv;
}

// ---------------------------------------------------------------------------
// Launch
// ---------------------------------------------------------------------------
extern "C" void kernel_launch(void* const* d_in, const int* in_sizes, int n_in,
                              void* d_out, int out_size) {
    const float* x  = (const float*)d_in[0];
    const float* Wq = (const float*)d_in[1];
    const float* Wk = (const float*)d_in[2];
    const float* Wv = (const float*)d_in[3];
    const float* Wo = (const float*)d_in[4];
    float* out = (float*)d_out;

    float *qp, *kp, *vp, *ap;
    cudaGetSymbolAddress((void**)&qp, g_q);
    cudaGetSymbolAddress((void**)&kp, g_k);
    cudaGetSymbolAddress((void**)&vp, g_v);
    cudaGetSymbolAddress((void**)&ap, g_att);

    __nv_bfloat16 *xh, *xl, *ah, *al;
    __nv_bfloat16 *wqh, *wql, *wkh, *wkl, *wvh, *wvl, *woh, *wol;
    cudaGetSymbolAddress((void**)&xh, g_x_hi);
    cudaGetSymbolAddress((void**)&xl, g_x_lo);
    cudaGetSymbolAddress((void**)&ah, g_a_hi);
    cudaGetSymbolAddress((void**)&al, g_a_lo);
    cudaGetSymbolAddress((void**)&wqh, g_wq_hi);
    cudaGetSymbolAddress((void**)&wql, g_wq_lo);
    cudaGetSymbolAddress((void**)&wkh, g_wk_hi);
    cudaGetSymbolAddress((void**)&wkl, g_wk_lo);
    cudaGetSymbolAddress((void**)&wvh, g_wv_hi);
    cudaGetSymbolAddress((void**)&wvl, g_wv_lo);
    cudaGetSymbolAddress((void**)&woh, g_wo_hi);
    cudaGetSymbolAddress((void**)&wol, g_wo_lo);

    cudaFuncSetAttribute(gemm_hmma3,
                         cudaFuncAttributeMaxDynamicSharedMemorySize, GEMM_SMEM);

    const int nx8 = S_LEN * DMODEL / 8;
    const int nw8 = DMODEL * DMODEL / 8;
    cvt_hilo<<<(nx8 + 255) / 256, 256>>>(x, xh, xl, nx8);
    cvt_hilo<<<(nw8 + 255) / 256, 256>>>(Wq, wqh, wql, nw8);
    cvt_hilo<<<(nw8 + 255) / 256, 256>>>(Wk, wkh, wkl, nw8);
    cvt_hilo<<<(nw8 + 255) / 256, 256>>>(Wv, wvh, wvl, nw8);
    cvt_hilo<<<(nw8 + 255) / 256, 256>>>(Wo, woh, wol, nw8);

    dim3 gg(DMODEL / 128, S_LEN / 128);
    gemm_hmma3<<<gg, 256, GEMM_SMEM>>>(xh, xl, wqh, wql, qp);
    gemm_hmma3<<<gg, 256, GEMM_SMEM>>>(xh, xl, wkh, wkl, kp);
    gemm_hmma3<<<gg, 256, GEMM_SMEM>>>(xh, xl, wvh, wvl, vp);

    rope_kernel<<<(S_LEN * NHEADS * 64 + 255) / 256, 256>>>(qp, kp);

    attn_kernel<<<dim3(S_LEN / 16, NHEADS), 512>>>(qp, kp, vp, ap);

    cvt_hilo<<<(nx8 + 255) / 256, 256>>>(ap, ah, al, nx8);
    gemm_hmma3<<<gg, 256, GEMM_SMEM>>>(ah, al, woh, wol, out);
}

// round 4
// speedup vs baseline: 3.0124x; 1.8595x over previous
#include <cuda_runtime.h>
#include <cuda_fp16.h>
#include <math.h>
#include <stdint.h>

#define S_LEN  4096
#define DMODEL 2048
#define NHEADS 16
#define HDIM   128
#define WIN    512

// ---------------------------------------------------------------------------
// Scratch (__device__ globals: allocation-free rule)
// ---------------------------------------------------------------------------
__device__ float g_q[S_LEN * DMODEL];
__device__ float g_k[S_LEN * DMODEL];
__device__ float g_v[S_LEN * DMODEL];
__device__ float g_att[S_LEN * DMODEL];

__device__ __half g_xh[S_LEN * DMODEL];
__device__ __half g_xl[S_LEN * DMODEL];
__device__ __half g_ah[S_LEN * DMODEL];
__device__ __half g_al[S_LEN * DMODEL];
__device__ __half g_qh[S_LEN * DMODEL];
__device__ __half g_ql[S_LEN * DMODEL];
__device__ __half g_kh[S_LEN * DMODEL];
__device__ __half g_vh[S_LEN * DMODEL];
__device__ __half g_wq[DMODEL * DMODEL];
__device__ __half g_wk[DMODEL * DMODEL];
__device__ __half g_wv[DMODEL * DMODEL];
__device__ __half g_wo[DMODEL * DMODEL];

// ---------------------------------------------------------------------------
// PTX primitives (baseline sm_80+)
// ---------------------------------------------------------------------------
__device__ __forceinline__ uint32_t smem_to_u32(const void* p) {
    uint32_t a;
    asm("{ .reg .u64 t; cvta.to.shared.u64 t, %1; cvt.u32.u64 %0, t; }"
        : "=r"(a) : "l"(p));
    return a;
}

#define CP_ASYNC16(dst, src) \
    asm volatile("cp.async.cg.shared.global [%0], [%1], 16;" \
        :: "r"(dst), "l"(src) : "memory")
#define CP_COMMIT() asm volatile("cp.async.commit_group;" ::: "memory")
#define CP_WAIT1()  asm volatile("cp.async.wait_group 1;" ::: "memory")
#define CP_WAIT0()  asm volatile("cp.async.wait_group 0;" ::: "memory")

#define LDM_X4(r, addr) \
    asm volatile("ldmatrix.sync.aligned.m8n8.x4.shared.b16 {%0,%1,%2,%3}, [%4];" \
        : "=r"((r)[0]), "=r"((r)[1]), "=r"((r)[2]), "=r"((r)[3]) : "r"(addr))

#define LDM_X4_T(r, addr) \
    asm volatile("ldmatrix.sync.aligned.m8n8.x4.trans.shared.b16 {%0,%1,%2,%3}, [%4];" \
        : "=r"((r)[0]), "=r"((r)[1]), "=r"((r)[2]), "=r"((r)[3]) : "r"(addr))

#define MMA_F16(c, a, b0, b1) \
    asm volatile("mma.sync.aligned.m16n8k16.row.col.f32.f16.f16.f32 " \
        "{%0,%1,%2,%3}, {%4,%5,%6,%7}, {%8,%9}, {%0,%1,%2,%3};" \
        : "+f"((c)[0]), "+f"((c)[1]), "+f"((c)[2]), "+f"((c)[3]) \
        : "r"((a)[0]), "r"((a)[1]), "r"((a)[2]), "r"((a)[3]), "r"(b0), "r"(b1))

// ---------------------------------------------------------------------------
// fp32 -> (fp16 hi, fp16 lo) split, 8 elems/thread
// ---------------------------------------------------------------------------
__global__ __launch_bounds__(256) void cvt_hilo_f16(const float* __restrict__ src,
                                                    __half* __restrict__ hi,
                                                    __half* __restrict__ lo,
                                                    int n8) {
    int i = blockIdx.x * blockDim.x + threadIdx.x;
    if (i >= n8) return;
    const float4* s4 = (const float4*)src + 2 * (size_t)i;
    float4 a = s4[0], b = s4[1];
    float v[8] = {a.x, a.y, a.z, a.w, b.x, b.y, b.z, b.w};
    __align__(16) __half h[8];
    __align__(16) __half l[8];
#pragma unroll
    for (int j = 0; j < 8; j++) {
        h[j] = __float2half_rn(v[j]);
        l[j] = __float2half_rn(v[j] - __half2float(h[j]));
    }
    ((uint4*)hi)[i] = *(const uint4*)h;
    ((uint4*)lo)[i] = *(const uint4*)l;
}

// fp32 -> fp16 single, 8 elems/thread (weights)
__global__ __launch_bounds__(256) void cvt_f16(const float* __restrict__ src,
                                               __half* __restrict__ dst, int n8) {
    int i = blockIdx.x * blockDim.x + threadIdx.x;
    if (i >= n8) return;
    const float4* s4 = (const float4*)src + 2 * (size_t)i;
    float4 a = s4[0], b = s4[1];
    float v[8] = {a.x, a.y, a.z, a.w, b.x, b.y, b.z, b.w};
    __align__(16) __half h[8];
#pragma unroll
    for (int j = 0; j < 8; j++) h[j] = __float2half_rn(v[j]);
    ((uint4*)dst)[i] = *(const uint4*)h;
}

// ---------------------------------------------------------------------------
// HMMA GEMM (2 MMAs): C = (Ah + Al) @ B^T.  A hi/lo fp16, B single fp16.
// 128x128 tile/CTA, BK=32, 3-stage cp.async, 8 warps (64x32 each).
// ---------------------------------------------------------------------------
#define GK DMODEL
#define NI (GK / 32)
#define PAD_ROW_B 80                 // 32 fp16 (64B) + 16B pad
#define TILE_B (128 * PAD_ROW_B)     // 10240
#define STAGE_B (3 * TILE_B)         // Ahi, Alo, B = 30720
#define GEMM_SMEM (3 * STAGE_B)      // 92160

__global__ __launch_bounds__(256, 1) void gemm_hmma2(
    const __half* __restrict__ Ahi, const __half* __restrict__ Alo,
    const __half* __restrict__ B, float* __restrict__ C) {
    extern __shared__ char smem[];
    const uint32_t sbase = smem_to_u32(smem);
    const int tid  = threadIdx.x;
    const int wid  = tid >> 5;
    const int lane = tid & 31;
    const int wm   = wid & 1;
    const int wn   = wid >> 1;
    const int m0   = blockIdx.y * 128;
    const int n0   = blockIdx.x * 128;

    const __half* gsrc[3] = {
        Ahi + (size_t)m0 * GK, Alo + (size_t)m0 * GK, B + (size_t)n0 * GK};

    int l_tile[6], l_row[6], l_c16[6];
#pragma unroll
    for (int t = 0; t < 6; t++) {
        int linear = t * 256 + tid;     // 1536 chunks total
        l_tile[t] = linear >> 9;
        int within = linear & 511;
        l_row[t] = within >> 2;
        l_c16[t] = within & 3;
    }

    // Prologue: stages 0 and 1
#pragma unroll
    for (int s = 0; s < 2; s++) {
        const uint32_t sb = sbase + s * STAGE_B;
        const int k0 = s * 32;
#pragma unroll
        for (int t = 0; t < 6; t++) {
            const __half* src = gsrc[l_tile[t]] + (size_t)l_row[t] * GK + k0 + l_c16[t] * 8;
            uint32_t dst = sb + l_tile[t] * TILE_B + l_row[t] * PAD_ROW_B + l_c16[t] * 16;
            CP_ASYNC16(dst, src);
        }
        CP_COMMIT();
    }

    float acc[4][4][4];
#pragma unroll
    for (int i = 0; i < 4; i++)
#pragma unroll
        for (int j = 0; j < 4; j++)
#pragma unroll
            for (int r = 0; r < 4; r++) acc[i][j][r] = 0.f;

    const int lrow = lane & 15;
    const int lcol = (lane >> 4) * 16;

    for (int i = 0; i < NI; i++) {
        if (i < NI - 1) { CP_WAIT1(); } else { CP_WAIT0(); }
        __syncthreads();

        if (i + 2 < NI) {
            const int k0n = (i + 2) * 32;
            const uint32_t sb = sbase + ((i + 2) % 3) * STAGE_B;
#pragma unroll
            for (int t = 0; t < 6; t++) {
                const __half* src = gsrc[l_tile[t]] + (size_t)l_row[t] * GK + k0n + l_c16[t] * 8;
                uint32_t dst = sb + l_tile[t] * TILE_B + l_row[t] * PAD_ROW_B + l_c16[t] * 16;
                CP_ASYNC16(dst, src);
            }
            CP_COMMIT();
        }

        const uint32_t sA = sbase + (i % 3) * STAGE_B;
#pragma unroll
        for (int ks = 0; ks < 2; ks++) {
            const uint32_t kb = ks * 32;
            uint32_t ah[4][4], al[4][4], b[4][2];
#pragma unroll
            for (int mt = 0; mt < 4; mt++) {
                uint32_t ad = sA + (wm * 64 + mt * 16 + lrow) * PAD_ROW_B + kb + lcol;
                LDM_X4(ah[mt], ad);
                LDM_X4(al[mt], ad + TILE_B);
            }
#pragma unroll
            for (int j = 0; j < 2; j++) {
                uint32_t bd = sA + 2 * TILE_B +
                              (wn * 32 + j * 16 + lrow) * PAD_ROW_B + kb + lcol;
                uint32_t r[4];
                LDM_X4(r, bd);
                b[2 * j][0] = r[0]; b[2 * j + 1][0] = r[1];
                b[2 * j][1] = r[2]; b[2 * j + 1][1] = r[3];
            }
#pragma unroll
            for (int mt = 0; mt < 4; mt++)
#pragma unroll
                for (int nt = 0; nt < 4; nt++) {
                    MMA_F16(acc[mt][nt], ah[mt], b[nt][0], b[nt][1]);
                    MMA_F16(acc[mt][nt], al[mt], b[nt][0], b[nt][1]);
                }
        }
    }

#pragma unroll
    for (int mt = 0; mt < 4; mt++) {
        const int r = m0 + wm * 64 + mt * 16 + (lane >> 2);
#pragma unroll
        for (int nt = 0; nt < 4; nt++) {
            const int c = n0 + wn * 32 + nt * 8 + (lane & 3) * 2;
            *(float2*)(C + (size_t)r * DMODEL + c) =
                make_float2(acc[mt][nt][0], acc[mt][nt][1]);
            *(float2*)(C + (size_t)(r + 8) * DMODEL + c) =
                make_float2(acc[mt][nt][2], acc[mt][nt][3]);
        }
    }
}

// ---------------------------------------------------------------------------
// RoPE (fp32 in) fused with fp16 conversion: q -> (qh, ql); k -> kh; v -> vh.
// ---------------------------------------------------------------------------
__global__ __launch_bounds__(256) void rope_cvt(const float* __restrict__ q,
                                                const float* __restrict__ k,
                                                const float* __restrict__ v,
                                                __half* __restrict__ qh,
                                                __half* __restrict__ ql,
                                                __half* __restrict__ kh,
                                                __half* __restrict__ vh) {
    int idx = blockIdx.x * blockDim.x + threadIdx.x;
    if (idx >= S_LEN * NHEADS * 64) return;
    int t = idx & 63;
    int h = (idx >> 6) & (NHEADS - 1);
    int s = idx >> 10;

    float inv_freq = exp2f(-(float)t * 0.20762050593045702f);
    float ang = (float)s * inv_freq;
    float sn, cs;
    sincosf(ang, &sn, &cs);

    int base = s * DMODEL + h * HDIM + 2 * t;
    float x1 = q[base], x2 = q[base + 1];
    float r1 = x1 * cs - x2 * sn;
    float r2 = x1 * sn + x2 * cs;
    __half h1 = __float2half_rn(r1);
    __half h2 = __float2half_rn(r2);
    qh[base] = h1;            qh[base + 1] = h2;
    ql[base] = __float2half_rn(r1 - __half2float(h1));
    ql[base + 1] = __float2half_rn(r2 - __half2float(h2));

    x1 = k[base]; x2 = k[base + 1];
    kh[base]     = __float2half_rn(x1 * cs - x2 * sn);
    kh[base + 1] = __float2half_rn(x1 * sn + x2 * cs);

    vh[base]     = __float2half_rn(v[base]);
    vh[base + 1] = __float2half_rn(v[base + 1]);
}

// ---------------------------------------------------------------------------
// HMMA flash attention. Block = 64 queries x 1 head, 4 warps (16 q-rows each).
// Scores: Q(hi/lo) x K(fp16) -> 2 MMAs; softmax fp32; P(fp16) x V(fp16).
// ---------------------------------------------------------------------------
#define AROW 272                      // 128 fp16 (256B) + 16B pad, per smem row
#define QT_B (64 * AROW)              // 17408 per tile
#define ATTN_SMEM (4 * QT_B)          // Qh, Ql, K, V = 69632

__global__ __launch_bounds__(128) void attn_mma(const __half* __restrict__ qh,
                                                const __half* __restrict__ ql,
                                                const __half* __restrict__ kh,
                                                const __half* __restrict__ vh,
                                                float* __restrict__ out) {
    extern __shared__ char smem[];
    const uint32_t sbase = smem_to_u32(smem);
    const uint32_t sQh = sbase;
    const uint32_t sQl = sbase + QT_B;
    const uint32_t sK  = sbase + 2 * QT_B;
    const uint32_t sV  = sbase + 3 * QT_B;

    const int h    = blockIdx.y;
    const int q0   = blockIdx.x * 64;
    const int tid  = threadIdx.x;
    const int wid  = tid >> 5;
    const int lane = tid & 31;
    const int lrow = lane & 15;
    const int lcol = (lane >> 4) * 16;
    const float SCALE = 0.088388347648318447f;

    // Load Q tile (hi & lo) once
    for (int ch = tid; ch < 64 * 16; ch += 128) {
        int row = ch >> 4, c8 = ch & 15;
        size_t g = (size_t)(q0 + row) * DMODEL + h * HDIM + c8 * 8;
        *(uint4*)(smem + (row * AROW + c8 * 16))          = *(const uint4*)(qh + g);
        *(uint4*)(smem + QT_B + (row * AROW + c8 * 16))   = *(const uint4*)(ql + g);
    }

    float O[16][4];
#pragma unroll
    for (int i = 0; i < 16; i++)
#pragma unroll
        for (int r = 0; r < 4; r++) O[i][r] = 0.f;
    float m0 = -1e30f, m1 = -1e30f, l0 = 0.f, l1 = 0.f;

    const int r0g = q0 + wid * 16 + (lane >> 2);
    const int r1g = r0g + 8;
    const int cbeg = max(0, q0 - (WIN - 1)) & ~63;

    for (int c = cbeg; c <= q0; c += 64) {
        __syncthreads();
        // Load K, V tiles
        for (int ch = tid; ch < 64 * 16; ch += 128) {
            int row = ch >> 4, c8 = ch & 15;
            size_t g = (size_t)(c + row) * DMODEL + h * HDIM + c8 * 8;
            *(uint4*)(smem + 2 * QT_B + (row * AROW + c8 * 16)) = *(const uint4*)(kh + g);
            *(uint4*)(smem + 3 * QT_B + (row * AROW + c8 * 16)) = *(const uint4*)(vh + g);
        }
        __syncthreads();

        // Scores: S[16q x 64k] per warp
        float S[8][4];
#pragma unroll
        for (int nt = 0; nt < 8; nt++)
#pragma unroll
            for (int r = 0; r < 4; r++) S[nt][r] = 0.f;

#pragma unroll
        for (int ks = 0; ks < 8; ks++) {
            uint32_t aH[4], aL[4];
            uint32_t qa = sQh + (wid * 16 + lrow) * AROW + ks * 32 + lcol;
            LDM_X4(aH, qa);
            LDM_X4(aL, qa + QT_B);
#pragma unroll
            for (int nb = 0; nb < 4; nb++) {
                uint32_t r[4];
                LDM_X4(r, sK + (nb * 16 + lrow) * AROW + ks * 32 + lcol);
                MMA_F16(S[2 * nb],     aH, r[0], r[2]);
                MMA_F16(S[2 * nb + 1], aH, r[1], r[3]);
                MMA_F16(S[2 * nb],     aL, r[0], r[2]);
                MMA_F16(S[2 * nb + 1], aL, r[1], r[3]);
            }
        }

        // Mask (edge tiles only)
        const bool need_mask = (c + 63 > q0) || (q0 + 63 - c >= WIN);
        if (need_mask) {
#pragma unroll
            for (int nt = 0; nt < 8; nt++) {
                int colb = c + nt * 8 + (lane & 3) * 2;
                if (colb > r0g     || r0g - colb >= WIN)     S[nt][0] = -1e30f;
                if (colb + 1 > r0g || r0g - colb - 1 >= WIN) S[nt][1] = -1e30f;
                if (colb > r1g     || r1g - colb >= WIN)     S[nt][2] = -1e30f;
                if (colb + 1 > r1g || r1g - colb - 1 >= WIN) S[nt][3] = -1e30f;
            }
        }

        // Online softmax
        float mx0 = -1e30f, mx1 = -1e30f;
#pragma unroll
        for (int nt = 0; nt < 8; nt++) {
            mx0 = fmaxf(mx0, fmaxf(S[nt][0], S[nt][1]));
            mx1 = fmaxf(mx1, fmaxf(S[nt][2], S[nt][3]));
        }
        mx0 = fmaxf(mx0, __shfl_xor_sync(0xffffffffu, mx0, 1));
        mx0 = fmaxf(mx0, __shfl_xor_sync(0xffffffffu, mx0, 2));
        mx1 = fmaxf(mx1, __shfl_xor_sync(0xffffffffu, mx1, 1));
        mx1 = fmaxf(mx1, __shfl_xor_sync(0xffffffffu, mx1, 2));

        float mn0 = fmaxf(m0, mx0 * SCALE);
        float mn1 = fmaxf(m1, mx1 * SCALE);
        float c0 = __expf(m0 - mn0);
        float c1 = __expf(m1 - mn1);
        l0 *= c0; l1 *= c1;
#pragma unroll
        for (int nt = 0; nt < 16; nt++) {
            O[nt][0] *= c0; O[nt][1] *= c0;
            O[nt][2] *= c1; O[nt][3] *= c1;
        }
        m0 = mn0; m1 = mn1;

        uint32_t P[8][2];
#pragma unroll
        for (int nt = 0; nt < 8; nt++) {
            float p0 = __expf(S[nt][0] * SCALE - m0);
            float p1 = __expf(S[nt][1] * SCALE - m0);
            float p2 = __expf(S[nt][2] * SCALE - m1);
            float p3 = __expf(S[nt][3] * SCALE - m1);
            l0 += p0 + p1; l1 += p2 + p3;
            __half2 h01 = __floats2half2_rn(p0, p1);
            __half2 h23 = __floats2half2_rn(p2, p3);
            P[nt][0] = *(uint32_t*)&h01;
            P[nt][1] = *(uint32_t*)&h23;
        }

        // P @ V
#pragma unroll
        for (int u = 0; u < 4; u++) {
            uint32_t pa[4] = {P[2 * u][0], P[2 * u][1], P[2 * u + 1][0], P[2 * u + 1][1]};
#pragma unroll
            for (int db = 0; db < 8; db++) {
                uint32_t r[4];
                LDM_X4_T(r, sV + (u * 16 + lrow) * AROW + db * 32 + lcol);
                MMA_F16(O[2 * db],     pa, r[0], r[1]);
                MMA_F16(O[2 * db + 1], pa, r[2], r[3]);
            }
        }
    }

    l0 += __shfl_xor_sync(0xffffffffu, l0, 1);
    l0 += __shfl_xor_sync(0xffffffffu, l0, 2);
    l1 += __shfl_xor_sync(0xffffffffu, l1, 1);
    l1 += __shfl_xor_sync(0xffffffffu, l1, 2);
    float inv0 = 1.f / l0;
    float inv1 = 1.f / l1;

#pragma unroll
    for (int nt = 0; nt < 16; nt++) {
        int colb = h * HDIM + nt * 8 + (lane & 3) * 2;
        *(float2*)(out + (size_t)r0g * DMODEL + colb) =
            make_float2(O[nt][0] * inv0, O[nt][1] * inv0);
        *(float2*)(out + (size_t)r1g * DMODEL + colb) =
            make_float2(O[nt][2] * inv1, O[nt][3] * inv1);
    }
}

// ---------------------------------------------------------------------------
// Launch
// ---------------------------------------------------------------------------
extern "C" void kernel_launch(void* const* d_in, const int* in_sizes, int n_in,
                              void* d_out, int out_size) {
    const float* x  = (const float*)d_in[0];
    const float* Wq = (const float*)d_in[1];
    const float* Wk = (const float*)d_in[2];
    const float* Wv = (const float*)d_in[3];
    const float* Wo = (const float*)d_in[4];
    float* out = (float*)d_out;

    float *qp, *kp, *vp, *ap;
    cudaGetSymbolAddress((void**)&qp, g_q);
    cudaGetSymbolAddress((void**)&kp, g_k);
    cudaGetSymbolAddress((void**)&vp, g_v);
    cudaGetSymbolAddress((void**)&ap, g_att);

    __half *xh, *xl, *ah, *al, *qhp, *qlp, *khp, *vhp;
    __half *wq, *wk, *wv, *wo;
    cudaGetSymbolAddress((void**)&xh, g_xh);
    cudaGetSymbolAddress((void**)&xl, g_xl);
    cudaGetSymbolAddress((void**)&ah, g_ah);
    cudaGetSymbolAddress((void**)&al, g_al);
    cudaGetSymbolAddress((void**)&qhp, g_qh);
    cudaGetSymbolAddress((void**)&qlp, g_ql);
    cudaGetSymbolAddress((void**)&khp, g_kh);
    cudaGetSymbolAddress((void**)&vhp, g_vh);
    cudaGetSymbolAddress((void**)&wq, g_wq);
    cudaGetSymbolAddress((void**)&wk, g_wk);
    cudaGetSymbolAddress((void**)&wv, g_wv);
    cudaGetSymbolAddress((void**)&wo, g_wo);

    cudaFuncSetAttribute(gemm_hmma2,
                         cudaFuncAttributeMaxDynamicSharedMemorySize, GEMM_SMEM);
    cudaFuncSetAttribute(attn_mma,
                         cudaFuncAttributeMaxDynamicSharedMemorySize, ATTN_SMEM);

    const int nx8 = S_LEN * DMODEL / 8;
    const int nw8 = DMODEL * DMODEL / 8;
    cvt_hilo_f16<<<(nx8 + 255) / 256, 256>>>(x, xh, xl, nx8);
    cvt_f16<<<(nw8 + 255) / 256, 256>>>(Wq, wq, nw8);
    cvt_f16<<<(nw8 + 255) / 256, 256>>>(Wk, wk, nw8);
    cvt_f16<<<(nw8 + 255) / 256, 256>>>(Wv, wv, nw8);
    cvt_f16<<<(nw8 + 255) / 256, 256>>>(Wo, wo, nw8);

    dim3 gg(DMODEL / 128, S_LEN / 128);
    gemm_hmma2<<<gg, 256, GEMM_SMEM>>>(xh, xl, wq, qp);
    gemm_hmma2<<<gg, 256, GEMM_SMEM>>>(xh, xl, wk, kp);
    gemm_hmma2<<<gg, 256, GEMM_SMEM>>>(xh, xl, wv, vp);

    rope_cvt<<<(S_LEN * NHEADS * 64 + 255) / 256, 256>>>(qp, kp, vp,
                                                         qhp, qlp, khp, vhp);

    attn_mma<<<dim3(S_LEN / 64, NHEADS), 128, ATTN_SMEM>>>(qhp, qlp, khp, vhp, ap);

    cvt_hilo_f16<<<(nx8 + 255) / 256, 256>>>(ap, ah, al, nx8);
    gemm_hmma2<<<gg, 256, GEMM_SMEM>>>(ah, al, wo, out);
}

// round 5
// speedup vs baseline: 5.0116x; 1.6636x over previous
#include <cuda_runtime.h>
#include <cuda_fp16.h>
#include <math.h>
#include <stdint.h>

#define S_LEN  4096
#define DMODEL 2048
#define NHEADS 16
#define HDIM   128
#define WIN    512

// ---------------------------------------------------------------------------
// Scratch (__device__ globals: allocation-free rule)
// ---------------------------------------------------------------------------
__device__ float g_q[S_LEN * DMODEL];
__device__ float g_k[S_LEN * DMODEL];
__device__ float g_v[S_LEN * DMODEL];
__device__ float g_att[S_LEN * DMODEL];

__device__ __half g_xh[S_LEN * DMODEL];
__device__ __half g_xl[S_LEN * DMODEL];
__device__ __half g_ah[S_LEN * DMODEL];
__device__ __half g_al[S_LEN * DMODEL];
__device__ __half g_qh[S_LEN * DMODEL];
__device__ __half g_ql[S_LEN * DMODEL];
__device__ __half g_kh[S_LEN * DMODEL];
__device__ __half g_vh[S_LEN * DMODEL];
__device__ __half g_wq[DMODEL * DMODEL];
__device__ __half g_wk[DMODEL * DMODEL];
__device__ __half g_wv[DMODEL * DMODEL];
__device__ __half g_wo[DMODEL * DMODEL];

// ---------------------------------------------------------------------------
// PTX primitives (baseline sm_80+)
// ---------------------------------------------------------------------------
__device__ __forceinline__ uint32_t smem_to_u32(const void* p) {
    uint32_t a;
    asm("{ .reg .u64 t; cvta.to.shared.u64 t, %1; cvt.u32.u64 %0, t; }"
        : "=r"(a) : "l"(p));
    return a;
}

#define CP_ASYNC16(dst, src) \
    asm volatile("cp.async.cg.shared.global [%0], [%1], 16;" \
        :: "r"(dst), "l"(src) : "memory")
#define CP_COMMIT() asm volatile("cp.async.commit_group;" ::: "memory")
#define CP_WAIT1()  asm volatile("cp.async.wait_group 1;" ::: "memory")
#define CP_WAIT0()  asm volatile("cp.async.wait_group 0;" ::: "memory")

#define LDM_X4(r, addr) \
    asm volatile("ldmatrix.sync.aligned.m8n8.x4.shared.b16 {%0,%1,%2,%3}, [%4];" \
        : "=r"((r)[0]), "=r"((r)[1]), "=r"((r)[2]), "=r"((r)[3]) : "r"(addr))

#define LDM_X4_T(r, addr) \
    asm volatile("ldmatrix.sync.aligned.m8n8.x4.trans.shared.b16 {%0,%1,%2,%3}, [%4];" \
        : "=r"((r)[0]), "=r"((r)[1]), "=r"((r)[2]), "=r"((r)[3]) : "r"(addr))

#define MMA_F16(c, a, b0, b1) \
    asm volatile("mma.sync.aligned.m16n8k16.row.col.f32.f16.f16.f32 " \
        "{%0,%1,%2,%3}, {%4,%5,%6,%7}, {%8,%9}, {%0,%1,%2,%3};" \
        : "+f"((c)[0]), "+f"((c)[1]), "+f"((c)[2]), "+f"((c)[3]) \
        : "r"((a)[0]), "r"((a)[1]), "r"((a)[2]), "r"((a)[3]), "r"(b0), "r"(b1))

// ---------------------------------------------------------------------------
// fp32 -> (fp16 hi, fp16 lo) split, 8 elems/thread
// ---------------------------------------------------------------------------
__global__ __launch_bounds__(256) void cvt_hilo_f16(const float* __restrict__ src,
                                                    __half* __restrict__ hi,
                                                    __half* __restrict__ lo,
                                                    int n8) {
    int i = blockIdx.x * blockDim.x + threadIdx.x;
    if (i >= n8) return;
    const float4* s4 = (const float4*)src + 2 * (size_t)i;
    float4 a = s4[0], b = s4[1];
    float v[8] = {a.x, a.y, a.z, a.w, b.x, b.y, b.z, b.w};
    __align__(16) __half h[8];
    __align__(16) __half l[8];
#pragma unroll
    for (int j = 0; j < 8; j++) {
        h[j] = __float2half_rn(v[j]);
        l[j] = __float2half_rn(v[j] - __half2float(h[j]));
    }
    ((uint4*)hi)[i] = *(const uint4*)h;
    ((uint4*)lo)[i] = *(const uint4*)l;
}

// Four weight matrices fp32 -> fp16 in one launch (blockIdx.y selects tensor)
__global__ __launch_bounds__(256) void cvt_f16x4(
    const float* __restrict__ s0, const float* __restrict__ s1,
    const float* __restrict__ s2, const float* __restrict__ s3,
    __half* __restrict__ d0, __half* __restrict__ d1,
    __half* __restrict__ d2, __half* __restrict__ d3, int n8) {
    int i = blockIdx.x * blockDim.x + threadIdx.x;
    if (i >= n8) return;
    const int w = blockIdx.y;
    const float* src = (w == 0) ? s0 : (w == 1) ? s1 : (w == 2) ? s2 : s3;
    __half* dst = (w == 0) ? d0 : (w == 1) ? d1 : (w == 2) ? d2 : d3;
    const float4* s4 = (const float4*)src + 2 * (size_t)i;
    float4 a = s4[0], b = s4[1];
    float v[8] = {a.x, a.y, a.z, a.w, b.x, b.y, b.z, b.w};
    __align__(16) __half h[8];
#pragma unroll
    for (int j = 0; j < 8; j++) h[j] = __float2half_rn(v[j]);
    ((uint4*)dst)[i] = *(const uint4*)h;
}

// ---------------------------------------------------------------------------
// HMMA GEMM (2 MMAs): C = (Ah + Al) @ B^T; fused over up to 3 (B, C) pairs
// via blockIdx.z. 128x128 tile/CTA, BK=32, 3-stage cp.async, 8 warps.
// Register-lean: A fragments loaded on demand; target 2 CTAs/SM.
// ---------------------------------------------------------------------------
#define GK DMODEL
#define NI (GK / 32)
#define PAD_ROW_B 80                 // 32 fp16 (64B) + 16B pad
#define TILE_B (128 * PAD_ROW_B)     // 10240
#define STAGE_B (3 * TILE_B)         // Ahi, Alo, B = 30720
#define GEMM_SMEM (3 * STAGE_B)      // 92160

__global__ __launch_bounds__(256, 2) void gemm_hmma2(
    const __half* __restrict__ Ahi, const __half* __restrict__ Alo,
    const __half* __restrict__ B0, const __half* __restrict__ B1,
    const __half* __restrict__ B2,
    float* __restrict__ C0, float* __restrict__ C1, float* __restrict__ C2) {
    extern __shared__ char smem[];
    const uint32_t sbase = smem_to_u32(smem);
    const int tid  = threadIdx.x;
    const int wid  = tid >> 5;
    const int lane = tid & 31;
    const int wm   = wid & 1;
    const int wn   = wid >> 1;
    const int m0   = blockIdx.y * 128;
    const int n0   = blockIdx.x * 128;
    const int z    = blockIdx.z;
    const __half* B = (z == 0) ? B0 : (z == 1) ? B1 : B2;
    float*       C = (z == 0) ? C0 : (z == 1) ? C1 : C2;

    const __half* gsrc[3] = {
        Ahi + (size_t)m0 * GK, Alo + (size_t)m0 * GK, B + (size_t)n0 * GK};

    int l_tile[6], l_row[6], l_c16[6];
#pragma unroll
    for (int t = 0; t < 6; t++) {
        int linear = t * 256 + tid;     // 1536 chunks total
        l_tile[t] = linear >> 9;
        int within = linear & 511;
        l_row[t] = within >> 2;
        l_c16[t] = within & 3;
    }

    // Prologue: stages 0 and 1
#pragma unroll
    for (int s = 0; s < 2; s++) {
        const uint32_t sb = sbase + s * STAGE_B;
        const int k0 = s * 32;
#pragma unroll
        for (int t = 0; t < 6; t++) {
            const __half* src = gsrc[l_tile[t]] + (size_t)l_row[t] * GK + k0 + l_c16[t] * 8;
            uint32_t dst = sb + l_tile[t] * TILE_B + l_row[t] * PAD_ROW_B + l_c16[t] * 16;
            CP_ASYNC16(dst, src);
        }
        CP_COMMIT();
    }

    float acc[4][4][4];
#pragma unroll
    for (int i = 0; i < 4; i++)
#pragma unroll
        for (int j = 0; j < 4; j++)
#pragma unroll
            for (int r = 0; r < 4; r++) acc[i][j][r] = 0.f;

    const int lrow = lane & 15;
    const int lcol = (lane >> 4) * 16;

    for (int i = 0; i < NI; i++) {
        if (i < NI - 1) { CP_WAIT1(); } else { CP_WAIT0(); }
        __syncthreads();

        if (i + 2 < NI) {
            const int k0n = (i + 2) * 32;
            const uint32_t sb = sbase + ((i + 2) % 3) * STAGE_B;
#pragma unroll
            for (int t = 0; t < 6; t++) {
                const __half* src = gsrc[l_tile[t]] + (size_t)l_row[t] * GK + k0n + l_c16[t] * 8;
                uint32_t dst = sb + l_tile[t] * TILE_B + l_row[t] * PAD_ROW_B + l_c16[t] * 16;
                CP_ASYNC16(dst, src);
            }
            CP_COMMIT();
        }

        const uint32_t sA = sbase + (i % 3) * STAGE_B;
#pragma unroll
        for (int ks = 0; ks < 2; ks++) {
            const uint32_t kb = ks * 32;
            uint32_t b[4][2];
#pragma unroll
            for (int j = 0; j < 2; j++) {
                uint32_t bd = sA + 2 * TILE_B +
                              (wn * 32 + j * 16 + lrow) * PAD_ROW_B + kb + lcol;
                uint32_t r[4];
                LDM_X4(r, bd);
                b[2 * j][0] = r[0]; b[2 * j + 1][0] = r[1];
                b[2 * j][1] = r[2]; b[2 * j + 1][1] = r[3];
            }
#pragma unroll
            for (int mt = 0; mt < 4; mt++) {
                uint32_t ah[4], al[4];
                uint32_t ad = sA + (wm * 64 + mt * 16 + lrow) * PAD_ROW_B + kb + lcol;
                LDM_X4(ah, ad);
                LDM_X4(al, ad + TILE_B);
#pragma unroll
                for (int nt = 0; nt < 4; nt++) {
                    MMA_F16(acc[mt][nt], ah, b[nt][0], b[nt][1]);
                    MMA_F16(acc[mt][nt], al, b[nt][0], b[nt][1]);
                }
            }
        }
    }

#pragma unroll
    for (int mt = 0; mt < 4; mt++) {
        const int r = m0 + wm * 64 + mt * 16 + (lane >> 2);
#pragma unroll
        for (int nt = 0; nt < 4; nt++) {
            const int c = n0 + wn * 32 + nt * 8 + (lane & 3) * 2;
            *(float2*)(C + (size_t)r * DMODEL + c) =
                make_float2(acc[mt][nt][0], acc[mt][nt][1]);
            *(float2*)(C + (size_t)(r + 8) * DMODEL + c) =
                make_float2(acc[mt][nt][2], acc[mt][nt][3]);
        }
    }
}

// ---------------------------------------------------------------------------
// RoPE (fp32 in) fused with fp16 conversion: q -> (qh, ql); k -> kh; v -> vh.
// ---------------------------------------------------------------------------
__global__ __launch_bounds__(256) void rope_cvt(const float* __restrict__ q,
                                                const float* __restrict__ k,
                                                const float* __restrict__ v,
                                                __half* __restrict__ qh,
                                                __half* __restrict__ ql,
                                                __half* __restrict__ kh,
                                                __half* __restrict__ vh) {
    int idx = blockIdx.x * blockDim.x + threadIdx.x;
    if (idx >= S_LEN * NHEADS * 64) return;
    int t = idx & 63;
    int h = (idx >> 6) & (NHEADS - 1);
    int s = idx >> 10;

    float inv_freq = exp2f(-(float)t * 0.20762050593045702f);
    float ang = (float)s * inv_freq;
    float sn, cs;
    sincosf(ang, &sn, &cs);

    int base = s * DMODEL + h * HDIM + 2 * t;
    float x1 = q[base], x2 = q[base + 1];
    float r1 = x1 * cs - x2 * sn;
    float r2 = x1 * sn + x2 * cs;
    __half h1 = __float2half_rn(r1);
    __half h2 = __float2half_rn(r2);
    qh[base] = h1;            qh[base + 1] = h2;
    ql[base] = __float2half_rn(r1 - __half2float(h1));
    ql[base + 1] = __float2half_rn(r2 - __half2float(h2));

    x1 = k[base]; x2 = k[base + 1];
    kh[base]     = __float2half_rn(x1 * cs - x2 * sn);
    kh[base + 1] = __float2half_rn(x1 * sn + x2 * cs);

    vh[base]     = __float2half_rn(v[base]);
    vh[base + 1] = __float2half_rn(v[base + 1]);
}

// ---------------------------------------------------------------------------
// HMMA flash attention. Block = 64 queries x 1 head, 4 warps (16 q-rows each).
// Scores: Q(hi/lo) x K(fp16) -> 2 MMAs; softmax fp32; P(fp16) x V(fp16).
// ---------------------------------------------------------------------------
#define AROW 272                      // 128 fp16 (256B) + 16B pad, per smem row
#define QT_B (64 * AROW)              // 17408 per tile
#define ATTN_SMEM (4 * QT_B)          // Qh, Ql, K, V = 69632

__global__ __launch_bounds__(128) void attn_mma(const __half* __restrict__ qh,
                                                const __half* __restrict__ ql,
                                                const __half* __restrict__ kh,
                                                const __half* __restrict__ vh,
                                                float* __restrict__ out) {
    extern __shared__ char smem[];
    const uint32_t sbase = smem_to_u32(smem);
    const uint32_t sQh = sbase;
    const uint32_t sK  = sbase + 2 * QT_B;
    const uint32_t sV  = sbase + 3 * QT_B;

    const int h    = blockIdx.y;
    const int q0   = blockIdx.x * 64;
    const int tid  = threadIdx.x;
    const int wid  = tid >> 5;
    const int lane = tid & 31;
    const int lrow = lane & 15;
    const int lcol = (lane >> 4) * 16;
    const float SCALE = 0.088388347648318447f;

    // Load Q tile (hi & lo) once
    for (int ch = tid; ch < 64 * 16; ch += 128) {
        int row = ch >> 4, c8 = ch & 15;
        size_t g = (size_t)(q0 + row) * DMODEL + h * HDIM + c8 * 8;
        *(uint4*)(smem + (row * AROW + c8 * 16))          = *(const uint4*)(qh + g);
        *(uint4*)(smem + QT_B + (row * AROW + c8 * 16))   = *(const uint4*)(ql + g);
    }

    float O[16][4];
#pragma unroll
    for (int i = 0; i < 16; i++)
#pragma unroll
        for (int r = 0; r < 4; r++) O[i][r] = 0.f;
    float m0 = -1e30f, m1 = -1e30f, l0 = 0.f, l1 = 0.f;

    const int r0g = q0 + wid * 16 + (lane >> 2);
    const int r1g = r0g + 8;
    const int cbeg = max(0, q0 - (WIN - 1)) & ~63;

    for (int c = cbeg; c <= q0; c += 64) {
        __syncthreads();
        for (int ch = tid; ch < 64 * 16; ch += 128) {
            int row = ch >> 4, c8 = ch & 15;
            size_t g = (size_t)(c + row) * DMODEL + h * HDIM + c8 * 8;
            *(uint4*)(smem + 2 * QT_B + (row * AROW + c8 * 16)) = *(const uint4*)(kh + g);
            *(uint4*)(smem + 3 * QT_B + (row * AROW + c8 * 16)) = *(const uint4*)(vh + g);
        }
        __syncthreads();

        float S[8][4];
#pragma unroll
        for (int nt = 0; nt < 8; nt++)
#pragma unroll
            for (int r = 0; r < 4; r++) S[nt][r] = 0.f;

#pragma unroll
        for (int ks = 0; ks < 8; ks++) {
            uint32_t aH[4], aL[4];
            uint32_t qa = sQh + (wid * 16 + lrow) * AROW + ks * 32 + lcol;
            LDM_X4(aH, qa);
            LDM_X4(aL, qa + QT_B);
#pragma unroll
            for (int nb = 0; nb < 4; nb++) {
                uint32_t r[4];
                LDM_X4(r, sK + (nb * 16 + lrow) * AROW + ks * 32 + lcol);
                MMA_F16(S[2 * nb],     aH, r[0], r[2]);
                MMA_F16(S[2 * nb + 1], aH, r[1], r[3]);
                MMA_F16(S[2 * nb],     aL, r[0], r[2]);
                MMA_F16(S[2 * nb + 1], aL, r[1], r[3]);
            }
        }

        const bool need_mask = (c + 63 > q0) || (q0 + 63 - c >= WIN);
        if (need_mask) {
#pragma unroll
            for (int nt = 0; nt < 8; nt++) {
                int colb = c + nt * 8 + (lane & 3) * 2;
                if (colb > r0g     || r0g - colb >= WIN)     S[nt][0] = -1e30f;
                if (colb + 1 > r0g || r0g - colb - 1 >= WIN) S[nt][1] = -1e30f;
                if (colb > r1g     || r1g - colb >= WIN)     S[nt][2] = -1e30f;
                if (colb + 1 > r1g || r1g - colb - 1 >= WIN) S[nt][3] = -1e30f;
            }
        }

        float mx0 = -1e30f, mx1 = -1e30f;
#pragma unroll
        for (int nt = 0; nt < 8; nt++) {
            mx0 = fmaxf(mx0, fmaxf(S[nt][0], S[nt][1]));
            mx1 = fmaxf(mx1, fmaxf(S[nt][2], S[nt][3]));
        }
        mx0 = fmaxf(mx0, __shfl_xor_sync(0xffffffffu, mx0, 1));
        mx0 = fmaxf(mx0, __shfl_xor_sync(0xffffffffu, mx0, 2));
        mx1 = fmaxf(mx1, __shfl_xor_sync(0xffffffffu, mx1, 1));
        mx1 = fmaxf(mx1, __shfl_xor_sync(0xffffffffu, mx1, 2));

        float mn0 = fmaxf(m0, mx0 * SCALE);
        float mn1 = fmaxf(m1, mx1 * SCALE);
        float c0 = __expf(m0 - mn0);
        float c1 = __expf(m1 - mn1);
        l0 *= c0; l1 *= c1;
#pragma unroll
        for (int nt = 0; nt < 16; nt++) {
            O[nt][0] *= c0; O[nt][1] *= c0;
            O[nt][2] *= c1; O[nt][3] *= c1;
        }
        m0 = mn0; m1 = mn1;

        uint32_t P[8][2];
#pragma unroll
        for (int nt = 0; nt < 8; nt++) {
            float p0 = __expf(S[nt][0] * SCALE - m0);
            float p1 = __expf(S[nt][1] * SCALE - m0);
            float p2 = __expf(S[nt][2] * SCALE - m1);
            float p3 = __expf(S[nt][3] * SCALE - m1);
            l0 += p0 + p1; l1 += p2 + p3;
            __half2 h01 = __floats2half2_rn(p0, p1);
            __half2 h23 = __floats2half2_rn(p2, p3);
            P[nt][0] = *(uint32_t*)&h01;
            P[nt][1] = *(uint32_t*)&h23;
        }

#pragma unroll
        for (int u = 0; u < 4; u++) {
            uint32_t pa[4] = {P[2 * u][0], P[2 * u][1], P[2 * u + 1][0], P[2 * u + 1][1]};
#pragma unroll
            for (int db = 0; db < 8; db++) {
                uint32_t r[4];
                LDM_X4_T(r, sV + (u * 16 + lrow) * AROW + db * 32 + lcol);
                MMA_F16(O[2 * db],     pa, r[0], r[1]);
                MMA_F16(O[2 * db + 1], pa, r[2], r[3]);
            }
        }
    }

    l0 += __shfl_xor_sync(0xffffffffu, l0, 1);
    l0 += __shfl_xor_sync(0xffffffffu, l0, 2);
    l1 += __shfl_xor_sync(0xffffffffu, l1, 1);
    l1 += __shfl_xor_sync(0xffffffffu, l1, 2);
    float inv0 = 1.f / l0;
    float inv1 = 1.f / l1;

#pragma unroll
    for (int nt = 0; nt < 16; nt++) {
        int colb = h * HDIM + nt * 8 + (lane & 3) * 2;
        *(float2*)(out + (size_t)r0g * DMODEL + colb) =
            make_float2(O[nt][0] * inv0, O[nt][1] * inv0);
        *(float2*)(out + (size_t)r1g * DMODEL + colb) =
            make_float2(O[nt][2] * inv1, O[nt][3] * inv1);
    }
}

// ---------------------------------------------------------------------------
// Launch
// ---------------------------------------------------------------------------
extern "C" void kernel_launch(void* const* d_in, const int* in_sizes, int n_in,
                              void* d_out, int out_size) {
    const float* x  = (const float*)d_in[0];
    const float* Wq = (const float*)d_in[1];
    const float* Wk = (const float*)d_in[2];
    const float* Wv = (const float*)d_in[3];
    const float* Wo = (const float*)d_in[4];
    float* out = (float*)d_out;

    float *qp, *kp, *vp, *ap;
    cudaGetSymbolAddress((void**)&qp, g_q);
    cudaGetSymbolAddress((void**)&kp, g_k);
    cudaGetSymbolAddress((void**)&vp, g_v);
    cudaGetSymbolAddress((void**)&ap, g_att);

    __half *xh, *xl, *ah, *al, *qhp, *qlp, *khp, *vhp;
    __half *wq, *wk, *wv, *wo;
    cudaGetSymbolAddress((void**)&xh, g_xh);
    cudaGetSymbolAddress((void**)&xl, g_xl);
    cudaGetSymbolAddress((void**)&ah, g_ah);
    cudaGetSymbolAddress((void**)&al, g_al);
    cudaGetSymbolAddress((void**)&qhp, g_qh);
    cudaGetSymbolAddress((void**)&qlp, g_ql);
    cudaGetSymbolAddress((void**)&khp, g_kh);
    cudaGetSymbolAddress((void**)&vhp, g_vh);
    cudaGetSymbolAddress((void**)&wq, g_wq);
    cudaGetSymbolAddress((void**)&wk, g_wk);
    cudaGetSymbolAddress((void**)&wv, g_wv);
    cudaGetSymbolAddress((void**)&wo, g_wo);

    cudaFuncSetAttribute(gemm_hmma2,
                         cudaFuncAttributeMaxDynamicSharedMemorySize, GEMM_SMEM);
    cudaFuncSetAttribute(attn_mma,
                         cudaFuncAttributeMaxDynamicSharedMemorySize, ATTN_SMEM);

    const int nx8 = S_LEN * DMODEL / 8;
    const int nw8 = DMODEL * DMODEL / 8;
    cvt_hilo_f16<<<(nx8 + 255) / 256, 256>>>(x, xh, xl, nx8);
    cvt_f16x4<<<dim3((nw8 + 255) / 256, 4), 256>>>(Wq, Wk, Wv, Wo,
                                                   wq, wk, wv, wo, nw8);

    // Fused Q/K/V projections: blockIdx.z selects (B, C)
    dim3 gqkv(DMODEL / 128, S_LEN / 128, 3);
    gemm_hmma2<<<gqkv, 256, GEMM_SMEM>>>(xh, xl, wq, wk, wv, qp, kp, vp);

    rope_cvt<<<(S_LEN * NHEADS * 64 + 255) / 256, 256>>>(qp, kp, vp,
                                                         qhp, qlp, khp, vhp);

    attn_mma<<<dim3(S_LEN / 64, NHEADS), 128, ATTN_SMEM>>>(qhp, qlp, khp, vhp, ap);

    cvt_hilo_f16<<<(nx8 + 255) / 256, 256>>>(ap, ah, al, nx8);

    dim3 go(DMODEL / 128, S_LEN / 128, 1);
    gemm_hmma2<<<go, 256, GEMM_SMEM>>>(ah, al, wo, wo, wo, out, out, out);
}

// round 6
// speedup vs baseline: 5.0596x; 1.0096x over previous
#include <cuda_runtime.h>
#include <cuda_fp16.h>
#include <math.h>
#include <stdint.h>

#define S_LEN  4096
#define DMODEL 2048
#define NHEADS 16
#define HDIM   128
#define WIN    512

// ---------------------------------------------------------------------------
// Scratch (__device__ globals: allocation-free rule)
// ---------------------------------------------------------------------------
__device__ __half g_xh[S_LEN * DMODEL];
__device__ __half g_xl[S_LEN * DMODEL];
__device__ __half g_ah[S_LEN * DMODEL];
__device__ __half g_al[S_LEN * DMODEL];
__device__ __half g_qh[S_LEN * DMODEL];
__device__ __half g_ql[S_LEN * DMODEL];
__device__ __half g_kh[S_LEN * DMODEL];
__device__ __half g_vh[S_LEN * DMODEL];
__device__ __half g_wq[DMODEL * DMODEL];
__device__ __half g_wk[DMODEL * DMODEL];
__device__ __half g_wv[DMODEL * DMODEL];
__device__ __half g_wo[DMODEL * DMODEL];
__device__ float2 g_rope[S_LEN * 64];

// ---------------------------------------------------------------------------
// PTX primitives (baseline sm_80+)
// ---------------------------------------------------------------------------
__device__ __forceinline__ uint32_t smem_to_u32(const void* p) {
    uint32_t a;
    asm("{ .reg .u64 t; cvta.to.shared.u64 t, %1; cvt.u32.u64 %0, t; }"
        : "=r"(a) : "l"(p));
    return a;
}

#define CP_ASYNC16(dst, src) \
    asm volatile("cp.async.cg.shared.global [%0], [%1], 16;" \
        :: "r"(dst), "l"(src) : "memory")
#define CP_COMMIT() asm volatile("cp.async.commit_group;" ::: "memory")
#define CP_WAIT1()  asm volatile("cp.async.wait_group 1;" ::: "memory")
#define CP_WAIT0()  asm volatile("cp.async.wait_group 0;" ::: "memory")

#define LDM_X4(r, addr) \
    asm volatile("ldmatrix.sync.aligned.m8n8.x4.shared.b16 {%0,%1,%2,%3}, [%4];" \
        : "=r"((r)[0]), "=r"((r)[1]), "=r"((r)[2]), "=r"((r)[3]) : "r"(addr))

#define LDM_X4_T(r, addr) \
    asm volatile("ldmatrix.sync.aligned.m8n8.x4.trans.shared.b16 {%0,%1,%2,%3}, [%4];" \
        : "=r"((r)[0]), "=r"((r)[1]), "=r"((r)[2]), "=r"((r)[3]) : "r"(addr))

#define MMA_F16(c, a, b0, b1) \
    asm volatile("mma.sync.aligned.m16n8k16.row.col.f32.f16.f16.f32 " \
        "{%0,%1,%2,%3}, {%4,%5,%6,%7}, {%8,%9}, {%0,%1,%2,%3};" \
        : "+f"((c)[0]), "+f"((c)[1]), "+f"((c)[2]), "+f"((c)[3]) \
        : "r"((a)[0]), "r"((a)[1]), "r"((a)[2]), "r"((a)[3]), "r"(b0), "r"(b1))

// ---------------------------------------------------------------------------
// RoPE cos/sin table: g_rope[s*64 + t] = (cos, sin) of s * 10000^(-t/64)
// ---------------------------------------------------------------------------
__global__ __launch_bounds__(256) void rope_build(float2* __restrict__ tab) {
    int idx = blockIdx.x * blockDim.x + threadIdx.x;
    if (idx >= S_LEN * 64) return;
    int t = idx & 63;
    int s = idx >> 6;
    float ang = (float)s * exp2f(-(float)t * 0.20762050593045702f);
    float sn, cs;
    sincosf(ang, &sn, &cs);
    tab[idx] = make_float2(cs, sn);
}

// ---------------------------------------------------------------------------
// fp32 -> (fp16 hi, fp16 lo) split, 8 elems/thread
// ---------------------------------------------------------------------------
__global__ __launch_bounds__(256) void cvt_hilo_f16(const float* __restrict__ src,
                                                    __half* __restrict__ hi,
                                                    __half* __restrict__ lo,
                                                    int n8) {
    int i = blockIdx.x * blockDim.x + threadIdx.x;
    if (i >= n8) return;
    const float4* s4 = (const float4*)src + 2 * (size_t)i;
    float4 a = s4[0], b = s4[1];
    float v[8] = {a.x, a.y, a.z, a.w, b.x, b.y, b.z, b.w};
    __align__(16) __half h[8];
    __align__(16) __half l[8];
#pragma unroll
    for (int j = 0; j < 8; j++) {
        h[j] = __float2half_rn(v[j]);
        l[j] = __float2half_rn(v[j] - __half2float(h[j]));
    }
    ((uint4*)hi)[i] = *(const uint4*)h;
    ((uint4*)lo)[i] = *(const uint4*)l;
}

// Four weight matrices fp32 -> fp16 in one launch (blockIdx.y selects tensor)
__global__ __launch_bounds__(256) void cvt_f16x4(
    const float* __restrict__ s0, const float* __restrict__ s1,
    const float* __restrict__ s2, const float* __restrict__ s3,
    __half* __restrict__ d0, __half* __restrict__ d1,
    __half* __restrict__ d2, __half* __restrict__ d3, int n8) {
    int i = blockIdx.x * blockDim.x + threadIdx.x;
    if (i >= n8) return;
    const int w = blockIdx.y;
    const float* src = (w == 0) ? s0 : (w == 1) ? s1 : (w == 2) ? s2 : s3;
    __half* dst = (w == 0) ? d0 : (w == 1) ? d1 : (w == 2) ? d2 : d3;
    const float4* s4 = (const float4*)src + 2 * (size_t)i;
    float4 a = s4[0], b = s4[1];
    float v[8] = {a.x, a.y, a.z, a.w, b.x, b.y, b.z, b.w};
    __align__(16) __half h[8];
#pragma unroll
    for (int j = 0; j < 8; j++) h[j] = __float2half_rn(v[j]);
    ((uint4*)dst)[i] = *(const uint4*)h;
}

// ---------------------------------------------------------------------------
// Shared GEMM mainloop (macro so fragment arrays stay in registers).
// Requires in scope: smem, sbase, tid, lane, wm, wn, m0, n0, acc[4][4][4].
// Computes acc = (Ahi + Alo) @ B^T for the CTA's 128x128 tile.
// ---------------------------------------------------------------------------
#define GK DMODEL
#define NI (GK / 32)
#define PAD_ROW_B 80                 // 32 fp16 (64B) + 16B pad
#define TILE_B (128 * PAD_ROW_B)     // 10240
#define STAGE_B (3 * TILE_B)         // Ahi, Alo, B = 30720
#define GEMM_SMEM (3 * STAGE_B)      // 92160

#define GEMM_MAINLOOP(AhiP, AloP, BP)                                          \
    const __half* gsrc[3] = {                                                  \
        (AhiP) + (size_t)m0 * GK, (AloP) + (size_t)m0 * GK,                    \
        (BP) + (size_t)n0 * GK};                                               \
    int l_tile[6], l_row[6], l_c16[6];                                         \
    _Pragma("unroll")                                                          \
    for (int t = 0; t < 6; t++) {                                              \
        int linear = t * 256 + tid;                                            \
        l_tile[t] = linear >> 9;                                               \
        int within = linear & 511;                                             \
        l_row[t] = within >> 2;                                                \
        l_c16[t] = within & 3;                                                 \
    }                                                                          \
    _Pragma("unroll")                                                          \
    for (int s = 0; s < 2; s++) {                                              \
        const uint32_t sb = sbase + s * STAGE_B;                               \
        const int k0 = s * 32;                                                 \
        _Pragma("unroll")                                                      \
        for (int t = 0; t < 6; t++) {                                          \
            const __half* src =                                                \
                gsrc[l_tile[t]] + (size_t)l_row[t] * GK + k0 + l_c16[t] * 8;   \
            uint32_t dst = sb + l_tile[t] * TILE_B + l_row[t] * PAD_ROW_B +    \
                           l_c16[t] * 16;                                      \
            CP_ASYNC16(dst, src);                                              \
        }                                                                      \
        CP_COMMIT();                                                           \
    }                                                                          \
    _Pragma("unroll")                                                          \
    for (int i = 0; i < 4; i++)                                                \
        _Pragma("unroll")                                                      \
        for (int j = 0; j < 4; j++)                                            \
            _Pragma("unroll")                                                  \
            for (int r = 0; r < 4; r++) acc[i][j][r] = 0.f;                    \
    const int lrow = lane & 15;                                                \
    const int lcol = (lane >> 4) * 16;                                         \
    for (int i = 0; i < NI; i++) {                                             \
        if (i < NI - 1) { CP_WAIT1(); } else { CP_WAIT0(); }                   \
        __syncthreads();                                                       \
        if (i + 2 < NI) {                                                      \
            const int k0n = (i + 2) * 32;                                      \
            const uint32_t sb = sbase + ((i + 2) % 3) * STAGE_B;               \
            _Pragma("unroll")                                                  \
            for (int t = 0; t < 6; t++) {                                      \
                const __half* src = gsrc[l_tile[t]] +                          \
                    (size_t)l_row[t] * GK + k0n + l_c16[t] * 8;                \
                uint32_t dst = sb + l_tile[t] * TILE_B +                       \
                               l_row[t] * PAD_ROW_B + l_c16[t] * 16;           \
                CP_ASYNC16(dst, src);                                          \
            }                                                                  \
            CP_COMMIT();                                                       \
        }                                                                      \
        const uint32_t sA = sbase + (i % 3) * STAGE_B;                         \
        _Pragma("unroll")                                                      \
        for (int ks = 0; ks < 2; ks++) {                                       \
            const uint32_t kb = ks * 32;                                       \
            uint32_t b[4][2];                                                  \
            _Pragma("unroll")                                                  \
            for (int j = 0; j < 2; j++) {                                      \
                uint32_t bd = sA + 2 * TILE_B +                                \
                    (wn * 32 + j * 16 + lrow) * PAD_ROW_B + kb + lcol;         \
                uint32_t r[4];                                                 \
                LDM_X4(r, bd);                                                 \
                b[2 * j][0] = r[0]; b[2 * j + 1][0] = r[1];                    \
                b[2 * j][1] = r[2]; b[2 * j + 1][1] = r[3];                    \
            }                                                                  \
            _Pragma("unroll")                                                  \
            for (int mt = 0; mt < 4; mt++) {                                   \
                uint32_t ah[4], al[4];                                         \
                uint32_t ad = sA + (wm * 64 + mt * 16 + lrow) * PAD_ROW_B +    \
                              kb + lcol;                                       \
                LDM_X4(ah, ad);                                                \
                LDM_X4(al, ad + TILE_B);                                       \
                _Pragma("unroll")                                              \
                for (int nt = 0; nt < 4; nt++) {                               \
                    MMA_F16(acc[mt][nt], ah, b[nt][0], b[nt][1]);              \
                    MMA_F16(acc[mt][nt], al, b[nt][0], b[nt][1]);              \
                }                                                              \
            }                                                                  \
        }                                                                      \
    }

// ---------------------------------------------------------------------------
// QKV GEMM with fused RoPE + fp16 epilogue. blockIdx.z: 0=Q (hi/lo), 1=K, 2=V.
// ---------------------------------------------------------------------------
__global__ __launch_bounds__(256, 2) void gemm_qkv(
    const __half* __restrict__ Ahi, const __half* __restrict__ Alo,
    const __half* __restrict__ B0, const __half* __restrict__ B1,
    const __half* __restrict__ B2,
    __half* __restrict__ qh, __half* __restrict__ ql,
    __half* __restrict__ kh, __half* __restrict__ vh,
    const float2* __restrict__ rope) {
    extern __shared__ char smem[];
    const uint32_t sbase = smem_to_u32(smem);
    const int tid  = threadIdx.x;
    const int wid  = tid >> 5;
    const int lane = tid & 31;
    const int wm   = wid & 1;
    const int wn   = wid >> 1;
    const int m0   = blockIdx.y * 128;
    const int n0   = blockIdx.x * 128;
    const int z    = blockIdx.z;
    const __half* B = (z == 0) ? B0 : (z == 1) ? B1 : B2;

    float acc[4][4][4];
    GEMM_MAINLOOP(Ahi, Alo, B)

#pragma unroll
    for (int mt = 0; mt < 4; mt++) {
        const int r = m0 + wm * 64 + mt * 16 + (lane >> 2);
#pragma unroll
        for (int nt = 0; nt < 4; nt++) {
            const int c = n0 + wn * 32 + nt * 8 + (lane & 3) * 2;
            const size_t o0 = (size_t)r * DMODEL + c;
            const size_t o1 = (size_t)(r + 8) * DMODEL + c;
            if (z == 2) {
                *(half2*)(vh + o0) = __floats2half2_rn(acc[mt][nt][0], acc[mt][nt][1]);
                *(half2*)(vh + o1) = __floats2half2_rn(acc[mt][nt][2], acc[mt][nt][3]);
            } else {
                const int t = (c & 127) >> 1;
                float2 cs0 = rope[r * 64 + t];
                float2 cs1 = rope[(r + 8) * 64 + t];
                float a1 = acc[mt][nt][0] * cs0.x - acc[mt][nt][1] * cs0.y;
                float a2 = acc[mt][nt][0] * cs0.y + acc[mt][nt][1] * cs0.x;
                float b1 = acc[mt][nt][2] * cs1.x - acc[mt][nt][3] * cs1.y;
                float b2 = acc[mt][nt][2] * cs1.y + acc[mt][nt][3] * cs1.x;
                if (z == 1) {
                    *(half2*)(kh + o0) = __floats2half2_rn(a1, a2);
                    *(half2*)(kh + o1) = __floats2half2_rn(b1, b2);
                } else {
                    __half h1 = __float2half_rn(a1), h2 = __float2half_rn(a2);
                    __half h3 = __float2half_rn(b1), h4 = __float2half_rn(b2);
                    *(half2*)(qh + o0) = __halves2half2(h1, h2);
                    *(half2*)(qh + o1) = __halves2half2(h3, h4);
                    *(half2*)(ql + o0) = __floats2half2_rn(
                        a1 - __half2float(h1), a2 - __half2float(h2));
                    *(half2*)(ql + o1) = __floats2half2_rn(
                        b1 - __half2float(h3), b2 - __half2float(h4));
                }
            }
        }
    }
}

// ---------------------------------------------------------------------------
// Output projection GEMM: fp32 epilogue to d_out.
// ---------------------------------------------------------------------------
__global__ __launch_bounds__(256, 2) void gemm_out(
    const __half* __restrict__ Ahi, const __half* __restrict__ Alo,
    const __half* __restrict__ Bw, float* __restrict__ C) {
    extern __shared__ char smem[];
    const uint32_t sbase = smem_to_u32(smem);
    const int tid  = threadIdx.x;
    const int wid  = tid >> 5;
    const int lane = tid & 31;
    const int wm   = wid & 1;
    const int wn   = wid >> 1;
    const int m0   = blockIdx.y * 128;
    const int n0   = blockIdx.x * 128;

    float acc[4][4][4];
    GEMM_MAINLOOP(Ahi, Alo, Bw)

#pragma unroll
    for (int mt = 0; mt < 4; mt++) {
        const int r = m0 + wm * 64 + mt * 16 + (lane >> 2);
#pragma unroll
        for (int nt = 0; nt < 4; nt++) {
            const int c = n0 + wn * 32 + nt * 8 + (lane & 3) * 2;
            *(float2*)(C + (size_t)r * DMODEL + c) =
                make_float2(acc[mt][nt][0], acc[mt][nt][1]);
            *(float2*)(C + (size_t)(r + 8) * DMODEL + c) =
                make_float2(acc[mt][nt][2], acc[mt][nt][3]);
        }
    }
}

// ---------------------------------------------------------------------------
// HMMA flash attention. Block = 64 queries x 1 head, 4 warps (16 q-rows each).
// Scores: Q(hi/lo) x K(fp16) -> 2 MMAs; softmax fp32; P(fp16) x V(fp16).
// Epilogue writes hi/lo fp16 split directly.
// ---------------------------------------------------------------------------
#define AROW 272                      // 128 fp16 (256B) + 16B pad, per smem row
#define QT_B (64 * AROW)              // 17408 per tile
#define ATTN_SMEM (4 * QT_B)          // Qh, Ql, K, V = 69632

__global__ __launch_bounds__(128) void attn_mma(const __half* __restrict__ qh,
                                                const __half* __restrict__ ql,
                                                const __half* __restrict__ kh,
                                                const __half* __restrict__ vh,
                                                __half* __restrict__ oh,
                                                __half* __restrict__ ol) {
    extern __shared__ char smem[];
    const uint32_t sbase = smem_to_u32(smem);
    const uint32_t sQh = sbase;
    const uint32_t sK  = sbase + 2 * QT_B;
    const uint32_t sV  = sbase + 3 * QT_B;

    const int h    = blockIdx.y;
    const int q0   = blockIdx.x * 64;
    const int tid  = threadIdx.x;
    const int wid  = tid >> 5;
    const int lane = tid & 31;
    const int lrow = lane & 15;
    const int lcol = (lane >> 4) * 16;
    const float SCALE = 0.088388347648318447f;

    for (int ch = tid; ch < 64 * 16; ch += 128) {
        int row = ch >> 4, c8 = ch & 15;
        size_t g = (size_t)(q0 + row) * DMODEL + h * HDIM + c8 * 8;
        *(uint4*)(smem + (row * AROW + c8 * 16))        = *(const uint4*)(qh + g);
        *(uint4*)(smem + QT_B + (row * AROW + c8 * 16)) = *(const uint4*)(ql + g);
    }

    float O[16][4];
#pragma unroll
    for (int i = 0; i < 16; i++)
#pragma unroll
        for (int r = 0; r < 4; r++) O[i][r] = 0.f;
    float m0 = -1e30f, m1 = -1e30f, l0 = 0.f, l1 = 0.f;

    const int r0g = q0 + wid * 16 + (lane >> 2);
    const int r1g = r0g + 8;
    const int cbeg = max(0, q0 - (WIN - 1)) & ~63;

    for (int c = cbeg; c <= q0; c += 64) {
        __syncthreads();
        for (int ch = tid; ch < 64 * 16; ch += 128) {
            int row = ch >> 4, c8 = ch & 15;
            size_t g = (size_t)(c + row) * DMODEL + h * HDIM + c8 * 8;
            *(uint4*)(smem + 2 * QT_B + (row * AROW + c8 * 16)) = *(const uint4*)(kh + g);
            *(uint4*)(smem + 3 * QT_B + (row * AROW + c8 * 16)) = *(const uint4*)(vh + g);
        }
        __syncthreads();

        float S[8][4];
#pragma unroll
        for (int nt = 0; nt < 8; nt++)
#pragma unroll
            for (int r = 0; r < 4; r++) S[nt][r] = 0.f;

#pragma unroll
        for (int ks = 0; ks < 8; ks++) {
            uint32_t aH[4], aL[4];
            uint32_t qa = sQh + (wid * 16 + lrow) * AROW + ks * 32 + lcol;
            LDM_X4(aH, qa);
            LDM_X4(aL, qa + QT_B);
#pragma unroll
            for (int nb = 0; nb < 4; nb++) {
                uint32_t r[4];
                LDM_X4(r, sK + (nb * 16 + lrow) * AROW + ks * 32 + lcol);
                MMA_F16(S[2 * nb],     aH, r[0], r[2]);
                MMA_F16(S[2 * nb + 1], aH, r[1], r[3]);
                MMA_F16(S[2 * nb],     aL, r[0], r[2]);
                MMA_F16(S[2 * nb + 1], aL, r[1], r[3]);
            }
        }

        const bool need_mask = (c + 63 > q0) || (q0 + 63 - c >= WIN);
        if (need_mask) {
#pragma unroll
            for (int nt = 0; nt < 8; nt++) {
                int colb = c + nt * 8 + (lane & 3) * 2;
                if (colb > r0g     || r0g - colb >= WIN)     S[nt][0] = -1e30f;
                if (colb + 1 > r0g || r0g - colb - 1 >= WIN) S[nt][1] = -1e30f;
                if (colb > r1g     || r1g - colb >= WIN)     S[nt][2] = -1e30f;
                if (colb + 1 > r1g || r1g - colb - 1 >= WIN) S[nt][3] = -1e30f;
            }
        }

        float mx0 = -1e30f, mx1 = -1e30f;
#pragma unroll
        for (int nt = 0; nt < 8; nt++) {
            mx0 = fmaxf(mx0, fmaxf(S[nt][0], S[nt][1]));
            mx1 = fmaxf(mx1, fmaxf(S[nt][2], S[nt][3]));
        }
        mx0 = fmaxf(mx0, __shfl_xor_sync(0xffffffffu, mx0, 1));
        mx0 = fmaxf(mx0, __shfl_xor_sync(0xffffffffu, mx0, 2));
        mx1 = fmaxf(mx1, __shfl_xor_sync(0xffffffffu, mx1, 1));
        mx1 = fmaxf(mx1, __shfl_xor_sync(0xffffffffu, mx1, 2));

        float mn0 = fmaxf(m0, mx0 * SCALE);
        float mn1 = fmaxf(m1, mx1 * SCALE);
        float c0 = __expf(m0 - mn0);
        float c1 = __expf(m1 - mn1);
        l0 *= c0; l1 *= c1;
#pragma unroll
        for (int nt = 0; nt < 16; nt++) {
            O[nt][0] *= c0; O[nt][1] *= c0;
            O[nt][2] *= c1; O[nt][3] *= c1;
        }
        m0 = mn0; m1 = mn1;

        uint32_t P[8][2];
#pragma unroll
        for (int nt = 0; nt < 8; nt++) {
            float p0 = __expf(S[nt][0] * SCALE - m0);
            float p1 = __expf(S[nt][1] * SCALE - m0);
            float p2 = __expf(S[nt][2] * SCALE - m1);
            float p3 = __expf(S[nt][3] * SCALE - m1);
            l0 += p0 + p1; l1 += p2 + p3;
            __half2 h01 = __floats2half2_rn(p0, p1);
            __half2 h23 = __floats2half2_rn(p2, p3);
            P[nt][0] = *(uint32_t*)&h01;
            P[nt][1] = *(uint32_t*)&h23;
        }

#pragma unroll
        for (int u = 0; u < 4; u++) {
            uint32_t pa[4] = {P[2 * u][0], P[2 * u][1], P[2 * u + 1][0], P[2 * u + 1][1]};
#pragma unroll
            for (int db = 0; db < 8; db++) {
                uint32_t r[4];
                LDM_X4_T(r, sV + (u * 16 + lrow) * AROW + db * 32 + lcol);
                MMA_F16(O[2 * db],     pa, r[0], r[1]);
                MMA_F16(O[2 * db + 1], pa, r[2], r[3]);
            }
        }
    }

    l0 += __shfl_xor_sync(0xffffffffu, l0, 1);
    l0 += __shfl_xor_sync(0xffffffffu, l0, 2);
    l1 += __shfl_xor_sync(0xffffffffu, l1, 1);
    l1 += __shfl_xor_sync(0xffffffffu, l1, 2);
    float inv0 = 1.f / l0;
    float inv1 = 1.f / l1;

#pragma unroll
    for (int nt = 0; nt < 16; nt++) {
        int colb = h * HDIM + nt * 8 + (lane & 3) * 2;
        float a0 = O[nt][0] * inv0, a1 = O[nt][1] * inv0;
        float b0 = O[nt][2] * inv1, b1 = O[nt][3] * inv1;
        __half h0 = __float2half_rn(a0), h1 = __float2half_rn(a1);
        __half h2 = __float2half_rn(b0), h3 = __float2half_rn(b1);
        *(half2*)(oh + (size_t)r0g * DMODEL + colb) = __halves2half2(h0, h1);
        *(half2*)(oh + (size_t)r1g * DMODEL + colb) = __halves2half2(h2, h3);
        *(half2*)(ol + (size_t)r0g * DMODEL + colb) = __floats2half2_rn(
            a0 - __half2float(h0), a1 - __half2float(h1));
        *(half2*)(ol + (size_t)r1g * DMODEL + colb) = __floats2half2_rn(
            b0 - __half2float(h2), b1 - __half2float(h3));
    }
}

// ---------------------------------------------------------------------------
// Launch
// ---------------------------------------------------------------------------
extern "C" void kernel_launch(void* const* d_in, const int* in_sizes, int n_in,
                              void* d_out, int out_size) {
    const float* x  = (const float*)d_in[0];
    const float* Wq = (const float*)d_in[1];
    const float* Wk = (const float*)d_in[2];
    const float* Wv = (const float*)d_in[3];
    const float* Wo = (const float*)d_in[4];
    float* out = (float*)d_out;

    __half *xh, *xl, *ah, *al, *qhp, *qlp, *khp, *vhp;
    __half *wq, *wk, *wv, *wo;
    float2* ropetab;
    cudaGetSymbolAddress((void**)&xh, g_xh);
    cudaGetSymbolAddress((void**)&xl, g_xl);
    cudaGetSymbolAddress((void**)&ah, g_ah);
    cudaGetSymbolAddress((void**)&al, g_al);
    cudaGetSymbolAddress((void**)&qhp, g_qh);
    cudaGetSymbolAddress((void**)&qlp, g_ql);
    cudaGetSymbolAddress((void**)&khp, g_kh);
    cudaGetSymbolAddress((void**)&vhp, g_vh);
    cudaGetSymbolAddress((void**)&wq, g_wq);
    cudaGetSymbolAddress((void**)&wk, g_wk);
    cudaGetSymbolAddress((void**)&wv, g_wv);
    cudaGetSymbolAddress((void**)&wo, g_wo);
    cudaGetSymbolAddress((void**)&ropetab, g_rope);

    cudaFuncSetAttribute(gemm_qkv,
                         cudaFuncAttributeMaxDynamicSharedMemorySize, GEMM_SMEM);
    cudaFuncSetAttribute(gemm_out,
                         cudaFuncAttributeMaxDynamicSharedMemorySize, GEMM_SMEM);
    cudaFuncSetAttribute(attn_mma,
                         cudaFuncAttributeMaxDynamicSharedMemorySize, ATTN_SMEM);

    const int nx8 = S_LEN * DMODEL / 8;
    const int nw8 = DMODEL * DMODEL / 8;
    rope_build<<<(S_LEN * 64 + 255) / 256, 256>>>(ropetab);
    cvt_hilo_f16<<<(nx8 + 255) / 256, 256>>>(x, xh, xl, nx8);
    cvt_f16x4<<<dim3((nw8 + 255) / 256, 4), 256>>>(Wq, Wk, Wv, Wo,
                                                   wq, wk, wv, wo, nw8);

    dim3 gqkv(DMODEL / 128, S_LEN / 128, 3);
    gemm_qkv<<<gqkv, 256, GEMM_SMEM>>>(xh, xl, wq, wk, wv,
                                       qhp, qlp, khp, vhp, ropetab);

    attn_mma<<<dim3(S_LEN / 64, NHEADS), 128, ATTN_SMEM>>>(qhp, qlp, khp, vhp,
                                                           ah, al);

    dim3 go(DMODEL / 128, S_LEN / 128);
    gemm_out<<<go, 256, GEMM_SMEM>>>(ah, al, wo, out);
}

// round 7
// speedup vs baseline: 5.6149x; 1.1097x over previous
#include <cuda_runtime.h>
#include <cuda_fp16.h>
#include <math.h>
#include <stdint.h>

#define S_LEN  4096
#define DMODEL 2048
#define NHEADS 16
#define HDIM   128
#define WIN    512

// ---------------------------------------------------------------------------
// Scratch (__device__ globals: allocation-free rule)
// ---------------------------------------------------------------------------
__device__ __half g_xh[S_LEN * DMODEL];
__device__ __half g_xl[S_LEN * DMODEL];
__device__ __half g_ah[S_LEN * DMODEL];
__device__ __half g_al[S_LEN * DMODEL];
__device__ __half g_qh[S_LEN * DMODEL];
__device__ __half g_ql[S_LEN * DMODEL];
__device__ __half g_kh[S_LEN * DMODEL];
__device__ __half g_vh[S_LEN * DMODEL];
__device__ __half g_wq[DMODEL * DMODEL];
__device__ __half g_wk[DMODEL * DMODEL];
__device__ __half g_wv[DMODEL * DMODEL];
__device__ __half g_wo[DMODEL * DMODEL];
__device__ float2 g_rope[S_LEN * 64];

// ---------------------------------------------------------------------------
// PTX primitives (baseline sm_80+)
// ---------------------------------------------------------------------------
__device__ __forceinline__ uint32_t smem_to_u32(const void* p) {
    uint32_t a;
    asm("{ .reg .u64 t; cvta.to.shared.u64 t, %1; cvt.u32.u64 %0, t; }"
        : "=r"(a) : "l"(p));
    return a;
}

#define CP_ASYNC16(dst, src) \
    asm volatile("cp.async.cg.shared.global [%0], [%1], 16;" \
        :: "r"(dst), "l"(src) : "memory")
#define CP_COMMIT() asm volatile("cp.async.commit_group;" ::: "memory")
#define CP_WAIT1()  asm volatile("cp.async.wait_group 1;" ::: "memory")
#define CP_WAIT0()  asm volatile("cp.async.wait_group 0;" ::: "memory")

#define LDM_X4(r, addr) \
    asm volatile("ldmatrix.sync.aligned.m8n8.x4.shared.b16 {%0,%1,%2,%3}, [%4];" \
        : "=r"((r)[0]), "=r"((r)[1]), "=r"((r)[2]), "=r"((r)[3]) : "r"(addr))

#define LDM_X4_T(r, addr) \
    asm volatile("ldmatrix.sync.aligned.m8n8.x4.trans.shared.b16 {%0,%1,%2,%3}, [%4];" \
        : "=r"((r)[0]), "=r"((r)[1]), "=r"((r)[2]), "=r"((r)[3]) : "r"(addr))

#define MMA_F16(c, a, b0, b1) \
    asm volatile("mma.sync.aligned.m16n8k16.row.col.f32.f16.f16.f32 " \
        "{%0,%1,%2,%3}, {%4,%5,%6,%7}, {%8,%9}, {%0,%1,%2,%3};" \
        : "+f"((c)[0]), "+f"((c)[1]), "+f"((c)[2]), "+f"((c)[3]) \
        : "r"((a)[0]), "r"((a)[1]), "r"((a)[2]), "r"((a)[3]), "r"(b0), "r"(b1))

// ---------------------------------------------------------------------------
// RoPE cos/sin table
// ---------------------------------------------------------------------------
__global__ __launch_bounds__(256) void rope_build(float2* __restrict__ tab) {
    int idx = blockIdx.x * blockDim.x + threadIdx.x;
    if (idx >= S_LEN * 64) return;
    int t = idx & 63;
    int s = idx >> 6;
    float ang = (float)s * exp2f(-(float)t * 0.20762050593045702f);
    float sn, cs;
    sincosf(ang, &sn, &cs);
    tab[idx] = make_float2(cs, sn);
}

// ---------------------------------------------------------------------------
// fp32 -> (fp16 hi, fp16 lo) split, 8 elems/thread
// ---------------------------------------------------------------------------
__global__ __launch_bounds__(256) void cvt_hilo_f16(const float* __restrict__ src,
                                                    __half* __restrict__ hi,
                                                    __half* __restrict__ lo,
                                                    int n8) {
    int i = blockIdx.x * blockDim.x + threadIdx.x;
    if (i >= n8) return;
    const float4* s4 = (const float4*)src + 2 * (size_t)i;
    float4 a = s4[0], b = s4[1];
    float v[8] = {a.x, a.y, a.z, a.w, b.x, b.y, b.z, b.w};
    __align__(16) __half h[8];
    __align__(16) __half l[8];
#pragma unroll
    for (int j = 0; j < 8; j++) {
        h[j] = __float2half_rn(v[j]);
        l[j] = __float2half_rn(v[j] - __half2float(h[j]));
    }
    ((uint4*)hi)[i] = *(const uint4*)h;
    ((uint4*)lo)[i] = *(const uint4*)l;
}

// Four weight matrices fp32 -> fp16 in one launch
__global__ __launch_bounds__(256) void cvt_f16x4(
    const float* __restrict__ s0, const float* __restrict__ s1,
    const float* __restrict__ s2, const float* __restrict__ s3,
    __half* __restrict__ d0, __half* __restrict__ d1,
    __half* __restrict__ d2, __half* __restrict__ d3, int n8) {
    int i = blockIdx.x * blockDim.x + threadIdx.x;
    if (i >= n8) return;
    const int w = blockIdx.y;
    const float* src = (w == 0) ? s0 : (w == 1) ? s1 : (w == 2) ? s2 : s3;
    __half* dst = (w == 0) ? d0 : (w == 1) ? d1 : (w == 2) ? d2 : d3;
    const float4* s4 = (const float4*)src + 2 * (size_t)i;
    float4 a = s4[0], b = s4[1];
    float v[8] = {a.x, a.y, a.z, a.w, b.x, b.y, b.z, b.w};
    __align__(16) __half h[8];
#pragma unroll
    for (int j = 0; j < 8; j++) h[j] = __float2half_rn(v[j]);
    ((uint4*)dst)[i] = *(const uint4*)h;
}

// ---------------------------------------------------------------------------
// Shared GEMM mainloop. use_lo: include the A-lo correction MMA (uniform bool).
// Requires in scope: smem, sbase, tid, lane, wm, wn, m0, n0, acc[4][4][4].
// ---------------------------------------------------------------------------
#define GK DMODEL
#define NI (GK / 32)
#define PAD_ROW_B 80                 // 32 fp16 (64B) + 16B pad
#define TILE_B (128 * PAD_ROW_B)     // 10240
#define STAGE_B (3 * TILE_B)         // Ahi, Alo, B = 30720
#define GEMM_SMEM (3 * STAGE_B)      // 92160

#define GEMM_MAINLOOP(AhiP, AloP, BP, use_lo)                                  \
    const __half* gsrc[3] = {                                                  \
        (AhiP) + (size_t)m0 * GK, (AloP) + (size_t)m0 * GK,                    \
        (BP) + (size_t)n0 * GK};                                               \
    int l_tile[6], l_row[6], l_c16[6];                                         \
    _Pragma("unroll")                                                          \
    for (int t = 0; t < 6; t++) {                                              \
        int linear = t * 256 + tid;                                            \
        l_tile[t] = linear >> 9;                                               \
        int within = linear & 511;                                             \
        l_row[t] = within >> 2;                                                \
        l_c16[t] = within & 3;                                                 \
    }                                                                          \
    _Pragma("unroll")                                                          \
    for (int s = 0; s < 2; s++) {                                              \
        const uint32_t sb = sbase + s * STAGE_B;                               \
        const int k0 = s * 32;                                                 \
        _Pragma("unroll")                                                      \
        for (int t = 0; t < 6; t++) {                                          \
            if ((use_lo) || l_tile[t] != 1) {                                  \
                const __half* src =                                            \
                    gsrc[l_tile[t]] + (size_t)l_row[t] * GK + k0 + l_c16[t] * 8;\
                uint32_t dst = sb + l_tile[t] * TILE_B +                       \
                               l_row[t] * PAD_ROW_B + l_c16[t] * 16;           \
                CP_ASYNC16(dst, src);                                          \
            }                                                                  \
        }                                                                      \
        CP_COMMIT();                                                           \
    }                                                                          \
    _Pragma("unroll")                                                          \
    for (int i = 0; i < 4; i++)                                                \
        _Pragma("unroll")                                                      \
        for (int j = 0; j < 4; j++)                                            \
            _Pragma("unroll")                                                  \
            for (int r = 0; r < 4; r++) acc[i][j][r] = 0.f;                    \
    const int lrow = lane & 15;                                                \
    const int lcol = (lane >> 4) * 16;                                         \
    for (int i = 0; i < NI; i++) {                                             \
        if (i < NI - 1) { CP_WAIT1(); } else { CP_WAIT0(); }                   \
        __syncthreads();                                                       \
        if (i + 2 < NI) {                                                      \
            const int k0n = (i + 2) * 32;                                      \
            const uint32_t sb = sbase + ((i + 2) % 3) * STAGE_B;               \
            _Pragma("unroll")                                                  \
            for (int t = 0; t < 6; t++) {                                      \
                if ((use_lo) || l_tile[t] != 1) {                              \
                    const __half* src = gsrc[l_tile[t]] +                      \
                        (size_t)l_row[t] * GK + k0n + l_c16[t] * 8;            \
                    uint32_t dst = sb + l_tile[t] * TILE_B +                   \
                                   l_row[t] * PAD_ROW_B + l_c16[t] * 16;       \
                    CP_ASYNC16(dst, src);                                      \
                }                                                              \
            }                                                                  \
            CP_COMMIT();                                                       \
        }                                                                      \
        const uint32_t sA = sbase + (i % 3) * STAGE_B;                         \
        _Pragma("unroll")                                                      \
        for (int ks = 0; ks < 2; ks++) {                                       \
            const uint32_t kb = ks * 32;                                       \
            uint32_t b[4][2];                                                  \
            _Pragma("unroll")                                                  \
            for (int j = 0; j < 2; j++) {                                      \
                uint32_t bd = sA + 2 * TILE_B +                                \
                    (wn * 32 + j * 16 + lrow) * PAD_ROW_B + kb + lcol;         \
                uint32_t r[4];                                                 \
                LDM_X4(r, bd);                                                 \
                b[2 * j][0] = r[0]; b[2 * j + 1][0] = r[1];                    \
                b[2 * j][1] = r[2]; b[2 * j + 1][1] = r[3];                    \
            }                                                                  \
            _Pragma("unroll")                                                  \
            for (int mt = 0; mt < 4; mt++) {                                   \
                uint32_t ah[4], al[4];                                         \
                uint32_t ad = sA + (wm * 64 + mt * 16 + lrow) * PAD_ROW_B +    \
                              kb + lcol;                                       \
                LDM_X4(ah, ad);                                                \
                if (use_lo) { LDM_X4(al, ad + TILE_B); }                       \
                _Pragma("unroll")                                              \
                for (int nt = 0; nt < 4; nt++) {                               \
                    MMA_F16(acc[mt][nt], ah, b[nt][0], b[nt][1]);              \
                }                                                              \
                if (use_lo) {                                                  \
                    _Pragma("unroll")                                          \
                    for (int nt = 0; nt < 4; nt++) {                           \
                        MMA_F16(acc[mt][nt], al, b[nt][0], b[nt][1]);          \
                    }                                                          \
                }                                                              \
            }                                                                  \
        }                                                                      \
    }

// ---------------------------------------------------------------------------
// QKV GEMM with fused RoPE + fp16 epilogue. blockIdx.z: 0=Q (hi/lo, 2 MMAs),
// 1=K (1 MMA), 2=V (1 MMA). K/V outputs are rounded to fp16 anyway, so the
// A-lo correction is skipped for them.
// ---------------------------------------------------------------------------
__global__ __launch_bounds__(256, 2) void gemm_qkv(
    const __half* __restrict__ Ahi, const __half* __restrict__ Alo,
    const __half* __restrict__ B0, const __half* __restrict__ B1,
    const __half* __restrict__ B2,
    __half* __restrict__ qh, __half* __restrict__ ql,
    __half* __restrict__ kh, __half* __restrict__ vh,
    const float2* __restrict__ rope) {
    extern __shared__ char smem[];
    const uint32_t sbase = smem_to_u32(smem);
    const int tid  = threadIdx.x;
    const int wid  = tid >> 5;
    const int lane = tid & 31;
    const int wm   = wid & 1;
    const int wn   = wid >> 1;
    const int m0   = blockIdx.y * 128;
    const int n0   = blockIdx.x * 128;
    const int z    = blockIdx.z;
    const __half* B = (z == 0) ? B0 : (z == 1) ? B1 : B2;
    const bool use_lo = (z == 0);

    float acc[4][4][4];
    GEMM_MAINLOOP(Ahi, Alo, B, use_lo)

#pragma unroll
    for (int mt = 0; mt < 4; mt++) {
        const int r = m0 + wm * 64 + mt * 16 + (lane >> 2);
#pragma unroll
        for (int nt = 0; nt < 4; nt++) {
            const int c = n0 + wn * 32 + nt * 8 + (lane & 3) * 2;
            const size_t o0 = (size_t)r * DMODEL + c;
            const size_t o1 = (size_t)(r + 8) * DMODEL + c;
            if (z == 2) {
                *(half2*)(vh + o0) = __floats2half2_rn(acc[mt][nt][0], acc[mt][nt][1]);
                *(half2*)(vh + o1) = __floats2half2_rn(acc[mt][nt][2], acc[mt][nt][3]);
            } else {
                const int t = (c & 127) >> 1;
                float2 cs0 = rope[r * 64 + t];
                float2 cs1 = rope[(r + 8) * 64 + t];
                float a1 = acc[mt][nt][0] * cs0.x - acc[mt][nt][1] * cs0.y;
                float a2 = acc[mt][nt][0] * cs0.y + acc[mt][nt][1] * cs0.x;
                float b1 = acc[mt][nt][2] * cs1.x - acc[mt][nt][3] * cs1.y;
                float b2 = acc[mt][nt][2] * cs1.y + acc[mt][nt][3] * cs1.x;
                if (z == 1) {
                    *(half2*)(kh + o0) = __floats2half2_rn(a1, a2);
                    *(half2*)(kh + o1) = __floats2half2_rn(b1, b2);
                } else {
                    __half h1 = __float2half_rn(a1), h2 = __float2half_rn(a2);
                    __half h3 = __float2half_rn(b1), h4 = __float2half_rn(b2);
                    *(half2*)(qh + o0) = __halves2half2(h1, h2);
                    *(half2*)(qh + o1) = __halves2half2(h3, h4);
                    *(half2*)(ql + o0) = __floats2half2_rn(
                        a1 - __half2float(h1), a2 - __half2float(h2));
                    *(half2*)(ql + o1) = __floats2half2_rn(
                        b1 - __half2float(h3), b2 - __half2float(h4));
                }
            }
        }
    }
}

// ---------------------------------------------------------------------------
// Output projection GEMM: fp32 epilogue to d_out. Keeps 2 MMAs.
// ---------------------------------------------------------------------------
__global__ __launch_bounds__(256, 2) void gemm_out(
    const __half* __restrict__ Ahi, const __half* __restrict__ Alo,
    const __half* __restrict__ Bw, float* __restrict__ C) {
    extern __shared__ char smem[];
    const uint32_t sbase = smem_to_u32(smem);
    const int tid  = threadIdx.x;
    const int wid  = tid >> 5;
    const int lane = tid & 31;
    const int wm   = wid & 1;
    const int wn   = wid >> 1;
    const int m0   = blockIdx.y * 128;
    const int n0   = blockIdx.x * 128;

    float acc[4][4][4];
    GEMM_MAINLOOP(Ahi, Alo, Bw, true)

#pragma unroll
    for (int mt = 0; mt < 4; mt++) {
        const int r = m0 + wm * 64 + mt * 16 + (lane >> 2);
#pragma unroll
        for (int nt = 0; nt < 4; nt++) {
            const int c = n0 + wn * 32 + nt * 8 + (lane & 3) * 2;
            *(float2*)(C + (size_t)r * DMODEL + c) =
                make_float2(acc[mt][nt][0], acc[mt][nt][1]);
            *(float2*)(C + (size_t)(r + 8) * DMODEL + c) =
                make_float2(acc[mt][nt][2], acc[mt][nt][3]);
        }
    }
}

// ---------------------------------------------------------------------------
// HMMA flash attention (unchanged from R6).
// ---------------------------------------------------------------------------
#define AROW 272
#define QT_B (64 * AROW)
#define ATTN_SMEM (4 * QT_B)

__global__ __launch_bounds__(128) void attn_mma(const __half* __restrict__ qh,
                                                const __half* __restrict__ ql,
                                                const __half* __restrict__ kh,
                                                const __half* __restrict__ vh,
                                                __half* __restrict__ oh,
                                                __half* __restrict__ ol) {
    extern __shared__ char smem[];
    const uint32_t sbase = smem_to_u32(smem);
    const uint32_t sQh = sbase;
    const uint32_t sK  = sbase + 2 * QT_B;
    const uint32_t sV  = sbase + 3 * QT_B;

    const int h    = blockIdx.y;
    const int q0   = blockIdx.x * 64;
    const int tid  = threadIdx.x;
    const int wid  = tid >> 5;
    const int lane = tid & 31;
    const int lrow = lane & 15;
    const int lcol = (lane >> 4) * 16;
    const float SCALE = 0.088388347648318447f;

    for (int ch = tid; ch < 64 * 16; ch += 128) {
        int row = ch >> 4, c8 = ch & 15;
        size_t g = (size_t)(q0 + row) * DMODEL + h * HDIM + c8 * 8;
        *(uint4*)(smem + (row * AROW + c8 * 16))        = *(const uint4*)(qh + g);
        *(uint4*)(smem + QT_B + (row * AROW + c8 * 16)) = *(const uint4*)(ql + g);
    }

    float O[16][4];
#pragma unroll
    for (int i = 0; i < 16; i++)
#pragma unroll
        for (int r = 0; r < 4; r++) O[i][r] = 0.f;
    float m0 = -1e30f, m1 = -1e30f, l0 = 0.f, l1 = 0.f;

    const int r0g = q0 + wid * 16 + (lane >> 2);
    const int r1g = r0g + 8;
    const int cbeg = max(0, q0 - (WIN - 1)) & ~63;

    for (int c = cbeg; c <= q0; c += 64) {
        __syncthreads();
        for (int ch = tid; ch < 64 * 16; ch += 128) {
            int row = ch >> 4, c8 = ch & 15;
            size_t g = (size_t)(c + row) * DMODEL + h * HDIM + c8 * 8;
            *(uint4*)(smem + 2 * QT_B + (row * AROW + c8 * 16)) = *(const uint4*)(kh + g);
            *(uint4*)(smem + 3 * QT_B + (row * AROW + c8 * 16)) = *(const uint4*)(vh + g);
        }
        __syncthreads();

        float S[8][4];
#pragma unroll
        for (int nt = 0; nt < 8; nt++)
#pragma unroll
            for (int r = 0; r < 4; r++) S[nt][r] = 0.f;

#pragma unroll
        for (int ks = 0; ks < 8; ks++) {
            uint32_t aH[4], aL[4];
            uint32_t qa = sQh + (wid * 16 + lrow) * AROW + ks * 32 + lcol;
            LDM_X4(aH, qa);
            LDM_X4(aL, qa + QT_B);
#pragma unroll
            for (int nb = 0; nb < 4; nb++) {
                uint32_t r[4];
                LDM_X4(r, sK + (nb * 16 + lrow) * AROW + ks * 32 + lcol);
                MMA_F16(S[2 * nb],     aH, r[0], r[2]);
                MMA_F16(S[2 * nb + 1], aH, r[1], r[3]);
                MMA_F16(S[2 * nb],     aL, r[0], r[2]);
                MMA_F16(S[2 * nb + 1], aL, r[1], r[3]);
            }
        }

        const bool need_mask = (c + 63 > q0) || (q0 + 63 - c >= WIN);
        if (need_mask) {
#pragma unroll
            for (int nt = 0; nt < 8; nt++) {
                int colb = c + nt * 8 + (lane & 3) * 2;
                if (colb > r0g     || r0g - colb >= WIN)     S[nt][0] = -1e30f;
                if (colb + 1 > r0g || r0g - colb - 1 >= WIN) S[nt][1] = -1e30f;
                if (colb > r1g     || r1g - colb >= WIN)     S[nt][2] = -1e30f;
                if (colb + 1 > r1g || r1g - colb - 1 >= WIN) S[nt][3] = -1e30f;
            }
        }

        float mx0 = -1e30f, mx1 = -1e30f;
#pragma unroll
        for (int nt = 0; nt < 8; nt++) {
            mx0 = fmaxf(mx0, fmaxf(S[nt][0], S[nt][1]));
            mx1 = fmaxf(mx1, fmaxf(S[nt][2], S[nt][3]));
        }
        mx0 = fmaxf(mx0, __shfl_xor_sync(0xffffffffu, mx0, 1));
        mx0 = fmaxf(mx0, __shfl_xor_sync(0xffffffffu, mx0, 2));
        mx1 = fmaxf(mx1, __shfl_xor_sync(0xffffffffu, mx1, 1));
        mx1 = fmaxf(mx1, __shfl_xor_sync(0xffffffffu, mx1, 2));

        float mn0 = fmaxf(m0, mx0 * SCALE);
        float mn1 = fmaxf(m1, mx1 * SCALE);
        float c0 = __expf(m0 - mn0);
        float c1 = __expf(m1 - mn1);
        l0 *= c0; l1 *= c1;
#pragma unroll
        for (int nt = 0; nt < 16; nt++) {
            O[nt][0] *= c0; O[nt][1] *= c0;
            O[nt][2] *= c1; O[nt][3] *= c1;
        }
        m0 = mn0; m1 = mn1;

        uint32_t P[8][2];
#pragma unroll
        for (int nt = 0; nt < 8; nt++) {
            float p0 = __expf(S[nt][0] * SCALE - m0);
            float p1 = __expf(S[nt][1] * SCALE - m0);
            float p2 = __expf(S[nt][2] * SCALE - m1);
            float p3 = __expf(S[nt][3] * SCALE - m1);
            l0 += p0 + p1; l1 += p2 + p3;
            __half2 h01 = __floats2half2_rn(p0, p1);
            __half2 h23 = __floats2half2_rn(p2, p3);
            P[nt][0] = *(uint32_t*)&h01;
            P[nt][1] = *(uint32_t*)&h23;
        }

#pragma unroll
        for (int u = 0; u < 4; u++) {
            uint32_t pa[4] = {P[2 * u][0], P[2 * u][1], P[2 * u + 1][0], P[2 * u + 1][1]};
#pragma unroll
            for (int db = 0; db < 8; db++) {
                uint32_t r[4];
                LDM_X4_T(r, sV + (u * 16 + lrow) * AROW + db * 32 + lcol);
                MMA_F16(O[2 * db],     pa, r[0], r[1]);
                MMA_F16(O[2 * db + 1], pa, r[2], r[3]);
            }
        }
    }

    l0 += __shfl_xor_sync(0xffffffffu, l0, 1);
    l0 += __shfl_xor_sync(0xffffffffu, l0, 2);
    l1 += __shfl_xor_sync(0xffffffffu, l1, 1);
    l1 += __shfl_xor_sync(0xffffffffu, l1, 2);
    float inv0 = 1.f / l0;
    float inv1 = 1.f / l1;

#pragma unroll
    for (int nt = 0; nt < 16; nt++) {
        int colb = h * HDIM + nt * 8 + (lane & 3) * 2;
        float a0 = O[nt][0] * inv0, a1 = O[nt][1] * inv0;
        float b0 = O[nt][2] * inv1, b1 = O[nt][3] * inv1;
        __half h0 = __float2half_rn(a0), h1 = __float2half_rn(a1);
        __half h2 = __float2half_rn(b0), h3 = __float2half_rn(b1);
        *(half2*)(oh + (size_t)r0g * DMODEL + colb) = __halves2half2(h0, h1);
        *(half2*)(oh + (size_t)r1g * DMODEL + colb) = __halves2half2(h2, h3);
        *(half2*)(ol + (size_t)r0g * DMODEL + colb) = __floats2half2_rn(
            a0 - __half2float(h0), a1 - __half2float(h1));
        *(half2*)(ol + (size_t)r1g * DMODEL + colb) = __floats2half2_rn(
            b0 - __half2float(h2), b1 - __half2float(h3));
    }
}

// ---------------------------------------------------------------------------
// Launch
// ---------------------------------------------------------------------------
extern "C" void kernel_launch(void* const* d_in, const int* in_sizes, int n_in,
                              void* d_out, int out_size) {
    const float* x  = (const float*)d_in[0];
    const float* Wq = (const float*)d_in[1];
    const float* Wk = (const float*)d_in[2];
    const float* Wv = (const float*)d_in[3];
    const float* Wo = (const float*)d_in[4];
    float* out = (float*)d_out;

    __half *xh, *xl, *ah, *al, *qhp, *qlp, *khp, *vhp;
    __half *wq, *wk, *wv, *wo;
    float2* ropetab;
    cudaGetSymbolAddress((void**)&xh, g_xh);
    cudaGetSymbolAddress((void**)&xl, g_xl);
    cudaGetSymbolAddress((void**)&ah, g_ah);
    cudaGetSymbolAddress((void**)&al, g_al);
    cudaGetSymbolAddress((void**)&qhp, g_qh);
    cudaGetSymbolAddress((void**)&qlp, g_ql);
    cudaGetSymbolAddress((void**)&khp, g_kh);
    cudaGetSymbolAddress((void**)&vhp, g_vh);
    cudaGetSymbolAddress((void**)&wq, g_wq);
    cudaGetSymbolAddress((void**)&wk, g_wk);
    cudaGetSymbolAddress((void**)&wv, g_wv);
    cudaGetSymbolAddress((void**)&wo, g_wo);
    cudaGetSymbolAddress((void**)&ropetab, g_rope);

    cudaFuncSetAttribute(gemm_qkv,
                         cudaFuncAttributeMaxDynamicSharedMemorySize, GEMM_SMEM);
    cudaFuncSetAttribute(gemm_out,
                         cudaFuncAttributeMaxDynamicSharedMemorySize, GEMM_SMEM);
    cudaFuncSetAttribute(attn_mma,
                         cudaFuncAttributeMaxDynamicSharedMemorySize, ATTN_SMEM);

    const int nx8 = S_LEN * DMODEL / 8;
    const int nw8 = DMODEL * DMODEL / 8;
    rope_build<<<(S_LEN * 64 + 255) / 256, 256>>>(ropetab);
    cvt_hilo_f16<<<(nx8 + 255) / 256, 256>>>(x, xh, xl, nx8);
    cvt_f16x4<<<dim3((nw8 + 255) / 256, 4), 256>>>(Wq, Wk, Wv, Wo,
                                                   wq, wk, wv, wo, nw8);

    dim3 gqkv(DMODEL / 128, S_LEN / 128, 3);
    gemm_qkv<<<gqkv, 256, GEMM_SMEM>>>(xh, xl, wq, wk, wv,
                                       qhp, qlp, khp, vhp, ropetab);

    attn_mma<<<dim3(S_LEN / 64, NHEADS), 128, ATTN_SMEM>>>(qhp, qlp, khp, vhp,
                                                           ah, al);

    dim3 go(DMODEL / 128, S_LEN / 128);
    gemm_out<<<go, 256, GEMM_SMEM>>>(ah, al, wo, out);
}

// round 8
// speedup vs baseline: 7.1362x; 1.2709x over previous
#include <cuda_runtime.h>
#include <cuda_fp16.h>
#include <math.h>
#include <stdint.h>

#define S_LEN  4096
#define DMODEL 2048
#define NHEADS 16
#define HDIM   128
#define WIN    512

// ---------------------------------------------------------------------------
// Scratch (__device__ globals: allocation-free rule)
// ---------------------------------------------------------------------------
__device__ __half g_xh[S_LEN * DMODEL];
__device__ __half g_ah[S_LEN * DMODEL];
__device__ __half g_al[S_LEN * DMODEL];
__device__ __half g_qh[S_LEN * DMODEL];
__device__ __half g_kh[S_LEN * DMODEL];
__device__ __half g_vh[S_LEN * DMODEL];
__device__ __half g_wq[DMODEL * DMODEL];
__device__ __half g_wk[DMODEL * DMODEL];
__device__ __half g_wv[DMODEL * DMODEL];
__device__ __half g_wo[DMODEL * DMODEL];
__device__ float2 g_rope[S_LEN * 64];

// ---------------------------------------------------------------------------
// PTX primitives (baseline sm_80+)
// ---------------------------------------------------------------------------
__device__ __forceinline__ uint32_t smem_to_u32(const void* p) {
    uint32_t a;
    asm("{ .reg .u64 t; cvta.to.shared.u64 t, %1; cvt.u32.u64 %0, t; }"
        : "=r"(a) : "l"(p));
    return a;
}

#define CP_ASYNC16(dst, src) \
    asm volatile("cp.async.cg.shared.global [%0], [%1], 16;" \
        :: "r"(dst), "l"(src) : "memory")
#define CP_COMMIT() asm volatile("cp.async.commit_group;" ::: "memory")
#define CP_WAIT1()  asm volatile("cp.async.wait_group 1;" ::: "memory")
#define CP_WAIT0()  asm volatile("cp.async.wait_group 0;" ::: "memory")

#define LDM_X4(r, addr) \
    asm volatile("ldmatrix.sync.aligned.m8n8.x4.shared.b16 {%0,%1,%2,%3}, [%4];" \
        : "=r"((r)[0]), "=r"((r)[1]), "=r"((r)[2]), "=r"((r)[3]) : "r"(addr))

#define LDM_X4_T(r, addr) \
    asm volatile("ldmatrix.sync.aligned.m8n8.x4.trans.shared.b16 {%0,%1,%2,%3}, [%4];" \
        : "=r"((r)[0]), "=r"((r)[1]), "=r"((r)[2]), "=r"((r)[3]) : "r"(addr))

#define MMA_F16(c, a, b0, b1) \
    asm volatile("mma.sync.aligned.m16n8k16.row.col.f32.f16.f16.f32 " \
        "{%0,%1,%2,%3}, {%4,%5,%6,%7}, {%8,%9}, {%0,%1,%2,%3};" \
        : "+f"((c)[0]), "+f"((c)[1]), "+f"((c)[2]), "+f"((c)[3]) \
        : "r"((a)[0]), "r"((a)[1]), "r"((a)[2]), "r"((a)[3]), "r"(b0), "r"(b1))

// ---------------------------------------------------------------------------
// RoPE cos/sin table
// ---------------------------------------------------------------------------
__global__ __launch_bounds__(256) void rope_build(float2* __restrict__ tab) {
    int idx = blockIdx.x * blockDim.x + threadIdx.x;
    if (idx >= S_LEN * 64) return;
    int t = idx & 63;
    int s = idx >> 6;
    float ang = (float)s * exp2f(-(float)t * 0.20762050593045702f);
    float sn, cs;
    sincosf(ang, &sn, &cs);
    tab[idx] = make_float2(cs, sn);
}

// ---------------------------------------------------------------------------
// fp32 -> fp16 single, 8 elems/thread
// ---------------------------------------------------------------------------
__global__ __launch_bounds__(256) void cvt_f16(const float* __restrict__ src,
                                               __half* __restrict__ dst, int n8) {
    int i = blockIdx.x * blockDim.x + threadIdx.x;
    if (i >= n8) return;
    const float4* s4 = (const float4*)src + 2 * (size_t)i;
    float4 a = s4[0], b = s4[1];
    float v[8] = {a.x, a.y, a.z, a.w, b.x, b.y, b.z, b.w};
    __align__(16) __half h[8];
#pragma unroll
    for (int j = 0; j < 8; j++) h[j] = __float2half_rn(v[j]);
    ((uint4*)dst)[i] = *(const uint4*)h;
}

// Four weight matrices fp32 -> fp16 in one launch
__global__ __launch_bounds__(256) void cvt_f16x4(
    const float* __restrict__ s0, const float* __restrict__ s1,
    const float* __restrict__ s2, const float* __restrict__ s3,
    __half* __restrict__ d0, __half* __restrict__ d1,
    __half* __restrict__ d2, __half* __restrict__ d3, int n8) {
    int i = blockIdx.x * blockDim.x + threadIdx.x;
    if (i >= n8) return;
    const int w = blockIdx.y;
    const float* src = (w == 0) ? s0 : (w == 1) ? s1 : (w == 2) ? s2 : s3;
    __half* dst = (w == 0) ? d0 : (w == 1) ? d1 : (w == 2) ? d2 : d3;
    const float4* s4 = (const float4*)src + 2 * (size_t)i;
    float4 a = s4[0], b = s4[1];
    float v[8] = {a.x, a.y, a.z, a.w, b.x, b.y, b.z, b.w};
    __align__(16) __half h[8];
#pragma unroll
    for (int j = 0; j < 8; j++) h[j] = __float2half_rn(v[j]);
    ((uint4*)dst)[i] = *(const uint4*)h;
}

// ---------------------------------------------------------------------------
// Shared GEMM mainloop. use_lo: include the A-lo correction MMA (uniform bool).
// Requires in scope: smem, sbase, tid, lane, wm, wn, m0, n0, acc[4][4][4].
// ---------------------------------------------------------------------------
#define GK DMODEL
#define NI (GK / 32)
#define PAD_ROW_B 80                 // 32 fp16 (64B) + 16B pad
#define TILE_B (128 * PAD_ROW_B)     // 10240
#define STAGE_B (3 * TILE_B)         // Ahi, Alo, B slots = 30720
#define GEMM_SMEM (3 * STAGE_B)      // 92160

#define GEMM_MAINLOOP(AhiP, AloP, BP, use_lo)                                  \
    const __half* gsrc[3] = {                                                  \
        (AhiP) + (size_t)m0 * GK, (AloP) + (size_t)m0 * GK,                    \
        (BP) + (size_t)n0 * GK};                                               \
    int l_tile[6], l_row[6], l_c16[6];                                         \
    _Pragma("unroll")                                                          \
    for (int t = 0; t < 6; t++) {                                              \
        int linear = t * 256 + tid;                                            \
        l_tile[t] = linear >> 9;                                               \
        int within = linear & 511;                                             \
        l_row[t] = within >> 2;                                                \
        l_c16[t] = within & 3;                                                 \
    }                                                                          \
    _Pragma("unroll")                                                          \
    for (int s = 0; s < 2; s++) {                                              \
        const uint32_t sb = sbase + s * STAGE_B;                               \
        const int k0 = s * 32;                                                 \
        _Pragma("unroll")                                                      \
        for (int t = 0; t < 6; t++) {                                          \
            if ((use_lo) || l_tile[t] != 1) {                                  \
                const __half* src =                                            \
                    gsrc[l_tile[t]] + (size_t)l_row[t] * GK + k0 + l_c16[t] * 8;\
                uint32_t dst = sb + l_tile[t] * TILE_B +                       \
                               l_row[t] * PAD_ROW_B + l_c16[t] * 16;           \
                CP_ASYNC16(dst, src);                                          \
            }                                                                  \
        }                                                                      \
        CP_COMMIT();                                                           \
    }                                                                          \
    _Pragma("unroll")                                                          \
    for (int i = 0; i < 4; i++)                                                \
        _Pragma("unroll")                                                      \
        for (int j = 0; j < 4; j++)                                            \
            _Pragma("unroll")                                                  \
            for (int r = 0; r < 4; r++) acc[i][j][r] = 0.f;                    \
    const int lrow = lane & 15;                                                \
    const int lcol = (lane >> 4) * 16;                                         \
    for (int i = 0; i < NI; i++) {                                             \
        if (i < NI - 1) { CP_WAIT1(); } else { CP_WAIT0(); }                   \
        __syncthreads();                                                       \
        if (i + 2 < NI) {                                                      \
            const int k0n = (i + 2) * 32;                                      \
            const uint32_t sb = sbase + ((i + 2) % 3) * STAGE_B;               \
            _Pragma("unroll")                                                  \
            for (int t = 0; t < 6; t++) {                                      \
                if ((use_lo) || l_tile[t] != 1) {                              \
                    const __half* src = gsrc[l_tile[t]] +                      \
                        (size_t)l_row[t] * GK + k0n + l_c16[t] * 8;            \
                    uint32_t dst = sb + l_tile[t] * TILE_B +                   \
                                   l_row[t] * PAD_ROW_B + l_c16[t] * 16;       \
                    CP_ASYNC16(dst, src);                                      \
                }                                                              \
            }                                                                  \
            CP_COMMIT();                                                       \
        }                                                                      \
        const uint32_t sA = sbase + (i % 3) * STAGE_B;                         \
        _Pragma("unroll")                                                      \
        for (int ks = 0; ks < 2; ks++) {                                       \
            const uint32_t kb = ks * 32;                                       \
            uint32_t b[4][2];                                                  \
            _Pragma("unroll")                                                  \
            for (int j = 0; j < 2; j++) {                                      \
                uint32_t bd = sA + 2 * TILE_B +                                \
                    (wn * 32 + j * 16 + lrow) * PAD_ROW_B + kb + lcol;         \
                uint32_t r[4];                                                 \
                LDM_X4(r, bd);                                                 \
                b[2 * j][0] = r[0]; b[2 * j + 1][0] = r[1];                    \
                b[2 * j][1] = r[2]; b[2 * j + 1][1] = r[3];                    \
            }                                                                  \
            _Pragma("unroll")                                                  \
            for (int mt = 0; mt < 4; mt++) {                                   \
                uint32_t ah[4], al[4];                                         \
                uint32_t ad = sA + (wm * 64 + mt * 16 + lrow) * PAD_ROW_B +    \
                              kb + lcol;                                       \
                LDM_X4(ah, ad);                                                \
                if (use_lo) { LDM_X4(al, ad + TILE_B); }                       \
                _Pragma("unroll")                                              \
                for (int nt = 0; nt < 4; nt++) {                               \
                    MMA_F16(acc[mt][nt], ah, b[nt][0], b[nt][1]);              \
                }                                                              \
                if (use_lo) {                                                  \
                    _Pragma("unroll")                                          \
                    for (int nt = 0; nt < 4; nt++) {                           \
                        MMA_F16(acc[mt][nt], al, b[nt][0], b[nt][1]);          \
                    }                                                          \
                }                                                              \
            }                                                                  \
        }                                                                      \
    }

// ---------------------------------------------------------------------------
// QKV GEMM, single fp16 MMA for all of Q/K/V (outputs are fp16-quantized
// anyway). Fused RoPE epilogue for Q and K. blockIdx.z: 0=Q, 1=K, 2=V.
// ---------------------------------------------------------------------------
__global__ __launch_bounds__(256, 2) void gemm_qkv(
    const __half* __restrict__ Ah,
    const __half* __restrict__ B0, const __half* __restrict__ B1,
    const __half* __restrict__ B2,
    __half* __restrict__ qh, __half* __restrict__ kh, __half* __restrict__ vh,
    const float2* __restrict__ rope) {
    extern __shared__ char smem[];
    const uint32_t sbase = smem_to_u32(smem);
    const int tid  = threadIdx.x;
    const int wid  = tid >> 5;
    const int lane = tid & 31;
    const int wm   = wid & 1;
    const int wn   = wid >> 1;
    const int m0   = blockIdx.y * 128;
    const int n0   = blockIdx.x * 128;
    const int z    = blockIdx.z;
    const __half* B = (z == 0) ? B0 : (z == 1) ? B1 : B2;

    float acc[4][4][4];
    GEMM_MAINLOOP(Ah, Ah, B, false)

    __half* outp = (z == 0) ? qh : (z == 1) ? kh : vh;
#pragma unroll
    for (int mt = 0; mt < 4; mt++) {
        const int r = m0 + wm * 64 + mt * 16 + (lane >> 2);
#pragma unroll
        for (int nt = 0; nt < 4; nt++) {
            const int c = n0 + wn * 32 + nt * 8 + (lane & 3) * 2;
            const size_t o0 = (size_t)r * DMODEL + c;
            const size_t o1 = (size_t)(r + 8) * DMODEL + c;
            if (z == 2) {
                *(half2*)(outp + o0) = __floats2half2_rn(acc[mt][nt][0], acc[mt][nt][1]);
                *(half2*)(outp + o1) = __floats2half2_rn(acc[mt][nt][2], acc[mt][nt][3]);
            } else {
                const int t = (c & 127) >> 1;
                float2 cs0 = rope[r * 64 + t];
                float2 cs1 = rope[(r + 8) * 64 + t];
                float a1 = acc[mt][nt][0] * cs0.x - acc[mt][nt][1] * cs0.y;
                float a2 = acc[mt][nt][0] * cs0.y + acc[mt][nt][1] * cs0.x;
                float b1 = acc[mt][nt][2] * cs1.x - acc[mt][nt][3] * cs1.y;
                float b2 = acc[mt][nt][2] * cs1.y + acc[mt][nt][3] * cs1.x;
                *(half2*)(outp + o0) = __floats2half2_rn(a1, a2);
                *(half2*)(outp + o1) = __floats2half2_rn(b1, b2);
            }
        }
    }
}

// ---------------------------------------------------------------------------
// Output projection GEMM: A hi/lo (2 MMAs), fp32 epilogue to d_out.
// ---------------------------------------------------------------------------
__global__ __launch_bounds__(256, 2) void gemm_out(
    const __half* __restrict__ Ahi, const __half* __restrict__ Alo,
    const __half* __restrict__ Bw, float* __restrict__ C) {
    extern __shared__ char smem[];
    const uint32_t sbase = smem_to_u32(smem);
    const int tid  = threadIdx.x;
    const int wid  = tid >> 5;
    const int lane = tid & 31;
    const int wm   = wid & 1;
    const int wn   = wid >> 1;
    const int m0   = blockIdx.y * 128;
    const int n0   = blockIdx.x * 128;

    float acc[4][4][4];
    GEMM_MAINLOOP(Ahi, Alo, Bw, true)

#pragma unroll
    for (int mt = 0; mt < 4; mt++) {
        const int r = m0 + wm * 64 + mt * 16 + (lane >> 2);
#pragma unroll
        for (int nt = 0; nt < 4; nt++) {
            const int c = n0 + wn * 32 + nt * 8 + (lane & 3) * 2;
            *(float2*)(C + (size_t)r * DMODEL + c) =
                make_float2(acc[mt][nt][0], acc[mt][nt][1]);
            *(float2*)(C + (size_t)(r + 8) * DMODEL + c) =
                make_float2(acc[mt][nt][2], acc[mt][nt][3]);
        }
    }
}

// ---------------------------------------------------------------------------
// HMMA flash attention. Q single fp16 now -> 1 score MMA per fragment.
// Epilogue still writes hi/lo split (feeds the corrected out-projection).
// ---------------------------------------------------------------------------
#define AROW 272
#define QT_B (64 * AROW)
#define ATTN_SMEM (3 * QT_B)          // Q, K, V

__global__ __launch_bounds__(128) void attn_mma(const __half* __restrict__ qh,
                                                const __half* __restrict__ kh,
                                                const __half* __restrict__ vh,
                                                __half* __restrict__ oh,
                                                __half* __restrict__ ol) {
    extern __shared__ char smem[];
    const uint32_t sbase = smem_to_u32(smem);
    const uint32_t sQ = sbase;
    const uint32_t sK = sbase + QT_B;
    const uint32_t sV = sbase + 2 * QT_B;

    const int h    = blockIdx.y;
    const int q0   = blockIdx.x * 64;
    const int tid  = threadIdx.x;
    const int wid  = tid >> 5;
    const int lane = tid & 31;
    const int lrow = lane & 15;
    const int lcol = (lane >> 4) * 16;
    const float SCALE = 0.088388347648318447f;

    for (int ch = tid; ch < 64 * 16; ch += 128) {
        int row = ch >> 4, c8 = ch & 15;
        size_t g = (size_t)(q0 + row) * DMODEL + h * HDIM + c8 * 8;
        *(uint4*)(smem + (row * AROW + c8 * 16)) = *(const uint4*)(qh + g);
    }

    float O[16][4];
#pragma unroll
    for (int i = 0; i < 16; i++)
#pragma unroll
        for (int r = 0; r < 4; r++) O[i][r] = 0.f;
    float m0 = -1e30f, m1 = -1e30f, l0 = 0.f, l1 = 0.f;

    const int r0g = q0 + wid * 16 + (lane >> 2);
    const int r1g = r0g + 8;
    const int cbeg = max(0, q0 - (WIN - 1)) & ~63;

    for (int c = cbeg; c <= q0; c += 64) {
        __syncthreads();
        for (int ch = tid; ch < 64 * 16; ch += 128) {
            int row = ch >> 4, c8 = ch & 15;
            size_t g = (size_t)(c + row) * DMODEL + h * HDIM + c8 * 8;
            *(uint4*)(smem + QT_B + (row * AROW + c8 * 16))     = *(const uint4*)(kh + g);
            *(uint4*)(smem + 2 * QT_B + (row * AROW + c8 * 16)) = *(const uint4*)(vh + g);
        }
        __syncthreads();

        float S[8][4];
#pragma unroll
        for (int nt = 0; nt < 8; nt++)
#pragma unroll
            for (int r = 0; r < 4; r++) S[nt][r] = 0.f;

#pragma unroll
        for (int ks = 0; ks < 8; ks++) {
            uint32_t aQ[4];
            LDM_X4(aQ, sQ + (wid * 16 + lrow) * AROW + ks * 32 + lcol);
#pragma unroll
            for (int nb = 0; nb < 4; nb++) {
                uint32_t r[4];
                LDM_X4(r, sK + (nb * 16 + lrow) * AROW + ks * 32 + lcol);
                MMA_F16(S[2 * nb],     aQ, r[0], r[2]);
                MMA_F16(S[2 * nb + 1], aQ, r[1], r[3]);
            }
        }

        const bool need_mask = (c + 63 > q0) || (q0 + 63 - c >= WIN);
        if (need_mask) {
#pragma unroll
            for (int nt = 0; nt < 8; nt++) {
                int colb = c + nt * 8 + (lane & 3) * 2;
                if (colb > r0g     || r0g - colb >= WIN)     S[nt][0] = -1e30f;
                if (colb + 1 > r0g || r0g - colb - 1 >= WIN) S[nt][1] = -1e30f;
                if (colb > r1g     || r1g - colb >= WIN)     S[nt][2] = -1e30f;
                if (colb + 1 > r1g || r1g - colb - 1 >= WIN) S[nt][3] = -1e30f;
            }
        }

        float mx0 = -1e30f, mx1 = -1e30f;
#pragma unroll
        for (int nt = 0; nt < 8; nt++) {
            mx0 = fmaxf(mx0, fmaxf(S[nt][0], S[nt][1]));
            mx1 = fmaxf(mx1, fmaxf(S[nt][2], S[nt][3]));
        }
        mx0 = fmaxf(mx0, __shfl_xor_sync(0xffffffffu, mx0, 1));
        mx0 = fmaxf(mx0, __shfl_xor_sync(0xffffffffu, mx0, 2));
        mx1 = fmaxf(mx1, __shfl_xor_sync(0xffffffffu, mx1, 1));
        mx1 = fmaxf(mx1, __shfl_xor_sync(0xffffffffu, mx1, 2));

        float mn0 = fmaxf(m0, mx0 * SCALE);
        float mn1 = fmaxf(m1, mx1 * SCALE);
        float c0 = __expf(m0 - mn0);
        float c1 = __expf(m1 - mn1);
        l0 *= c0; l1 *= c1;
#pragma unroll
        for (int nt = 0; nt < 16; nt++) {
            O[nt][0] *= c0; O[nt][1] *= c0;
            O[nt][2] *= c1; O[nt][3] *= c1;
        }
        m0 = mn0; m1 = mn1;

        uint32_t P[8][2];
#pragma unroll
        for (int nt = 0; nt < 8; nt++) {
            float p0 = __expf(S[nt][0] * SCALE - m0);
            float p1 = __expf(S[nt][1] * SCALE - m0);
            float p2 = __expf(S[nt][2] * SCALE - m1);
            float p3 = __expf(S[nt][3] * SCALE - m1);
            l0 += p0 + p1; l1 += p2 + p3;
            __half2 h01 = __floats2half2_rn(p0, p1);
            __half2 h23 = __floats2half2_rn(p2, p3);
            P[nt][0] = *(uint32_t*)&h01;
            P[nt][1] = *(uint32_t*)&h23;
        }

#pragma unroll
        for (int u = 0; u < 4; u++) {
            uint32_t pa[4] = {P[2 * u][0], P[2 * u][1], P[2 * u + 1][0], P[2 * u + 1][1]};
#pragma unroll
            for (int db = 0; db < 8; db++) {
                uint32_t r[4];
                LDM_X4_T(r, sV + (u * 16 + lrow) * AROW + db * 32 + lcol);
                MMA_F16(O[2 * db],     pa, r[0], r[1]);
                MMA_F16(O[2 * db + 1], pa, r[2], r[3]);
            }
        }
    }

    l0 += __shfl_xor_sync(0xffffffffu, l0, 1);
    l0 += __shfl_xor_sync(0xffffffffu, l0, 2);
    l1 += __shfl_xor_sync(0xffffffffu, l1, 1);
    l1 += __shfl_xor_sync(0xffffffffu, l1, 2);
    float inv0 = 1.f / l0;
    float inv1 = 1.f / l1;

#pragma unroll
    for (int nt = 0; nt < 16; nt++) {
        int colb = h * HDIM + nt * 8 + (lane & 3) * 2;
        float a0 = O[nt][0] * inv0, a1 = O[nt][1] * inv0;
        float b0 = O[nt][2] * inv1, b1 = O[nt][3] * inv1;
        __half h0 = __float2half_rn(a0), h1 = __float2half_rn(a1);
        __half h2 = __float2half_rn(b0), h3 = __float2half_rn(b1);
        *(half2*)(oh + (size_t)r0g * DMODEL + colb) = __halves2half2(h0, h1);
        *(half2*)(oh + (size_t)r1g * DMODEL + colb) = __halves2half2(h2, h3);
        *(half2*)(ol + (size_t)r0g * DMODEL + colb) = __floats2half2_rn(
            a0 - __half2float(h0), a1 - __half2float(h1));
        *(half2*)(ol + (size_t)r1g * DMODEL + colb) = __floats2half2_rn(
            b0 - __half2float(h2), b1 - __half2float(h3));
    }
}

// ---------------------------------------------------------------------------
// Launch
// ---------------------------------------------------------------------------
extern "C" void kernel_launch(void* const* d_in, const int* in_sizes, int n_in,
                              void* d_out, int out_size) {
    const float* x  = (const float*)d_in[0];
    const float* Wq = (const float*)d_in[1];
    const float* Wk = (const float*)d_in[2];
    const float* Wv = (const float*)d_in[3];
    const float* Wo = (const float*)d_in[4];
    float* out = (float*)d_out;

    __half *xh, *ah, *al, *qhp, *khp, *vhp;
    __half *wq, *wk, *wv, *wo;
    float2* ropetab;
    cudaGetSymbolAddress((void**)&xh, g_xh);
    cudaGetSymbolAddress((void**)&ah, g_ah);
    cudaGetSymbolAddress((void**)&al, g_al);
    cudaGetSymbolAddress((void**)&qhp, g_qh);
    cudaGetSymbolAddress((void**)&khp, g_kh);
    cudaGetSymbolAddress((void**)&vhp, g_vh);
    cudaGetSymbolAddress((void**)&wq, g_wq);
    cudaGetSymbolAddress((void**)&wk, g_wk);
    cudaGetSymbolAddress((void**)&wv, g_wv);
    cudaGetSymbolAddress((void**)&wo, g_wo);
    cudaGetSymbolAddress((void**)&ropetab, g_rope);

    cudaFuncSetAttribute(gemm_qkv,
                         cudaFuncAttributeMaxDynamicSharedMemorySize, GEMM_SMEM);
    cudaFuncSetAttribute(gemm_out,
                         cudaFuncAttributeMaxDynamicSharedMemorySize, GEMM_SMEM);
    cudaFuncSetAttribute(attn_mma,
                         cudaFuncAttributeMaxDynamicSharedMemorySize, ATTN_SMEM);

    const int nx8 = S_LEN * DMODEL / 8;
    const int nw8 = DMODEL * DMODEL / 8;
    rope_build<<<(S_LEN * 64 + 255) / 256, 256>>>(ropetab);
    cvt_f16<<<(nx8 + 255) / 256, 256>>>(x, xh, nx8);
    cvt_f16x4<<<dim3((nw8 + 255) / 256, 4), 256>>>(Wq, Wk, Wv, Wo,
                                                   wq, wk, wv, wo, nw8);

    dim3 gqkv(DMODEL / 128, S_LEN / 128, 3);
    gemm_qkv<<<gqkv, 256, GEMM_SMEM>>>(xh, wq, wk, wv, qhp, khp, vhp, ropetab);

    attn_mma<<<dim3(S_LEN / 64, NHEADS), 128, ATTN_SMEM>>>(qhp, khp, vhp, ah, al);

    dim3 go(DMODEL / 128, S_LEN / 128);
    gemm_out<<<go, 256, GEMM_SMEM>>>(ah, al, wo, out);
}

// round 9
// speedup vs baseline: 8.3962x; 1.1766x over previous
#include <cuda_runtime.h>
#include <cuda_fp16.h>
#include <math.h>
#include <stdint.h>

#define S_LEN  4096
#define DMODEL 2048
#define NHEADS 16
#define HDIM   128
#define WIN    512

// ---------------------------------------------------------------------------
// Scratch (__device__ globals: allocation-free rule)
// ---------------------------------------------------------------------------
__device__ __half g_xh[S_LEN * DMODEL];
__device__ __half g_ah[S_LEN * DMODEL];
__device__ __half g_qh[S_LEN * DMODEL];
__device__ __half g_kh[S_LEN * DMODEL];
__device__ __half g_vh[S_LEN * DMODEL];
__device__ __half g_wq[DMODEL * DMODEL];
__device__ __half g_wk[DMODEL * DMODEL];
__device__ __half g_wv[DMODEL * DMODEL];
__device__ __half g_wo[DMODEL * DMODEL];
__device__ float2 g_rope[S_LEN * 64];

// ---------------------------------------------------------------------------
// PTX primitives (baseline sm_80+)
// ---------------------------------------------------------------------------
__device__ __forceinline__ uint32_t smem_to_u32(const void* p) {
    uint32_t a;
    asm("{ .reg .u64 t; cvta.to.shared.u64 t, %1; cvt.u32.u64 %0, t; }"
        : "=r"(a) : "l"(p));
    return a;
}

#define CP_ASYNC16(dst, src) \
    asm volatile("cp.async.cg.shared.global [%0], [%1], 16;" \
        :: "r"(dst), "l"(src) : "memory")
#define CP_COMMIT() asm volatile("cp.async.commit_group;" ::: "memory")
#define CP_WAIT1()  asm volatile("cp.async.wait_group 1;" ::: "memory")
#define CP_WAIT0()  asm volatile("cp.async.wait_group 0;" ::: "memory")

#define LDM_X4(r, addr) \
    asm volatile("ldmatrix.sync.aligned.m8n8.x4.shared.b16 {%0,%1,%2,%3}, [%4];" \
        : "=r"((r)[0]), "=r"((r)[1]), "=r"((r)[2]), "=r"((r)[3]) : "r"(addr))

#define LDM_X4_T(r, addr) \
    asm volatile("ldmatrix.sync.aligned.m8n8.x4.trans.shared.b16 {%0,%1,%2,%3}, [%4];" \
        : "=r"((r)[0]), "=r"((r)[1]), "=r"((r)[2]), "=r"((r)[3]) : "r"(addr))

#define MMA_F16(c, a, b0, b1) \
    asm volatile("mma.sync.aligned.m16n8k16.row.col.f32.f16.f16.f32 " \
        "{%0,%1,%2,%3}, {%4,%5,%6,%7}, {%8,%9}, {%0,%1,%2,%3};" \
        : "+f"((c)[0]), "+f"((c)[1]), "+f"((c)[2]), "+f"((c)[3]) \
        : "r"((a)[0]), "r"((a)[1]), "r"((a)[2]), "r"((a)[3]), "r"(b0), "r"(b1))

// ---------------------------------------------------------------------------
// RoPE cos/sin table
// ---------------------------------------------------------------------------
__global__ __launch_bounds__(256) void rope_build(float2* __restrict__ tab) {
    int idx = blockIdx.x * blockDim.x + threadIdx.x;
    if (idx >= S_LEN * 64) return;
    int t = idx & 63;
    int s = idx >> 6;
    float ang = (float)s * exp2f(-(float)t * 0.20762050593045702f);
    float sn, cs;
    sincosf(ang, &sn, &cs);
    tab[idx] = make_float2(cs, sn);
}

// ---------------------------------------------------------------------------
// fp32 -> fp16 single, 8 elems/thread
// ---------------------------------------------------------------------------
__global__ __launch_bounds__(256) void cvt_f16(const float* __restrict__ src,
                                               __half* __restrict__ dst, int n8) {
    int i = blockIdx.x * blockDim.x + threadIdx.x;
    if (i >= n8) return;
    const float4* s4 = (const float4*)src + 2 * (size_t)i;
    float4 a = s4[0], b = s4[1];
    float v[8] = {a.x, a.y, a.z, a.w, b.x, b.y, b.z, b.w};
    __align__(16) __half h[8];
#pragma unroll
    for (int j = 0; j < 8; j++) h[j] = __float2half_rn(v[j]);
    ((uint4*)dst)[i] = *(const uint4*)h;
}

// Four weight matrices fp32 -> fp16 in one launch
__global__ __launch_bounds__(256) void cvt_f16x4(
    const float* __restrict__ s0, const float* __restrict__ s1,
    const float* __restrict__ s2, const float* __restrict__ s3,
    __half* __restrict__ d0, __half* __restrict__ d1,
    __half* __restrict__ d2, __half* __restrict__ d3, int n8) {
    int i = blockIdx.x * blockDim.x + threadIdx.x;
    if (i >= n8) return;
    const int w = blockIdx.y;
    const float* src = (w == 0) ? s0 : (w == 1) ? s1 : (w == 2) ? s2 : s3;
    __half* dst = (w == 0) ? d0 : (w == 1) ? d1 : (w == 2) ? d2 : d3;
    const float4* s4 = (const float4*)src + 2 * (size_t)i;
    float4 a = s4[0], b = s4[1];
    float v[8] = {a.x, a.y, a.z, a.w, b.x, b.y, b.z, b.w};
    __align__(16) __half h[8];
#pragma unroll
    for (int j = 0; j < 8; j++) h[j] = __float2half_rn(v[j]);
    ((uint4*)dst)[i] = *(const uint4*)h;
}

// ---------------------------------------------------------------------------
// Shared GEMM mainloop, single fp16 MMA per fragment (at the legacy-HMMA
// issue floor: time = MMA count x 16 cyc / SMSP).
// Requires in scope: smem, sbase, tid, lane, wm, wn, m0, n0, acc[4][4][4].
// ---------------------------------------------------------------------------
#define GK DMODEL
#define NI (GK / 32)
#define PAD_ROW_B 80                 // 32 fp16 (64B) + 16B pad
#define TILE_B (128 * PAD_ROW_B)     // 10240
#define STAGE_B (2 * TILE_B)         // A, B = 20480
#define GEMM_SMEM (3 * STAGE_B)      // 61440

#define GEMM_MAINLOOP(AP, BP)                                                  \
    const __half* gsrc[2] = {                                                  \
        (AP) + (size_t)m0 * GK, (BP) + (size_t)n0 * GK};                       \
    int l_tile[4], l_row[4], l_c16[4];                                         \
    _Pragma("unroll")                                                          \
    for (int t = 0; t < 4; t++) {                                              \
        int linear = t * 256 + tid;                                            \
        l_tile[t] = linear >> 9;                                               \
        int within = linear & 511;                                             \
        l_row[t] = within >> 2;                                                \
        l_c16[t] = within & 3;                                                 \
    }                                                                          \
    _Pragma("unroll")                                                          \
    for (int s = 0; s < 2; s++) {                                              \
        const uint32_t sb = sbase + s * STAGE_B;                               \
        const int k0 = s * 32;                                                 \
        _Pragma("unroll")                                                      \
        for (int t = 0; t < 4; t++) {                                          \
            const __half* src =                                                \
                gsrc[l_tile[t]] + (size_t)l_row[t] * GK + k0 + l_c16[t] * 8;   \
            uint32_t dst = sb + l_tile[t] * TILE_B +                           \
                           l_row[t] * PAD_ROW_B + l_c16[t] * 16;               \
            CP_ASYNC16(dst, src);                                              \
        }                                                                      \
        CP_COMMIT();                                                           \
    }                                                                          \
    _Pragma("unroll")                                                          \
    for (int i = 0; i < 4; i++)                                                \
        _Pragma("unroll")                                                      \
        for (int j = 0; j < 4; j++)                                            \
            _Pragma("unroll")                                                  \
            for (int r = 0; r < 4; r++) acc[i][j][r] = 0.f;                    \
    const int lrow = lane & 15;                                                \
    const int lcol = (lane >> 4) * 16;                                         \
    for (int i = 0; i < NI; i++) {                                             \
        if (i < NI - 1) { CP_WAIT1(); } else { CP_WAIT0(); }                   \
        __syncthreads();                                                       \
        if (i + 2 < NI) {                                                      \
            const int k0n = (i + 2) * 32;                                      \
            const uint32_t sb = sbase + ((i + 2) % 3) * STAGE_B;               \
            _Pragma("unroll")                                                  \
            for (int t = 0; t < 4; t++) {                                      \
                const __half* src = gsrc[l_tile[t]] +                          \
                    (size_t)l_row[t] * GK + k0n + l_c16[t] * 8;                \
                uint32_t dst = sb + l_tile[t] * TILE_B +                       \
                               l_row[t] * PAD_ROW_B + l_c16[t] * 16;           \
                CP_ASYNC16(dst, src);                                          \
            }                                                                  \
            CP_COMMIT();                                                       \
        }                                                                      \
        const uint32_t sA = sbase + (i % 3) * STAGE_B;                         \
        _Pragma("unroll")                                                      \
        for (int ks = 0; ks < 2; ks++) {                                       \
            const uint32_t kb = ks * 32;                                       \
            uint32_t b[4][2];                                                  \
            _Pragma("unroll")                                                  \
            for (int j = 0; j < 2; j++) {                                      \
                uint32_t bd = sA + TILE_B +                                    \
                    (wn * 32 + j * 16 + lrow) * PAD_ROW_B + kb + lcol;         \
                uint32_t r[4];                                                 \
                LDM_X4(r, bd);                                                 \
                b[2 * j][0] = r[0]; b[2 * j + 1][0] = r[1];                    \
                b[2 * j][1] = r[2]; b[2 * j + 1][1] = r[3];                    \
            }                                                                  \
            _Pragma("unroll")                                                  \
            for (int mt = 0; mt < 4; mt++) {                                   \
                uint32_t ah[4];                                                \
                uint32_t ad = sA + (wm * 64 + mt * 16 + lrow) * PAD_ROW_B +    \
                              kb + lcol;                                       \
                LDM_X4(ah, ad);                                                \
                _Pragma("unroll")                                              \
                for (int nt = 0; nt < 4; nt++) {                               \
                    MMA_F16(acc[mt][nt], ah, b[nt][0], b[nt][1]);              \
                }                                                              \
            }                                                                  \
        }                                                                      \
    }

// ---------------------------------------------------------------------------
// QKV GEMM, single fp16 MMA; fused RoPE epilogue. blockIdx.z: 0=Q, 1=K, 2=V.
// ---------------------------------------------------------------------------
__global__ __launch_bounds__(256, 2) void gemm_qkv(
    const __half* __restrict__ Ah,
    const __half* __restrict__ B0, const __half* __restrict__ B1,
    const __half* __restrict__ B2,
    __half* __restrict__ qh, __half* __restrict__ kh, __half* __restrict__ vh,
    const float2* __restrict__ rope) {
    extern __shared__ char smem[];
    const uint32_t sbase = smem_to_u32(smem);
    const int tid  = threadIdx.x;
    const int wid  = tid >> 5;
    const int lane = tid & 31;
    const int wm   = wid & 1;
    const int wn   = wid >> 1;
    const int m0   = blockIdx.y * 128;
    const int n0   = blockIdx.x * 128;
    const int z    = blockIdx.z;
    const __half* B = (z == 0) ? B0 : (z == 1) ? B1 : B2;

    float acc[4][4][4];
    GEMM_MAINLOOP(Ah, B)

    __half* outp = (z == 0) ? qh : (z == 1) ? kh : vh;
#pragma unroll
    for (int mt = 0; mt < 4; mt++) {
        const int r = m0 + wm * 64 + mt * 16 + (lane >> 2);
#pragma unroll
        for (int nt = 0; nt < 4; nt++) {
            const int c = n0 + wn * 32 + nt * 8 + (lane & 3) * 2;
            const size_t o0 = (size_t)r * DMODEL + c;
            const size_t o1 = (size_t)(r + 8) * DMODEL + c;
            if (z == 2) {
                *(half2*)(outp + o0) = __floats2half2_rn(acc[mt][nt][0], acc[mt][nt][1]);
                *(half2*)(outp + o1) = __floats2half2_rn(acc[mt][nt][2], acc[mt][nt][3]);
            } else {
                const int t = (c & 127) >> 1;
                float2 cs0 = rope[r * 64 + t];
                float2 cs1 = rope[(r + 8) * 64 + t];
                float a1 = acc[mt][nt][0] * cs0.x - acc[mt][nt][1] * cs0.y;
                float a2 = acc[mt][nt][0] * cs0.y + acc[mt][nt][1] * cs0.x;
                float b1 = acc[mt][nt][2] * cs1.x - acc[mt][nt][3] * cs1.y;
                float b2 = acc[mt][nt][2] * cs1.y + acc[mt][nt][3] * cs1.x;
                *(half2*)(outp + o0) = __floats2half2_rn(a1, a2);
                *(half2*)(outp + o1) = __floats2half2_rn(b1, b2);
            }
        }
    }
}

// ---------------------------------------------------------------------------
// Output projection GEMM: single fp16 MMA, fp32 epilogue to d_out.
// ---------------------------------------------------------------------------
__global__ __launch_bounds__(256, 2) void gemm_out(
    const __half* __restrict__ Ah, const __half* __restrict__ Bw,
    float* __restrict__ C) {
    extern __shared__ char smem[];
    const uint32_t sbase = smem_to_u32(smem);
    const int tid  = threadIdx.x;
    const int wid  = tid >> 5;
    const int lane = tid & 31;
    const int wm   = wid & 1;
    const int wn   = wid >> 1;
    const int m0   = blockIdx.y * 128;
    const int n0   = blockIdx.x * 128;

    float acc[4][4][4];
    GEMM_MAINLOOP(Ah, Bw)

#pragma unroll
    for (int mt = 0; mt < 4; mt++) {
        const int r = m0 + wm * 64 + mt * 16 + (lane >> 2);
#pragma unroll
        for (int nt = 0; nt < 4; nt++) {
            const int c = n0 + wn * 32 + nt * 8 + (lane & 3) * 2;
            *(float2*)(C + (size_t)r * DMODEL + c) =
                make_float2(acc[mt][nt][0], acc[mt][nt][1]);
            *(float2*)(C + (size_t)(r + 8) * DMODEL + c) =
                make_float2(acc[mt][nt][2], acc[mt][nt][3]);
        }
    }
}

// ---------------------------------------------------------------------------
// HMMA flash attention. Single fp16 Q; epilogue writes single fp16.
// ---------------------------------------------------------------------------
#define AROW 272
#define QT_B (64 * AROW)
#define ATTN_SMEM (3 * QT_B)          // Q, K, V

__global__ __launch_bounds__(128) void attn_mma(const __half* __restrict__ qh,
                                                const __half* __restrict__ kh,
                                                const __half* __restrict__ vh,
                                                __half* __restrict__ oh) {
    extern __shared__ char smem[];
    const uint32_t sbase = smem_to_u32(smem);
    const uint32_t sQ = sbase;
    const uint32_t sK = sbase + QT_B;
    const uint32_t sV = sbase + 2 * QT_B;

    const int h    = blockIdx.y;
    const int q0   = blockIdx.x * 64;
    const int tid  = threadIdx.x;
    const int wid  = tid >> 5;
    const int lane = tid & 31;
    const int lrow = lane & 15;
    const int lcol = (lane >> 4) * 16;
    const float SCALE = 0.088388347648318447f;

    for (int ch = tid; ch < 64 * 16; ch += 128) {
        int row = ch >> 4, c8 = ch & 15;
        size_t g = (size_t)(q0 + row) * DMODEL + h * HDIM + c8 * 8;
        *(uint4*)(smem + (row * AROW + c8 * 16)) = *(const uint4*)(qh + g);
    }

    float O[16][4];
#pragma unroll
    for (int i = 0; i < 16; i++)
#pragma unroll
        for (int r = 0; r < 4; r++) O[i][r] = 0.f;
    float m0 = -1e30f, m1 = -1e30f, l0 = 0.f, l1 = 0.f;

    const int r0g = q0 + wid * 16 + (lane >> 2);
    const int r1g = r0g + 8;
    const int cbeg = max(0, q0 - (WIN - 1)) & ~63;

    for (int c = cbeg; c <= q0; c += 64) {
        __syncthreads();
        for (int ch = tid; ch < 64 * 16; ch += 128) {
            int row = ch >> 4, c8 = ch & 15;
            size_t g = (size_t)(c + row) * DMODEL + h * HDIM + c8 * 8;
            *(uint4*)(smem + QT_B + (row * AROW + c8 * 16))     = *(const uint4*)(kh + g);
            *(uint4*)(smem + 2 * QT_B + (row * AROW + c8 * 16)) = *(const uint4*)(vh + g);
        }
        __syncthreads();

        float S[8][4];
#pragma unroll
        for (int nt = 0; nt < 8; nt++)
#pragma unroll
            for (int r = 0; r < 4; r++) S[nt][r] = 0.f;

#pragma unroll
        for (int ks = 0; ks < 8; ks++) {
            uint32_t aQ[4];
            LDM_X4(aQ, sQ + (wid * 16 + lrow) * AROW + ks * 32 + lcol);
#pragma unroll
            for (int nb = 0; nb < 4; nb++) {
                uint32_t r[4];
                LDM_X4(r, sK + (nb * 16 + lrow) * AROW + ks * 32 + lcol);
                MMA_F16(S[2 * nb],     aQ, r[0], r[2]);
                MMA_F16(S[2 * nb + 1], aQ, r[1], r[3]);
            }
        }

        const bool need_mask = (c + 63 > q0) || (q0 + 63 - c >= WIN);
        if (need_mask) {
#pragma unroll
            for (int nt = 0; nt < 8; nt++) {
                int colb = c + nt * 8 + (lane & 3) * 2;
                if (colb > r0g     || r0g - colb >= WIN)     S[nt][0] = -1e30f;
                if (colb + 1 > r0g || r0g - colb - 1 >= WIN) S[nt][1] = -1e30f;
                if (colb > r1g     || r1g - colb >= WIN)     S[nt][2] = -1e30f;
                if (colb + 1 > r1g || r1g - colb - 1 >= WIN) S[nt][3] = -1e30f;
            }
        }

        float mx0 = -1e30f, mx1 = -1e30f;
#pragma unroll
        for (int nt = 0; nt < 8; nt++) {
            mx0 = fmaxf(mx0, fmaxf(S[nt][0], S[nt][1]));
            mx1 = fmaxf(mx1, fmaxf(S[nt][2], S[nt][3]));
        }
        mx0 = fmaxf(mx0, __shfl_xor_sync(0xffffffffu, mx0, 1));
        mx0 = fmaxf(mx0, __shfl_xor_sync(0xffffffffu, mx0, 2));
        mx1 = fmaxf(mx1, __shfl_xor_sync(0xffffffffu, mx1, 1));
        mx1 = fmaxf(mx1, __shfl_xor_sync(0xffffffffu, mx1, 2));

        float mn0 = fmaxf(m0, mx0 * SCALE);
        float mn1 = fmaxf(m1, mx1 * SCALE);
        float c0 = __expf(m0 - mn0);
        float c1 = __expf(m1 - mn1);
        l0 *= c0; l1 *= c1;
#pragma unroll
        for (int nt = 0; nt < 16; nt++) {
            O[nt][0] *= c0; O[nt][1] *= c0;
            O[nt][2] *= c1; O[nt][3] *= c1;
        }
        m0 = mn0; m1 = mn1;

        uint32_t P[8][2];
#pragma unroll
        for (int nt = 0; nt < 8; nt++) {
            float p0 = __expf(S[nt][0] * SCALE - m0);
            float p1 = __expf(S[nt][1] * SCALE - m0);
            float p2 = __expf(S[nt][2] * SCALE - m1);
            float p3 = __expf(S[nt][3] * SCALE - m1);
            l0 += p0 + p1; l1 += p2 + p3;
            __half2 h01 = __floats2half2_rn(p0, p1);
            __half2 h23 = __floats2half2_rn(p2, p3);
            P[nt][0] = *(uint32_t*)&h01;
            P[nt][1] = *(uint32_t*)&h23;
        }

#pragma unroll
        for (int u = 0; u < 4; u++) {
            uint32_t pa[4] = {P[2 * u][0], P[2 * u][1], P[2 * u + 1][0], P[2 * u + 1][1]};
#pragma unroll
            for (int db = 0; db < 8; db++) {
                uint32_t r[4];
                LDM_X4_T(r, sV + (u * 16 + lrow) * AROW + db * 32 + lcol);
                MMA_F16(O[2 * db],     pa, r[0], r[1]);
                MMA_F16(O[2 * db + 1], pa, r[2], r[3]);
            }
        }
    }

    l0 += __shfl_xor_sync(0xffffffffu, l0, 1);
    l0 += __shfl_xor_sync(0xffffffffu, l0, 2);
    l1 += __shfl_xor_sync(0xffffffffu, l1, 1);
    l1 += __shfl_xor_sync(0xffffffffu, l1, 2);
    float inv0 = 1.f / l0;
    float inv1 = 1.f / l1;

#pragma unroll
    for (int nt = 0; nt < 16; nt++) {
        int colb = h * HDIM + nt * 8 + (lane & 3) * 2;
        *(half2*)(oh + (size_t)r0g * DMODEL + colb) =
            __floats2half2_rn(O[nt][0] * inv0, O[nt][1] * inv0);
        *(half2*)(oh + (size_t)r1g * DMODEL + colb) =
            __floats2half2_rn(O[nt][2] * inv1, O[nt][3] * inv1);
    }
}

// ---------------------------------------------------------------------------
// Launch
// ---------------------------------------------------------------------------
extern "C" void kernel_launch(void* const* d_in, const int* in_sizes, int n_in,
                              void* d_out, int out_size) {
    const float* x  = (const float*)d_in[0];
    const float* Wq = (const float*)d_in[1];
    const float* Wk = (const float*)d_in[2];
    const float* Wv = (const float*)d_in[3];
    const float* Wo = (const float*)d_in[4];
    float* out = (float*)d_out;

    __half *xh, *ah, *qhp, *khp, *vhp;
    __half *wq, *wk, *wv, *wo;
    float2* ropetab;
    cudaGetSymbolAddress((void**)&xh, g_xh);
    cudaGetSymbolAddress((void**)&ah, g_ah);
    cudaGetSymbolAddress((void**)&qhp, g_qh);
    cudaGetSymbolAddress((void**)&khp, g_kh);
    cudaGetSymbolAddress((void**)&vhp, g_vh);
    cudaGetSymbolAddress((void**)&wq, g_wq);
    cudaGetSymbolAddress((void**)&wk, g_wk);
    cudaGetSymbolAddress((void**)&wv, g_wv);
    cudaGetSymbolAddress((void**)&wo, g_wo);
    cudaGetSymbolAddress((void**)&ropetab, g_rope);

    cudaFuncSetAttribute(gemm_qkv,
                         cudaFuncAttributeMaxDynamicSharedMemorySize, GEMM_SMEM);
    cudaFuncSetAttribute(gemm_out,
                         cudaFuncAttributeMaxDynamicSharedMemorySize, GEMM_SMEM);
    cudaFuncSetAttribute(attn_mma,
                         cudaFuncAttributeMaxDynamicSharedMemorySize, ATTN_SMEM);

    const int nx8 = S_LEN * DMODEL / 8;
    const int nw8 = DMODEL * DMODEL / 8;
    rope_build<<<(S_LEN * 64 + 255) / 256, 256>>>(ropetab);
    cvt_f16<<<(nx8 + 255) / 256, 256>>>(x, xh, nx8);
    cvt_f16x4<<<dim3((nw8 + 255) / 256, 4), 256>>>(Wq, Wk, Wv, Wo,
                                                   wq, wk, wv, wo, nw8);

    dim3 gqkv(DMODEL / 128, S_LEN / 128, 3);
    gemm_qkv<<<gqkv, 256, GEMM_SMEM>>>(xh, wq, wk, wv, qhp, khp, vhp, ropetab);

    attn_mma<<<dim3(S_LEN / 64, NHEADS), 128, ATTN_SMEM>>>(qhp, khp, vhp, ah);

    dim3 go(DMODEL / 128, S_LEN / 128);
    gemm_out<<<go, 256, GEMM_SMEM>>>(ah, wo, out);
}

// round 10
// speedup vs baseline: 8.4272x; 1.0037x over previous
#include <cuda_runtime.h>
#include <cuda_fp16.h>
#include <math.h>
#include <stdint.h>

#define S_LEN  4096
#define DMODEL 2048
#define NHEADS 16
#define HDIM   128
#define WIN    512

// ---------------------------------------------------------------------------
// Scratch (__device__ globals: allocation-free rule)
// ---------------------------------------------------------------------------
__device__ __half g_xh[S_LEN * DMODEL];
__device__ __half g_ah[S_LEN * DMODEL];
__device__ __half g_qh[S_LEN * DMODEL];
__device__ __half g_kh[S_LEN * DMODEL];
__device__ __half g_vh[S_LEN * DMODEL];
__device__ __half g_wq[DMODEL * DMODEL];
__device__ __half g_wk[DMODEL * DMODEL];
__device__ __half g_wv[DMODEL * DMODEL];
__device__ __half g_wo[DMODEL * DMODEL];
__device__ float2 g_rope[S_LEN * 64];

// ---------------------------------------------------------------------------
// PTX primitives (baseline sm_80+)
// ---------------------------------------------------------------------------
__device__ __forceinline__ uint32_t smem_to_u32(const void* p) {
    uint32_t a;
    asm("{ .reg .u64 t; cvta.to.shared.u64 t, %1; cvt.u32.u64 %0, t; }"
        : "=r"(a) : "l"(p));
    return a;
}

#define CP_ASYNC16(dst, src) \
    asm volatile("cp.async.cg.shared.global [%0], [%1], 16;" \
        :: "r"(dst), "l"(src) : "memory")
#define CP_COMMIT() asm volatile("cp.async.commit_group;" ::: "memory")
#define CP_WAIT1()  asm volatile("cp.async.wait_group 1;" ::: "memory")
#define CP_WAIT0()  asm volatile("cp.async.wait_group 0;" ::: "memory")

#define LDM_X4(r, addr) \
    asm volatile("ldmatrix.sync.aligned.m8n8.x4.shared.b16 {%0,%1,%2,%3}, [%4];" \
        : "=r"((r)[0]), "=r"((r)[1]), "=r"((r)[2]), "=r"((r)[3]) : "r"(addr))

#define LDM_X4_T(r, addr) \
    asm volatile("ldmatrix.sync.aligned.m8n8.x4.trans.shared.b16 {%0,%1,%2,%3}, [%4];" \
        : "=r"((r)[0]), "=r"((r)[1]), "=r"((r)[2]), "=r"((r)[3]) : "r"(addr))

#define MMA_F16(c, a, b0, b1) \
    asm volatile("mma.sync.aligned.m16n8k16.row.col.f32.f16.f16.f32 " \
        "{%0,%1,%2,%3}, {%4,%5,%6,%7}, {%8,%9}, {%0,%1,%2,%3};" \
        : "+f"((c)[0]), "+f"((c)[1]), "+f"((c)[2]), "+f"((c)[3]) \
        : "r"((a)[0]), "r"((a)[1]), "r"((a)[2]), "r"((a)[3]), "r"(b0), "r"(b1))

// ---------------------------------------------------------------------------
// RoPE cos/sin table
// ---------------------------------------------------------------------------
__global__ __launch_bounds__(256) void rope_build(float2* __restrict__ tab) {
    int idx = blockIdx.x * blockDim.x + threadIdx.x;
    if (idx >= S_LEN * 64) return;
    int t = idx & 63;
    int s = idx >> 6;
    float ang = (float)s * exp2f(-(float)t * 0.20762050593045702f);
    float sn, cs;
    sincosf(ang, &sn, &cs);
    tab[idx] = make_float2(cs, sn);
}

// ---------------------------------------------------------------------------
// fp32 -> fp16 single, 8 elems/thread
// ---------------------------------------------------------------------------
__global__ __launch_bounds__(256) void cvt_f16(const float* __restrict__ src,
                                               __half* __restrict__ dst, int n8) {
    int i = blockIdx.x * blockDim.x + threadIdx.x;
    if (i >= n8) return;
    const float4* s4 = (const float4*)src + 2 * (size_t)i;
    float4 a = s4[0], b = s4[1];
    float v[8] = {a.x, a.y, a.z, a.w, b.x, b.y, b.z, b.w};
    __align__(16) __half h[8];
#pragma unroll
    for (int j = 0; j < 8; j++) h[j] = __float2half_rn(v[j]);
    ((uint4*)dst)[i] = *(const uint4*)h;
}

// Four weight matrices fp32 -> fp16 in one launch
__global__ __launch_bounds__(256) void cvt_f16x4(
    const float* __restrict__ s0, const float* __restrict__ s1,
    const float* __restrict__ s2, const float* __restrict__ s3,
    __half* __restrict__ d0, __half* __restrict__ d1,
    __half* __restrict__ d2, __half* __restrict__ d3, int n8) {
    int i = blockIdx.x * blockDim.x + threadIdx.x;
    if (i >= n8) return;
    const int w = blockIdx.y;
    const float* src = (w == 0) ? s0 : (w == 1) ? s1 : (w == 2) ? s2 : s3;
    __half* dst = (w == 0) ? d0 : (w == 1) ? d1 : (w == 2) ? d2 : d3;
    const float4* s4 = (const float4*)src + 2 * (size_t)i;
    float4 a = s4[0], b = s4[1];
    float v[8] = {a.x, a.y, a.z, a.w, b.x, b.y, b.z, b.w};
    __align__(16) __half h[8];
#pragma unroll
    for (int j = 0; j < 8; j++) h[j] = __float2half_rn(v[j]);
    ((uint4*)dst)[i] = *(const uint4*)h;
}

// ---------------------------------------------------------------------------
// Shared GEMM mainloop, single fp16 MMA per fragment, with software-pipelined
// A-fragment loads (double buffer: each LDSM issued >= 4 MMAs before use).
// Requires in scope: smem, sbase, tid, lane, wm, wn, m0, n0, acc[4][4][4].
// ---------------------------------------------------------------------------
#define GK DMODEL
#define NI (GK / 32)
#define PAD_ROW_B 80                 // 32 fp16 (64B) + 16B pad
#define TILE_B (128 * PAD_ROW_B)     // 10240
#define STAGE_B (2 * TILE_B)         // A, B = 20480
#define GEMM_SMEM (3 * STAGE_B)      // 61440

#define MMA4(accr, a, b)                                                       \
    MMA_F16((accr)[0], a, (b)[0][0], (b)[0][1]);                               \
    MMA_F16((accr)[1], a, (b)[1][0], (b)[1][1]);                               \
    MMA_F16((accr)[2], a, (b)[2][0], (b)[2][1]);                               \
    MMA_F16((accr)[3], a, (b)[3][0], (b)[3][1]);

#define GEMM_MAINLOOP(AP, BP)                                                  \
    const __half* gsrc[2] = {                                                  \
        (AP) + (size_t)m0 * GK, (BP) + (size_t)n0 * GK};                       \
    int l_tile[4], l_row[4], l_c16[4];                                         \
    _Pragma("unroll")                                                          \
    for (int t = 0; t < 4; t++) {                                              \
        int linear = t * 256 + tid;                                            \
        l_tile[t] = linear >> 9;                                               \
        int within = linear & 511;                                             \
        l_row[t] = within >> 2;                                                \
        l_c16[t] = within & 3;                                                 \
    }                                                                          \
    _Pragma("unroll")                                                          \
    for (int s = 0; s < 2; s++) {                                              \
        const uint32_t sb = sbase + s * STAGE_B;                               \
        const int k0 = s * 32;                                                 \
        _Pragma("unroll")                                                      \
        for (int t = 0; t < 4; t++) {                                          \
            const __half* src =                                                \
                gsrc[l_tile[t]] + (size_t)l_row[t] * GK + k0 + l_c16[t] * 8;   \
            uint32_t dst = sb + l_tile[t] * TILE_B +                           \
                           l_row[t] * PAD_ROW_B + l_c16[t] * 16;               \
            CP_ASYNC16(dst, src);                                              \
        }                                                                      \
        CP_COMMIT();                                                           \
    }                                                                          \
    _Pragma("unroll")                                                          \
    for (int i = 0; i < 4; i++)                                                \
        _Pragma("unroll")                                                      \
        for (int j = 0; j < 4; j++)                                            \
            _Pragma("unroll")                                                  \
            for (int r = 0; r < 4; r++) acc[i][j][r] = 0.f;                    \
    const int lrow = lane & 15;                                                \
    const int lcol = (lane >> 4) * 16;                                         \
    for (int i = 0; i < NI; i++) {                                             \
        if (i < NI - 1) { CP_WAIT1(); } else { CP_WAIT0(); }                   \
        __syncthreads();                                                       \
        if (i + 2 < NI) {                                                      \
            const int k0n = (i + 2) * 32;                                      \
            const uint32_t sb = sbase + ((i + 2) % 3) * STAGE_B;               \
            _Pragma("unroll")                                                  \
            for (int t = 0; t < 4; t++) {                                      \
                const __half* src = gsrc[l_tile[t]] +                          \
                    (size_t)l_row[t] * GK + k0n + l_c16[t] * 8;                \
                uint32_t dst = sb + l_tile[t] * TILE_B +                       \
                               l_row[t] * PAD_ROW_B + l_c16[t] * 16;           \
                CP_ASYNC16(dst, src);                                          \
            }                                                                  \
            CP_COMMIT();                                                       \
        }                                                                      \
        const uint32_t sA = sbase + (i % 3) * STAGE_B;                         \
        _Pragma("unroll")                                                      \
        for (int ks = 0; ks < 2; ks++) {                                       \
            const uint32_t kb = ks * 32;                                       \
            uint32_t b[4][2];                                                  \
            _Pragma("unroll")                                                  \
            for (int j = 0; j < 2; j++) {                                      \
                uint32_t bd = sA + TILE_B +                                    \
                    (wn * 32 + j * 16 + lrow) * PAD_ROW_B + kb + lcol;         \
                uint32_t r[4];                                                 \
                LDM_X4(r, bd);                                                 \
                b[2 * j][0] = r[0]; b[2 * j + 1][0] = r[1];                    \
                b[2 * j][1] = r[2]; b[2 * j + 1][1] = r[3];                    \
            }                                                                  \
            const uint32_t adb = sA + (wm * 64 + lrow) * PAD_ROW_B + kb + lcol;\
            uint32_t aC[4], aN[4];                                             \
            LDM_X4(aC, adb);                                                   \
            LDM_X4(aN, adb + 16 * PAD_ROW_B);                                  \
            MMA4(acc[0], aC, b)                                                \
            LDM_X4(aC, adb + 32 * PAD_ROW_B);                                  \
            MMA4(acc[1], aN, b)                                                \
            LDM_X4(aN, adb + 48 * PAD_ROW_B);                                  \
            MMA4(acc[2], aC, b)                                                \
            MMA4(acc[3], aN, b)                                                \
        }                                                                      \
    }

// ---------------------------------------------------------------------------
// QKV GEMM, single fp16 MMA; fused RoPE epilogue. blockIdx.z: 0=Q, 1=K, 2=V.
// ---------------------------------------------------------------------------
__global__ __launch_bounds__(256, 2) void gemm_qkv(
    const __half* __restrict__ Ah,
    const __half* __restrict__ B0, const __half* __restrict__ B1,
    const __half* __restrict__ B2,
    __half* __restrict__ qh, __half* __restrict__ kh, __half* __restrict__ vh,
    const float2* __restrict__ rope) {
    extern __shared__ char smem[];
    const uint32_t sbase = smem_to_u32(smem);
    const int tid  = threadIdx.x;
    const int wid  = tid >> 5;
    const int lane = tid & 31;
    const int wm   = wid & 1;
    const int wn   = wid >> 1;
    const int m0   = blockIdx.y * 128;
    const int n0   = blockIdx.x * 128;
    const int z    = blockIdx.z;
    const __half* B = (z == 0) ? B0 : (z == 1) ? B1 : B2;

    float acc[4][4][4];
    GEMM_MAINLOOP(Ah, B)

    __half* outp = (z == 0) ? qh : (z == 1) ? kh : vh;
#pragma unroll
    for (int mt = 0; mt < 4; mt++) {
        const int r = m0 + wm * 64 + mt * 16 + (lane >> 2);
#pragma unroll
        for (int nt = 0; nt < 4; nt++) {
            const int c = n0 + wn * 32 + nt * 8 + (lane & 3) * 2;
            const size_t o0 = (size_t)r * DMODEL + c;
            const size_t o1 = (size_t)(r + 8) * DMODEL + c;
            if (z == 2) {
                *(half2*)(outp + o0) = __floats2half2_rn(acc[mt][nt][0], acc[mt][nt][1]);
                *(half2*)(outp + o1) = __floats2half2_rn(acc[mt][nt][2], acc[mt][nt][3]);
            } else {
                const int t = (c & 127) >> 1;
                float2 cs0 = rope[r * 64 + t];
                float2 cs1 = rope[(r + 8) * 64 + t];
                float a1 = acc[mt][nt][0] * cs0.x - acc[mt][nt][1] * cs0.y;
                float a2 = acc[mt][nt][0] * cs0.y + acc[mt][nt][1] * cs0.x;
                float b1 = acc[mt][nt][2] * cs1.x - acc[mt][nt][3] * cs1.y;
                float b2 = acc[mt][nt][2] * cs1.y + acc[mt][nt][3] * cs1.x;
                *(half2*)(outp + o0) = __floats2half2_rn(a1, a2);
                *(half2*)(outp + o1) = __floats2half2_rn(b1, b2);
            }
        }
    }
}

// ---------------------------------------------------------------------------
// Output projection GEMM: single fp16 MMA, fp32 epilogue to d_out.
// ---------------------------------------------------------------------------
__global__ __launch_bounds__(256, 2) void gemm_out(
    const __half* __restrict__ Ah, const __half* __restrict__ Bw,
    float* __restrict__ C) {
    extern __shared__ char smem[];
    const uint32_t sbase = smem_to_u32(smem);
    const int tid  = threadIdx.x;
    const int wid  = tid >> 5;
    const int lane = tid & 31;
    const int wm   = wid & 1;
    const int wn   = wid >> 1;
    const int m0   = blockIdx.y * 128;
    const int n0   = blockIdx.x * 128;

    float acc[4][4][4];
    GEMM_MAINLOOP(Ah, Bw)

#pragma unroll
    for (int mt = 0; mt < 4; mt++) {
        const int r = m0 + wm * 64 + mt * 16 + (lane >> 2);
#pragma unroll
        for (int nt = 0; nt < 4; nt++) {
            const int c = n0 + wn * 32 + nt * 8 + (lane & 3) * 2;
            *(float2*)(C + (size_t)r * DMODEL + c) =
                make_float2(acc[mt][nt][0], acc[mt][nt][1]);
            *(float2*)(C + (size_t)(r + 8) * DMODEL + c) =
                make_float2(acc[mt][nt][2], acc[mt][nt][3]);
        }
    }
}

// ---------------------------------------------------------------------------
// HMMA flash attention, K/V fragment loads software-pipelined.
// ---------------------------------------------------------------------------
#define AROW 272
#define QT_B (64 * AROW)
#define ATTN_SMEM (3 * QT_B)          // Q, K, V

#define MMA2S(s0r, s1r, a, kf)                                                 \
    MMA_F16(s0r, a, (kf)[0], (kf)[2]);                                         \
    MMA_F16(s1r, a, (kf)[1], (kf)[3]);

__global__ __launch_bounds__(128) void attn_mma(const __half* __restrict__ qh,
                                                const __half* __restrict__ kh,
                                                const __half* __restrict__ vh,
                                                __half* __restrict__ oh) {
    extern __shared__ char smem[];
    const uint32_t sbase = smem_to_u32(smem);
    const uint32_t sQ = sbase;
    const uint32_t sK = sbase + QT_B;
    const uint32_t sV = sbase + 2 * QT_B;

    const int h    = blockIdx.y;
    const int q0   = blockIdx.x * 64;
    const int tid  = threadIdx.x;
    const int wid  = tid >> 5;
    const int lane = tid & 31;
    const int lrow = lane & 15;
    const int lcol = (lane >> 4) * 16;
    const float SCALE = 0.088388347648318447f;

    for (int ch = tid; ch < 64 * 16; ch += 128) {
        int row = ch >> 4, c8 = ch & 15;
        size_t g = (size_t)(q0 + row) * DMODEL + h * HDIM + c8 * 8;
        *(uint4*)(smem + (row * AROW + c8 * 16)) = *(const uint4*)(qh + g);
    }

    float O[16][4];
#pragma unroll
    for (int i = 0; i < 16; i++)
#pragma unroll
        for (int r = 0; r < 4; r++) O[i][r] = 0.f;
    float m0 = -1e30f, m1 = -1e30f, l0 = 0.f, l1 = 0.f;

    const int r0g = q0 + wid * 16 + (lane >> 2);
    const int r1g = r0g + 8;
    const int cbeg = max(0, q0 - (WIN - 1)) & ~63;

    for (int c = cbeg; c <= q0; c += 64) {
        __syncthreads();
        for (int ch = tid; ch < 64 * 16; ch += 128) {
            int row = ch >> 4, c8 = ch & 15;
            size_t g = (size_t)(c + row) * DMODEL + h * HDIM + c8 * 8;
            *(uint4*)(smem + QT_B + (row * AROW + c8 * 16))     = *(const uint4*)(kh + g);
            *(uint4*)(smem + 2 * QT_B + (row * AROW + c8 * 16)) = *(const uint4*)(vh + g);
        }
        __syncthreads();

        float S[8][4];
#pragma unroll
        for (int nt = 0; nt < 8; nt++)
#pragma unroll
            for (int r = 0; r < 4; r++) S[nt][r] = 0.f;

#pragma unroll
        for (int ks = 0; ks < 8; ks++) {
            const uint32_t kboff = ks * 32 + lcol;
            uint32_t aQ[4], kC[4], kN[4];
            LDM_X4(aQ, sQ + (wid * 16 + lrow) * AROW + kboff);
            LDM_X4(kC, sK + (lrow) * AROW + kboff);
            LDM_X4(kN, sK + (16 + lrow) * AROW + kboff);
            MMA2S(S[0], S[1], aQ, kC)
            LDM_X4(kC, sK + (32 + lrow) * AROW + kboff);
            MMA2S(S[2], S[3], aQ, kN)
            LDM_X4(kN, sK + (48 + lrow) * AROW + kboff);
            MMA2S(S[4], S[5], aQ, kC)
            MMA2S(S[6], S[7], aQ, kN)
        }

        const bool need_mask = (c + 63 > q0) || (q0 + 63 - c >= WIN);
        if (need_mask) {
#pragma unroll
            for (int nt = 0; nt < 8; nt++) {
                int colb = c + nt * 8 + (lane & 3) * 2;
                if (colb > r0g     || r0g - colb >= WIN)     S[nt][0] = -1e30f;
                if (colb + 1 > r0g || r0g - colb - 1 >= WIN) S[nt][1] = -1e30f;
                if (colb > r1g     || r1g - colb >= WIN)     S[nt][2] = -1e30f;
                if (colb + 1 > r1g || r1g - colb - 1 >= WIN) S[nt][3] = -1e30f;
            }
        }

        float mx0 = -1e30f, mx1 = -1e30f;
#pragma unroll
        for (int nt = 0; nt < 8; nt++) {
            mx0 = fmaxf(mx0, fmaxf(S[nt][0], S[nt][1]));
            mx1 = fmaxf(mx1, fmaxf(S[nt][2], S[nt][3]));
        }
        mx0 = fmaxf(mx0, __shfl_xor_sync(0xffffffffu, mx0, 1));
        mx0 = fmaxf(mx0, __shfl_xor_sync(0xffffffffu, mx0, 2));
        mx1 = fmaxf(mx1, __shfl_xor_sync(0xffffffffu, mx1, 1));
        mx1 = fmaxf(mx1, __shfl_xor_sync(0xffffffffu, mx1, 2));

        float mn0 = fmaxf(m0, mx0 * SCALE);
        float mn1 = fmaxf(m1, mx1 * SCALE);
        float c0 = __expf(m0 - mn0);
        float c1 = __expf(m1 - mn1);
        l0 *= c0; l1 *= c1;
#pragma unroll
        for (int nt = 0; nt < 16; nt++) {
            O[nt][0] *= c0; O[nt][1] *= c0;
            O[nt][2] *= c1; O[nt][3] *= c1;
        }
        m0 = mn0; m1 = mn1;

        uint32_t P[8][2];
#pragma unroll
        for (int nt = 0; nt < 8; nt++) {
            float p0 = __expf(S[nt][0] * SCALE - m0);
            float p1 = __expf(S[nt][1] * SCALE - m0);
            float p2 = __expf(S[nt][2] * SCALE - m1);
            float p3 = __expf(S[nt][3] * SCALE - m1);
            l0 += p0 + p1; l1 += p2 + p3;
            __half2 h01 = __floats2half2_rn(p0, p1);
            __half2 h23 = __floats2half2_rn(p2, p3);
            P[nt][0] = *(uint32_t*)&h01;
            P[nt][1] = *(uint32_t*)&h23;
        }

#pragma unroll
        for (int u = 0; u < 4; u++) {
            uint32_t pa[4] = {P[2 * u][0], P[2 * u][1], P[2 * u + 1][0], P[2 * u + 1][1]};
            const uint32_t vb = sV + (u * 16 + lrow) * AROW + lcol;
            uint32_t vC[4], vN[4];
            LDM_X4_T(vC, vb);
            LDM_X4_T(vN, vb + 32);
            MMA_F16(O[0], pa, vC[0], vC[1]);
            MMA_F16(O[1], pa, vC[2], vC[3]);
            LDM_X4_T(vC, vb + 64);
            MMA_F16(O[2], pa, vN[0], vN[1]);
            MMA_F16(O[3], pa, vN[2], vN[3]);
            LDM_X4_T(vN, vb + 96);
            MMA_F16(O[4], pa, vC[0], vC[1]);
            MMA_F16(O[5], pa, vC[2], vC[3]);
            LDM_X4_T(vC, vb + 128);
            MMA_F16(O[6], pa, vN[0], vN[1]);
            MMA_F16(O[7], pa, vN[2], vN[3]);
            LDM_X4_T(vN, vb + 160);
            MMA_F16(O[8], pa, vC[0], vC[1]);
            MMA_F16(O[9], pa, vC[2], vC[3]);
            LDM_X4_T(vC, vb + 192);
            MMA_F16(O[10], pa, vN[0], vN[1]);
            MMA_F16(O[11], pa, vN[2], vN[3]);
            LDM_X4_T(vN, vb + 224);
            MMA_F16(O[12], pa, vC[0], vC[1]);
            MMA_F16(O[13], pa, vC[2], vC[3]);
            MMA_F16(O[14], pa, vN[0], vN[1]);
            MMA_F16(O[15], pa, vN[2], vN[3]);
        }
    }

    l0 += __shfl_xor_sync(0xffffffffu, l0, 1);
    l0 += __shfl_xor_sync(0xffffffffu, l0, 2);
    l1 += __shfl_xor_sync(0xffffffffu, l1, 1);
    l1 += __shfl_xor_sync(0xffffffffu, l1, 2);
    float inv0 = 1.f / l0;
    float inv1 = 1.f / l1;

#pragma unroll
    for (int nt = 0; nt < 16; nt++) {
        int colb = h * HDIM + nt * 8 + (lane & 3) * 2;
        *(half2*)(oh + (size_t)r0g * DMODEL + colb) =
            __floats2half2_rn(O[nt][0] * inv0, O[nt][1] * inv0);
        *(half2*)(oh + (size_t)r1g * DMODEL + colb) =
            __floats2half2_rn(O[nt][2] * inv1, O[nt][3] * inv1);
    }
}

// ---------------------------------------------------------------------------
// Launch
// ---------------------------------------------------------------------------
extern "C" void kernel_launch(void* const* d_in, const int* in_sizes, int n_in,
                              void* d_out, int out_size) {
    const float* x  = (const float*)d_in[0];
    const float* Wq = (const float*)d_in[1];
    const float* Wk = (const float*)d_in[2];
    const float* Wv = (const float*)d_in[3];
    const float* Wo = (const float*)d_in[4];
    float* out = (float*)d_out;

    __half *xh, *ah, *qhp, *khp, *vhp;
    __half *wq, *wk, *wv, *wo;
    float2* ropetab;
    cudaGetSymbolAddress((void**)&xh, g_xh);
    cudaGetSymbolAddress((void**)&ah, g_ah);
    cudaGetSymbolAddress((void**)&qhp, g_qh);
    cudaGetSymbolAddress((void**)&khp, g_kh);
    cudaGetSymbolAddress((void**)&vhp, g_vh);
    cudaGetSymbolAddress((void**)&wq, g_wq);
    cudaGetSymbolAddress((void**)&wk, g_wk);
    cudaGetSymbolAddress((void**)&wv, g_wv);
    cudaGetSymbolAddress((void**)&wo, g_wo);
    cudaGetSymbolAddress((void**)&ropetab, g_rope);

    cudaFuncSetAttribute(gemm_qkv,
                         cudaFuncAttributeMaxDynamicSharedMemorySize, GEMM_SMEM);
    cudaFuncSetAttribute(gemm_out,
                         cudaFuncAttributeMaxDynamicSharedMemorySize, GEMM_SMEM);
    cudaFuncSetAttribute(attn_mma,
                         cudaFuncAttributeMaxDynamicSharedMemorySize, ATTN_SMEM);

    const int nx8 = S_LEN * DMODEL / 8;
    const int nw8 = DMODEL * DMODEL / 8;
    rope_build<<<(S_LEN * 64 + 255) / 256, 256>>>(ropetab);
    cvt_f16<<<(nx8 + 255) / 256, 256>>>(x, xh, nx8);
    cvt_f16x4<<<dim3((nw8 + 255) / 256, 4), 256>>>(Wq, Wk, Wv, Wo,
                                                   wq, wk, wv, wo, nw8);

    dim3 gqkv(DMODEL / 128, S_LEN / 128, 3);
    gemm_qkv<<<gqkv, 256, GEMM_SMEM>>>(xh, wq, wk, wv, qhp, khp, vhp, ropetab);

    attn_mma<<<dim3(S_LEN / 64, NHEADS), 128, ATTN_SMEM>>>(qhp, khp, vhp, ah);

    dim3 go(DMODEL / 128, S_LEN / 128);
    gemm_out<<<go, 256, GEMM_SMEM>>>(ah, wo, out);
}

// round 11
// speedup vs baseline: 9.1670x; 1.0878x over previous
#include <cuda_runtime.h>
#include <cuda_fp16.h>
#include <math.h>
#include <stdint.h>

#define S_LEN  4096
#define DMODEL 2048
#define NHEADS 16
#define HDIM   128
#define WIN    512

// ---------------------------------------------------------------------------
// Scratch (__device__ globals: allocation-free rule)
// ---------------------------------------------------------------------------
__device__ __half g_xh[S_LEN * DMODEL];
__device__ __half g_ah[S_LEN * DMODEL];
__device__ __half g_qh[S_LEN * DMODEL];
__device__ __half g_kh[S_LEN * DMODEL];
__device__ __half g_vh[S_LEN * DMODEL];
__device__ __half g_wq[DMODEL * DMODEL];
__device__ __half g_wk[DMODEL * DMODEL];
__device__ __half g_wv[DMODEL * DMODEL];
__device__ __half g_wo[DMODEL * DMODEL];
__device__ float2 g_rope[S_LEN * 64];

// ---------------------------------------------------------------------------
// PTX primitives (baseline sm_80+)
// ---------------------------------------------------------------------------
__device__ __forceinline__ uint32_t smem_to_u32(const void* p) {
    uint32_t a;
    asm("{ .reg .u64 t; cvta.to.shared.u64 t, %1; cvt.u32.u64 %0, t; }"
        : "=r"(a) : "l"(p));
    return a;
}

#define CP_ASYNC16(dst, src) \
    asm volatile("cp.async.cg.shared.global [%0], [%1], 16;" \
        :: "r"(dst), "l"(src) : "memory")
#define CP_COMMIT() asm volatile("cp.async.commit_group;" ::: "memory")
#define CP_WAIT1()  asm volatile("cp.async.wait_group 1;" ::: "memory")
#define CP_WAIT0()  asm volatile("cp.async.wait_group 0;" ::: "memory")

#define LDM_X4(r, addr) \
    asm volatile("ldmatrix.sync.aligned.m8n8.x4.shared.b16 {%0,%1,%2,%3}, [%4];" \
        : "=r"((r)[0]), "=r"((r)[1]), "=r"((r)[2]), "=r"((r)[3]) : "r"(addr))

#define LDM_X4_T(r, addr) \
    asm volatile("ldmatrix.sync.aligned.m8n8.x4.trans.shared.b16 {%0,%1,%2,%3}, [%4];" \
        : "=r"((r)[0]), "=r"((r)[1]), "=r"((r)[2]), "=r"((r)[3]) : "r"(addr))

#define MMA_F16(c, a, b0, b1) \
    asm volatile("mma.sync.aligned.m16n8k16.row.col.f32.f16.f16.f32 " \
        "{%0,%1,%2,%3}, {%4,%5,%6,%7}, {%8,%9}, {%0,%1,%2,%3};" \
        : "+f"((c)[0]), "+f"((c)[1]), "+f"((c)[2]), "+f"((c)[3]) \
        : "r"((a)[0]), "r"((a)[1]), "r"((a)[2]), "r"((a)[3]), "r"(b0), "r"(b1))

// ---------------------------------------------------------------------------
// RoPE cos/sin table
// ---------------------------------------------------------------------------
__global__ __launch_bounds__(256) void rope_build(float2* __restrict__ tab) {
    int idx = blockIdx.x * blockDim.x + threadIdx.x;
    if (idx >= S_LEN * 64) return;
    int t = idx & 63;
    int s = idx >> 6;
    float ang = (float)s * exp2f(-(float)t * 0.20762050593045702f);
    float sn, cs;
    sincosf(ang, &sn, &cs);
    tab[idx] = make_float2(cs, sn);
}

// ---------------------------------------------------------------------------
// fp32 -> fp16 single, 8 elems/thread
// ---------------------------------------------------------------------------
__global__ __launch_bounds__(256) void cvt_f16(const float* __restrict__ src,
                                               __half* __restrict__ dst, int n8) {
    int i = blockIdx.x * blockDim.x + threadIdx.x;
    if (i >= n8) return;
    const float4* s4 = (const float4*)src + 2 * (size_t)i;
    float4 a = s4[0], b = s4[1];
    float v[8] = {a.x, a.y, a.z, a.w, b.x, b.y, b.z, b.w};
    __align__(16) __half h[8];
#pragma unroll
    for (int j = 0; j < 8; j++) h[j] = __float2half_rn(v[j]);
    ((uint4*)dst)[i] = *(const uint4*)h;
}

// Four weight matrices fp32 -> fp16 in one launch
__global__ __launch_bounds__(256) void cvt_f16x4(
    const float* __restrict__ s0, const float* __restrict__ s1,
    const float* __restrict__ s2, const float* __restrict__ s3,
    __half* __restrict__ d0, __half* __restrict__ d1,
    __half* __restrict__ d2, __half* __restrict__ d3, int n8) {
    int i = blockIdx.x * blockDim.x + threadIdx.x;
    if (i >= n8) return;
    const int w = blockIdx.y;
    const float* src = (w == 0) ? s0 : (w == 1) ? s1 : (w == 2) ? s2 : s3;
    __half* dst = (w == 0) ? d0 : (w == 1) ? d1 : (w == 2) ? d2 : d3;
    const float4* s4 = (const float4*)src + 2 * (size_t)i;
    float4 a = s4[0], b = s4[1];
    float v[8] = {a.x, a.y, a.z, a.w, b.x, b.y, b.z, b.w};
    __align__(16) __half h[8];
#pragma unroll
    for (int j = 0; j < 8; j++) h[j] = __float2half_rn(v[j]);
    ((uint4*)dst)[i] = *(const uint4*)h;
}

// ---------------------------------------------------------------------------
// Shared GEMM mainloop: 512 threads, 16 warps, warp-tile 32x32 (4x4 warp
// grid over the 128x128 CTA tile). 8 warps/SMSP at 2 CTAs/SM breaks the
// post-sync crossbar/tensor convoy.
// Requires in scope: smem, sbase, tid, lane, wm, wn, m0, n0, acc[2][4][4].
// ---------------------------------------------------------------------------
#define GK DMODEL
#define NI (GK / 32)
#define PAD_ROW_B 80                 // 32 fp16 (64B) + 16B pad
#define TILE_B (128 * PAD_ROW_B)     // 10240
#define STAGE_B (2 * TILE_B)         // A, B = 20480
#define GEMM_SMEM (3 * STAGE_B)      // 61440

#define GEMM_MAINLOOP(AP, BP)                                                  \
    const __half* gsrc[2] = {                                                  \
        (AP) + (size_t)m0 * GK, (BP) + (size_t)n0 * GK};                       \
    int l_tile[2], l_row[2], l_c16[2];                                         \
    _Pragma("unroll")                                                          \
    for (int t = 0; t < 2; t++) {                                              \
        int linear = t * 512 + tid;                                            \
        l_tile[t] = linear >> 9;                                               \
        int within = linear & 511;                                             \
        l_row[t] = within >> 2;                                                \
        l_c16[t] = within & 3;                                                 \
    }                                                                          \
    _Pragma("unroll")                                                          \
    for (int s = 0; s < 2; s++) {                                              \
        const uint32_t sb = sbase + s * STAGE_B;                               \
        const int k0 = s * 32;                                                 \
        _Pragma("unroll")                                                      \
        for (int t = 0; t < 2; t++) {                                          \
            const __half* src =                                                \
                gsrc[l_tile[t]] + (size_t)l_row[t] * GK + k0 + l_c16[t] * 8;   \
            uint32_t dst = sb + l_tile[t] * TILE_B +                           \
                           l_row[t] * PAD_ROW_B + l_c16[t] * 16;               \
            CP_ASYNC16(dst, src);                                              \
        }                                                                      \
        CP_COMMIT();                                                           \
    }                                                                          \
    _Pragma("unroll")                                                          \
    for (int i = 0; i < 2; i++)                                                \
        _Pragma("unroll")                                                      \
        for (int j = 0; j < 4; j++)                                            \
            _Pragma("unroll")                                                  \
            for (int r = 0; r < 4; r++) acc[i][j][r] = 0.f;                    \
    const int lrow = lane & 15;                                                \
    const int lcol = (lane >> 4) * 16;                                         \
    for (int i = 0; i < NI; i++) {                                             \
        if (i < NI - 1) { CP_WAIT1(); } else { CP_WAIT0(); }                   \
        __syncthreads();                                                       \
        if (i + 2 < NI) {                                                      \
            const int k0n = (i + 2) * 32;                                      \
            const uint32_t sb = sbase + ((i + 2) % 3) * STAGE_B;               \
            _Pragma("unroll")                                                  \
            for (int t = 0; t < 2; t++) {                                      \
                const __half* src = gsrc[l_tile[t]] +                          \
                    (size_t)l_row[t] * GK + k0n + l_c16[t] * 8;                \
                uint32_t dst = sb + l_tile[t] * TILE_B +                       \
                               l_row[t] * PAD_ROW_B + l_c16[t] * 16;           \
                CP_ASYNC16(dst, src);                                          \
            }                                                                  \
            CP_COMMIT();                                                       \
        }                                                                      \
        const uint32_t sA = sbase + (i % 3) * STAGE_B;                         \
        _Pragma("unroll")                                                      \
        for (int ks = 0; ks < 2; ks++) {                                       \
            const uint32_t kb = ks * 32 + lcol;                                \
            uint32_t b[4][2];                                                  \
            _Pragma("unroll")                                                  \
            for (int j = 0; j < 2; j++) {                                      \
                uint32_t bd = sA + TILE_B +                                    \
                    (wn * 32 + j * 16 + lrow) * PAD_ROW_B + kb;                \
                uint32_t r[4];                                                 \
                LDM_X4(r, bd);                                                 \
                b[2 * j][0] = r[0]; b[2 * j + 1][0] = r[1];                    \
                b[2 * j][1] = r[2]; b[2 * j + 1][1] = r[3];                    \
            }                                                                  \
            _Pragma("unroll")                                                  \
            for (int mt = 0; mt < 2; mt++) {                                   \
                uint32_t ah[4];                                                \
                uint32_t ad = sA + (wm * 32 + mt * 16 + lrow) * PAD_ROW_B + kb;\
                LDM_X4(ah, ad);                                                \
                _Pragma("unroll")                                              \
                for (int nt = 0; nt < 4; nt++) {                               \
                    MMA_F16(acc[mt][nt], ah, b[nt][0], b[nt][1]);              \
                }                                                              \
            }                                                                  \
        }                                                                      \
    }

// ---------------------------------------------------------------------------
// QKV GEMM, single fp16 MMA; fused RoPE epilogue. blockIdx.z: 0=Q, 1=K, 2=V.
// ---------------------------------------------------------------------------
__global__ __launch_bounds__(512, 2) void gemm_qkv(
    const __half* __restrict__ Ah,
    const __half* __restrict__ B0, const __half* __restrict__ B1,
    const __half* __restrict__ B2,
    __half* __restrict__ qh, __half* __restrict__ kh, __half* __restrict__ vh,
    const float2* __restrict__ rope) {
    extern __shared__ char smem[];
    const uint32_t sbase = smem_to_u32(smem);
    const int tid  = threadIdx.x;
    const int wid  = tid >> 5;
    const int lane = tid & 31;
    const int wm   = wid & 3;
    const int wn   = wid >> 2;
    const int m0   = blockIdx.y * 128;
    const int n0   = blockIdx.x * 128;
    const int z    = blockIdx.z;
    const __half* B = (z == 0) ? B0 : (z == 1) ? B1 : B2;

    float acc[2][4][4];
    GEMM_MAINLOOP(Ah, B)

    __half* outp = (z == 0) ? qh : (z == 1) ? kh : vh;
#pragma unroll
    for (int mt = 0; mt < 2; mt++) {
        const int r = m0 + wm * 32 + mt * 16 + (lane >> 2);
#pragma unroll
        for (int nt = 0; nt < 4; nt++) {
            const int c = n0 + wn * 32 + nt * 8 + (lane & 3) * 2;
            const size_t o0 = (size_t)r * DMODEL + c;
            const size_t o1 = (size_t)(r + 8) * DMODEL + c;
            if (z == 2) {
                *(half2*)(outp + o0) = __floats2half2_rn(acc[mt][nt][0], acc[mt][nt][1]);
                *(half2*)(outp + o1) = __floats2half2_rn(acc[mt][nt][2], acc[mt][nt][3]);
            } else {
                const int t = (c & 127) >> 1;
                float2 cs0 = rope[r * 64 + t];
                float2 cs1 = rope[(r + 8) * 64 + t];
                float a1 = acc[mt][nt][0] * cs0.x - acc[mt][nt][1] * cs0.y;
                float a2 = acc[mt][nt][0] * cs0.y + acc[mt][nt][1] * cs0.x;
                float b1 = acc[mt][nt][2] * cs1.x - acc[mt][nt][3] * cs1.y;
                float b2 = acc[mt][nt][2] * cs1.y + acc[mt][nt][3] * cs1.x;
                *(half2*)(outp + o0) = __floats2half2_rn(a1, a2);
                *(half2*)(outp + o1) = __floats2half2_rn(b1, b2);
            }
        }
    }
}

// ---------------------------------------------------------------------------
// Output projection GEMM: single fp16 MMA, fp32 epilogue to d_out.
// ---------------------------------------------------------------------------
__global__ __launch_bounds__(512, 2) void gemm_out(
    const __half* __restrict__ Ah, const __half* __restrict__ Bw,
    float* __restrict__ C) {
    extern __shared__ char smem[];
    const uint32_t sbase = smem_to_u32(smem);
    const int tid  = threadIdx.x;
    const int wid  = tid >> 5;
    const int lane = tid & 31;
    const int wm   = wid & 3;
    const int wn   = wid >> 2;
    const int m0   = blockIdx.y * 128;
    const int n0   = blockIdx.x * 128;

    float acc[2][4][4];
    GEMM_MAINLOOP(Ah, Bw)

#pragma unroll
    for (int mt = 0; mt < 2; mt++) {
        const int r = m0 + wm * 32 + mt * 16 + (lane >> 2);
#pragma unroll
        for (int nt = 0; nt < 4; nt++) {
            const int c = n0 + wn * 32 + nt * 8 + (lane & 3) * 2;
            *(float2*)(C + (size_t)r * DMODEL + c) =
                make_float2(acc[mt][nt][0], acc[mt][nt][1]);
            *(float2*)(C + (size_t)(r + 8) * DMODEL + c) =
                make_float2(acc[mt][nt][2], acc[mt][nt][3]);
        }
    }
}

// ---------------------------------------------------------------------------
// HMMA flash attention (unchanged from R10 — passed, known perf).
// ---------------------------------------------------------------------------
#define AROW 272
#define QT_B (64 * AROW)
#define ATTN_SMEM (3 * QT_B)          // Q, K, V

#define MMA2S(s0r, s1r, a, kf)                                                 \
    MMA_F16(s0r, a, (kf)[0], (kf)[2]);                                         \
    MMA_F16(s1r, a, (kf)[1], (kf)[3]);

__global__ __launch_bounds__(128) void attn_mma(const __half* __restrict__ qh,
                                                const __half* __restrict__ kh,
                                                const __half* __restrict__ vh,
                                                __half* __restrict__ oh) {
    extern __shared__ char smem[];
    const uint32_t sbase = smem_to_u32(smem);
    const uint32_t sQ = sbase;
    const uint32_t sK = sbase + QT_B;
    const uint32_t sV = sbase + 2 * QT_B;

    const int h    = blockIdx.y;
    const int q0   = blockIdx.x * 64;
    const int tid  = threadIdx.x;
    const int wid  = tid >> 5;
    const int lane = tid & 31;
    const int lrow = lane & 15;
    const int lcol = (lane >> 4) * 16;
    const float SCALE = 0.088388347648318447f;

    for (int ch = tid; ch < 64 * 16; ch += 128) {
        int row = ch >> 4, c8 = ch & 15;
        size_t g = (size_t)(q0 + row) * DMODEL + h * HDIM + c8 * 8;
        *(uint4*)(smem + (row * AROW + c8 * 16)) = *(const uint4*)(qh + g);
    }

    float O[16][4];
#pragma unroll
    for (int i = 0; i < 16; i++)
#pragma unroll
        for (int r = 0; r < 4; r++) O[i][r] = 0.f;
    float m0 = -1e30f, m1 = -1e30f, l0 = 0.f, l1 = 0.f;

    const int r0g = q0 + wid * 16 + (lane >> 2);
    const int r1g = r0g + 8;
    const int cbeg = max(0, q0 - (WIN - 1)) & ~63;

    for (int c = cbeg; c <= q0; c += 64) {
        __syncthreads();
        for (int ch = tid; ch < 64 * 16; ch += 128) {
            int row = ch >> 4, c8 = ch & 15;
            size_t g = (size_t)(c + row) * DMODEL + h * HDIM + c8 * 8;
            *(uint4*)(smem + QT_B + (row * AROW + c8 * 16))     = *(const uint4*)(kh + g);
            *(uint4*)(smem + 2 * QT_B + (row * AROW + c8 * 16)) = *(const uint4*)(vh + g);
        }
        __syncthreads();

        float S[8][4];
#pragma unroll
        for (int nt = 0; nt < 8; nt++)
#pragma unroll
            for (int r = 0; r < 4; r++) S[nt][r] = 0.f;

#pragma unroll
        for (int ks = 0; ks < 8; ks++) {
            const uint32_t kboff = ks * 32 + lcol;
            uint32_t aQ[4], kC[4], kN[4];
            LDM_X4(aQ, sQ + (wid * 16 + lrow) * AROW + kboff);
            LDM_X4(kC, sK + (lrow) * AROW + kboff);
            LDM_X4(kN, sK + (16 + lrow) * AROW + kboff);
            MMA2S(S[0], S[1], aQ, kC)
            LDM_X4(kC, sK + (32 + lrow) * AROW + kboff);
            MMA2S(S[2], S[3], aQ, kN)
            LDM_X4(kN, sK + (48 + lrow) * AROW + kboff);
            MMA2S(S[4], S[5], aQ, kC)
            MMA2S(S[6], S[7], aQ, kN)
        }

        const bool need_mask = (c + 63 > q0) || (q0 + 63 - c >= WIN);
        if (need_mask) {
#pragma unroll
            for (int nt = 0; nt < 8; nt++) {
                int colb = c + nt * 8 + (lane & 3) * 2;
                if (colb > r0g     || r0g - colb >= WIN)     S[nt][0] = -1e30f;
                if (colb + 1 > r0g || r0g - colb - 1 >= WIN) S[nt][1] = -1e30f;
                if (colb > r1g     || r1g - colb >= WIN)     S[nt][2] = -1e30f;
                if (colb + 1 > r1g || r1g - colb - 1 >= WIN) S[nt][3] = -1e30f;
            }
        }

        float mx0 = -1e30f, mx1 = -1e30f;
#pragma unroll
        for (int nt = 0; nt < 8; nt++) {
            mx0 = fmaxf(mx0, fmaxf(S[nt][0], S[nt][1]));
            mx1 = fmaxf(mx1, fmaxf(S[nt][2], S[nt][3]));
        }
        mx0 = fmaxf(mx0, __shfl_xor_sync(0xffffffffu, mx0, 1));
        mx0 = fmaxf(mx0, __shfl_xor_sync(0xffffffffu, mx0, 2));
        mx1 = fmaxf(mx1, __shfl_xor_sync(0xffffffffu, mx1, 1));
        mx1 = fmaxf(mx1, __shfl_xor_sync(0xffffffffu, mx1, 2));

        float mn0 = fmaxf(m0, mx0 * SCALE);
        float mn1 = fmaxf(m1, mx1 * SCALE);
        float c0 = __expf(m0 - mn0);
        float c1 = __expf(m1 - mn1);
        l0 *= c0; l1 *= c1;
#pragma unroll
        for (int nt = 0; nt < 16; nt++) {
            O[nt][0] *= c0; O[nt][1] *= c0;
            O[nt][2] *= c1; O[nt][3] *= c1;
        }
        m0 = mn0; m1 = mn1;

        uint32_t P[8][2];
#pragma unroll
        for (int nt = 0; nt < 8; nt++) {
            float p0 = __expf(S[nt][0] * SCALE - m0);
            float p1 = __expf(S[nt][1] * SCALE - m0);
            float p2 = __expf(S[nt][2] * SCALE - m1);
            float p3 = __expf(S[nt][3] * SCALE - m1);
            l0 += p0 + p1; l1 += p2 + p3;
            __half2 h01 = __floats2half2_rn(p0, p1);
            __half2 h23 = __floats2half2_rn(p2, p3);
            P[nt][0] = *(uint32_t*)&h01;
            P[nt][1] = *(uint32_t*)&h23;
        }

#pragma unroll
        for (int u = 0; u < 4; u++) {
            uint32_t pa[4] = {P[2 * u][0], P[2 * u][1], P[2 * u + 1][0], P[2 * u + 1][1]};
            const uint32_t vb = sV + (u * 16 + lrow) * AROW + lcol;
            uint32_t vC[4], vN[4];
            LDM_X4_T(vC, vb);
            LDM_X4_T(vN, vb + 32);
            MMA_F16(O[0], pa, vC[0], vC[1]);
            MMA_F16(O[1], pa, vC[2], vC[3]);
            LDM_X4_T(vC, vb + 64);
            MMA_F16(O[2], pa, vN[0], vN[1]);
            MMA_F16(O[3], pa, vN[2], vN[3]);
            LDM_X4_T(vN, vb + 96);
            MMA_F16(O[4], pa, vC[0], vC[1]);
            MMA_F16(O[5], pa, vC[2], vC[3]);
            LDM_X4_T(vC, vb + 128);
            MMA_F16(O[6], pa, vN[0], vN[1]);
            MMA_F16(O[7], pa, vN[2], vN[3]);
            LDM_X4_T(vN, vb + 160);
            MMA_F16(O[8], pa, vC[0], vC[1]);
            MMA_F16(O[9], pa, vC[2], vC[3]);
            LDM_X4_T(vC, vb + 192);
            MMA_F16(O[10], pa, vN[0], vN[1]);
            MMA_F16(O[11], pa, vN[2], vN[3]);
            LDM_X4_T(vN, vb + 224);
            MMA_F16(O[12], pa, vC[0], vC[1]);
            MMA_F16(O[13], pa, vC[2], vC[3]);
            MMA_F16(O[14], pa, vN[0], vN[1]);
            MMA_F16(O[15], pa, vN[2], vN[3]);
        }
    }

    l0 += __shfl_xor_sync(0xffffffffu, l0, 1);
    l0 += __shfl_xor_sync(0xffffffffu, l0, 2);
    l1 += __shfl_xor_sync(0xffffffffu, l1, 1);
    l1 += __shfl_xor_sync(0xffffffffu, l1, 2);
    float inv0 = 1.f / l0;
    float inv1 = 1.f / l1;

#pragma unroll
    for (int nt = 0; nt < 16; nt++) {
        int colb = h * HDIM + nt * 8 + (lane & 3) * 2;
        *(half2*)(oh + (size_t)r0g * DMODEL + colb) =
            __floats2half2_rn(O[nt][0] * inv0, O[nt][1] * inv0);
        *(half2*)(oh + (size_t)r1g * DMODEL + colb) =
            __floats2half2_rn(O[nt][2] * inv1, O[nt][3] * inv1);
    }
}

// ---------------------------------------------------------------------------
// Launch
// ---------------------------------------------------------------------------
extern "C" void kernel_launch(void* const* d_in, const int* in_sizes, int n_in,
                              void* d_out, int out_size) {
    const float* x  = (const float*)d_in[0];
    const float* Wq = (const float*)d_in[1];
    const float* Wk = (const float*)d_in[2];
    const float* Wv = (const float*)d_in[3];
    const float* Wo = (const float*)d_in[4];
    float* out = (float*)d_out;

    __half *xh, *ah, *qhp, *khp, *vhp;
    __half *wq, *wk, *wv, *wo;
    float2* ropetab;
    cudaGetSymbolAddress((void**)&xh, g_xh);
    cudaGetSymbolAddress((void**)&ah, g_ah);
    cudaGetSymbolAddress((void**)&qhp, g_qh);
    cudaGetSymbolAddress((void**)&khp, g_kh);
    cudaGetSymbolAddress((void**)&vhp, g_vh);
    cudaGetSymbolAddress((void**)&wq, g_wq);
    cudaGetSymbolAddress((void**)&wk, g_wk);
    cudaGetSymbolAddress((void**)&wv, g_wv);
    cudaGetSymbolAddress((void**)&wo, g_wo);
    cudaGetSymbolAddress((void**)&ropetab, g_rope);

    cudaFuncSetAttribute(gemm_qkv,
                         cudaFuncAttributeMaxDynamicSharedMemorySize, GEMM_SMEM);
    cudaFuncSetAttribute(gemm_out,
                         cudaFuncAttributeMaxDynamicSharedMemorySize, GEMM_SMEM);
    cudaFuncSetAttribute(attn_mma,
                         cudaFuncAttributeMaxDynamicSharedMemorySize, ATTN_SMEM);

    const int nx8 = S_LEN * DMODEL / 8;
    const int nw8 = DMODEL * DMODEL / 8;
    rope_build<<<(S_LEN * 64 + 255) / 256, 256>>>(ropetab);
    cvt_f16<<<(nx8 + 255) / 256, 256>>>(x, xh, nx8);
    cvt_f16x4<<<dim3((nw8 + 255) / 256, 4), 256>>>(Wq, Wk, Wv, Wo,
                                                   wq, wk, wv, wo, nw8);

    dim3 gqkv(DMODEL / 128, S_LEN / 128, 3);
    gemm_qkv<<<gqkv, 512, GEMM_SMEM>>>(xh, wq, wk, wv, qhp, khp, vhp, ropetab);

    attn_mma<<<dim3(S_LEN / 64, NHEADS), 128, ATTN_SMEM>>>(qhp, khp, vhp, ah);

    dim3 go(DMODEL / 128, S_LEN / 128);
    gemm_out<<<go, 512, GEMM_SMEM>>>(ah, wo, out);
}

// round 13
// speedup vs baseline: 9.3752x; 1.0227x over previous
#include <cuda_runtime.h>
#include <cuda_fp16.h>
#include <math.h>
#include <stdint.h>

#define S_LEN  4096
#define DMODEL 2048
#define NHEADS 16
#define HDIM   128
#define WIN    512

// ---------------------------------------------------------------------------
// Scratch (__device__ globals: allocation-free rule)
// ---------------------------------------------------------------------------
__device__ __half g_xh[S_LEN * DMODEL];
__device__ __half g_ah[S_LEN * DMODEL];
__device__ __half g_qh[S_LEN * DMODEL];
__device__ __half g_kh[S_LEN * DMODEL];
__device__ __half g_vh[S_LEN * DMODEL];
__device__ __half g_wq[DMODEL * DMODEL];
__device__ __half g_wk[DMODEL * DMODEL];
__device__ __half g_wv[DMODEL * DMODEL];
__device__ __half g_wo[DMODEL * DMODEL];
__device__ float2 g_rope[S_LEN * 64];

// ---------------------------------------------------------------------------
// PTX primitives (baseline sm_80+)
// ---------------------------------------------------------------------------
__device__ __forceinline__ uint32_t smem_to_u32(const void* p) {
    uint32_t a;
    asm("{ .reg .u64 t; cvta.to.shared.u64 t, %1; cvt.u32.u64 %0, t; }"
        : "=r"(a) : "l"(p));
    return a;
}

#define CP_ASYNC16(dst, src) \
    asm volatile("cp.async.cg.shared.global [%0], [%1], 16;" \
        :: "r"(dst), "l"(src) : "memory")
#define CP_COMMIT() asm volatile("cp.async.commit_group;" ::: "memory")
#define CP_WAIT1()  asm volatile("cp.async.wait_group 1;" ::: "memory")
#define CP_WAIT0()  asm volatile("cp.async.wait_group 0;" ::: "memory")

#define LDM_X4(r, addr) \
    asm volatile("ldmatrix.sync.aligned.m8n8.x4.shared.b16 {%0,%1,%2,%3}, [%4];" \
        : "=r"((r)[0]), "=r"((r)[1]), "=r"((r)[2]), "=r"((r)[3]) : "r"(addr))

#define LDM_X4_T(r, addr) \
    asm volatile("ldmatrix.sync.aligned.m8n8.x4.trans.shared.b16 {%0,%1,%2,%3}, [%4];" \
        : "=r"((r)[0]), "=r"((r)[1]), "=r"((r)[2]), "=r"((r)[3]) : "r"(addr))

#define MMA_F16(c, a, b0, b1) \
    asm volatile("mma.sync.aligned.m16n8k16.row.col.f32.f16.f16.f32 " \
        "{%0,%1,%2,%3}, {%4,%5,%6,%7}, {%8,%9}, {%0,%1,%2,%3};" \
        : "+f"((c)[0]), "+f"((c)[1]), "+f"((c)[2]), "+f"((c)[3]) \
        : "r"((a)[0]), "r"((a)[1]), "r"((a)[2]), "r"((a)[3]), "r"(b0), "r"(b1))

// ---------------------------------------------------------------------------
// RoPE cos/sin table
// ---------------------------------------------------------------------------
__global__ __launch_bounds__(256) void rope_build(float2* __restrict__ tab) {
    int idx = blockIdx.x * blockDim.x + threadIdx.x;
    if (idx >= S_LEN * 64) return;
    int t = idx & 63;
    int s = idx >> 6;
    float ang = (float)s * exp2f(-(float)t * 0.20762050593045702f);
    float sn, cs;
    sincosf(ang, &sn, &cs);
    tab[idx] = make_float2(cs, sn);
}

// ---------------------------------------------------------------------------
// fp32 -> fp16 single, 8 elems/thread
// ---------------------------------------------------------------------------
__global__ __launch_bounds__(256) void cvt_f16(const float* __restrict__ src,
                                               __half* __restrict__ dst, int n8) {
    int i = blockIdx.x * blockDim.x + threadIdx.x;
    if (i >= n8) return;
    const float4* s4 = (const float4*)src + 2 * (size_t)i;
    float4 a = s4[0], b = s4[1];
    float v[8] = {a.x, a.y, a.z, a.w, b.x, b.y, b.z, b.w};
    __align__(16) __half h[8];
#pragma unroll
    for (int j = 0; j < 8; j++) h[j] = __float2half_rn(v[j]);
    ((uint4*)dst)[i] = *(const uint4*)h;
}

// Four weight matrices fp32 -> fp16 in one launch
__global__ __launch_bounds__(256) void cvt_f16x4(
    const float* __restrict__ s0, const float* __restrict__ s1,
    const float* __restrict__ s2, const float* __restrict__ s3,
    __half* __restrict__ d0, __half* __restrict__ d1,
    __half* __restrict__ d2, __half* __restrict__ d3, int n8) {
    int i = blockIdx.x * blockDim.x + threadIdx.x;
    if (i >= n8) return;
    const int w = blockIdx.y;
    const float* src = (w == 0) ? s0 : (w == 1) ? s1 : (w == 2) ? s2 : s3;
    __half* dst = (w == 0) ? d0 : (w == 1) ? d1 : (w == 2) ? d2 : d3;
    const float4* s4 = (const float4*)src + 2 * (size_t)i;
    float4 a = s4[0], b = s4[1];
    float v[8] = {a.x, a.y, a.z, a.w, b.x, b.y, b.z, b.w};
    __align__(16) __half h[8];
#pragma unroll
    for (int j = 0; j < 8; j++) h[j] = __float2half_rn(v[j]);
    ((uint4*)dst)[i] = *(const uint4*)h;
}

// ---------------------------------------------------------------------------
// Shared GEMM mainloop: 512 threads, 16 warps, warp-tile 32x32, BK=64
// (32 iterations; per-iter sync/convoy cost amortized over 2x MMA work).
// Row pitch 144B = 9 x 16B chunks (9 coprime 8 -> ldmatrix conflict-free).
// Requires in scope: smem, sbase, tid, lane, wm, wn, m0, n0, acc[2][4][4].
// ---------------------------------------------------------------------------
#define GK DMODEL
#define NI (GK / 64)                 // 32 iterations
#define PAD_ROW_B 144                // 64 fp16 (128B) + 16B pad
#define TILE_B (128 * PAD_ROW_B)     // 18432
#define STAGE_B (2 * TILE_B)         // A, B = 36864
#define GEMM_SMEM (3 * STAGE_B)      // 110592

#define GEMM_MAINLOOP(AP, BP)                                                  \
    const __half* gsrc[2] = {                                                  \
        (AP) + (size_t)m0 * GK, (BP) + (size_t)n0 * GK};                       \
    int l_tile[4], l_row[4], l_c16[4];                                         \
    _Pragma("unroll")                                                          \
    for (int t = 0; t < 4; t++) {                                              \
        int linear = t * 512 + tid;      /* 2048 chunks per stage */           \
        l_tile[t] = linear >> 10;        /* 1024 chunks per tile  */           \
        int within = linear & 1023;                                            \
        l_row[t] = within >> 3;                                                \
        l_c16[t] = within & 7;                                                 \
    }                                                                          \
    _Pragma("unroll")                                                          \
    for (int s = 0; s < 2; s++) {                                              \
        const uint32_t sb = sbase + s * STAGE_B;                               \
        const int k0 = s * 64;                                                 \
        _Pragma("unroll")                                                      \
        for (int t = 0; t < 4; t++) {                                          \
            const __half* src =                                                \
                gsrc[l_tile[t]] + (size_t)l_row[t] * GK + k0 + l_c16[t] * 8;   \
            uint32_t dst = sb + l_tile[t] * TILE_B +                           \
                           l_row[t] * PAD_ROW_B + l_c16[t] * 16;               \
            CP_ASYNC16(dst, src);                                              \
        }                                                                      \
        CP_COMMIT();                                                           \
    }                                                                          \
    _Pragma("unroll")                                                          \
    for (int i = 0; i < 2; i++)                                                \
        _Pragma("unroll")                                                      \
        for (int j = 0; j < 4; j++)                                            \
            _Pragma("unroll")                                                  \
            for (int r = 0; r < 4; r++) acc[i][j][r] = 0.f;                    \
    const int lrow = lane & 15;                                                \
    const int lcol = (lane >> 4) * 16;                                         \
    for (int i = 0; i < NI; i++) {                                             \
        if (i < NI - 1) { CP_WAIT1(); } else { CP_WAIT0(); }                   \
        __syncthreads();                                                       \
        if (i + 2 < NI) {                                                      \
            const int k0n = (i + 2) * 64;                                      \
            const uint32_t sb = sbase + ((i + 2) % 3) * STAGE_B;               \
            _Pragma("unroll")                                                  \
            for (int t = 0; t < 4; t++) {                                      \
                const __half* src = gsrc[l_tile[t]] +                          \
                    (size_t)l_row[t] * GK + k0n + l_c16[t] * 8;                \
                uint32_t dst = sb + l_tile[t] * TILE_B +                       \
                               l_row[t] * PAD_ROW_B + l_c16[t] * 16;           \
                CP_ASYNC16(dst, src);                                          \
            }                                                                  \
            CP_COMMIT();                                                       \
        }                                                                      \
        const uint32_t sA = sbase + (i % 3) * STAGE_B;                         \
        _Pragma("unroll")                                                      \
        for (int ks = 0; ks < 4; ks++) {                                       \
            const uint32_t kb = ks * 32 + lcol;                                \
            uint32_t b[4][2];                                                  \
            _Pragma("unroll")                                                  \
            for (int j = 0; j < 2; j++) {                                      \
                uint32_t bd = sA + TILE_B +                                    \
                    (wn * 32 + j * 16 + lrow) * PAD_ROW_B + kb;                \
                uint32_t r[4];                                                 \
                LDM_X4(r, bd);                                                 \
                b[2 * j][0] = r[0]; b[2 * j + 1][0] = r[1];                    \
                b[2 * j][1] = r[2]; b[2 * j + 1][1] = r[3];                    \
            }                                                                  \
            _Pragma("unroll")                                                  \
            for (int mt = 0; mt < 2; mt++) {                                   \
                uint32_t ah[4];                                                \
                uint32_t ad = sA + (wm * 32 + mt * 16 + lrow) * PAD_ROW_B + kb;\
                LDM_X4(ah, ad);                                                \
                _Pragma("unroll")                                              \
                for (int nt = 0; nt < 4; nt++) {                               \
                    MMA_F16(acc[mt][nt], ah, b[nt][0], b[nt][1]);              \
                }                                                              \
            }                                                                  \
        }                                                                      \
    }

// ---------------------------------------------------------------------------
// QKV GEMM, single fp16 MMA; fused RoPE epilogue. blockIdx.z: 0=Q, 1=K, 2=V.
// ---------------------------------------------------------------------------
__global__ __launch_bounds__(512, 2) void gemm_qkv(
    const __half* __restrict__ Ah,
    const __half* __restrict__ B0, const __half* __restrict__ B1,
    const __half* __restrict__ B2,
    __half* __restrict__ qh, __half* __restrict__ kh, __half* __restrict__ vh,
    const float2* __restrict__ rope) {
    extern __shared__ char smem[];
    const uint32_t sbase = smem_to_u32(smem);
    const int tid  = threadIdx.x;
    const int wid  = tid >> 5;
    const int lane = tid & 31;
    const int wm   = wid & 3;
    const int wn   = wid >> 2;
    const int m0   = blockIdx.y * 128;
    const int n0   = blockIdx.x * 128;
    const int z    = blockIdx.z;
    const __half* B = (z == 0) ? B0 : (z == 1) ? B1 : B2;

    float acc[2][4][4];
    GEMM_MAINLOOP(Ah, B)

    __half* outp = (z == 0) ? qh : (z == 1) ? kh : vh;
#pragma unroll
    for (int mt = 0; mt < 2; mt++) {
        const int r = m0 + wm * 32 + mt * 16 + (lane >> 2);
#pragma unroll
        for (int nt = 0; nt < 4; nt++) {
            const int c = n0 + wn * 32 + nt * 8 + (lane & 3) * 2;
            const size_t o0 = (size_t)r * DMODEL + c;
            const size_t o1 = (size_t)(r + 8) * DMODEL + c;
            if (z == 2) {
                *(half2*)(outp + o0) = __floats2half2_rn(acc[mt][nt][0], acc[mt][nt][1]);
                *(half2*)(outp + o1) = __floats2half2_rn(acc[mt][nt][2], acc[mt][nt][3]);
            } else {
                const int t = (c & 127) >> 1;
                float2 cs0 = rope[r * 64 + t];
                float2 cs1 = rope[(r + 8) * 64 + t];
                float a1 = acc[mt][nt][0] * cs0.x - acc[mt][nt][1] * cs0.y;
                float a2 = acc[mt][nt][0] * cs0.y + acc[mt][nt][1] * cs0.x;
                float b1 = acc[mt][nt][2] * cs1.x - acc[mt][nt][3] * cs1.y;
                float b2 = acc[mt][nt][2] * cs1.y + acc[mt][nt][3] * cs1.x;
                *(half2*)(outp + o0) = __floats2half2_rn(a1, a2);
                *(half2*)(outp + o1) = __floats2half2_rn(b1, b2);
            }
        }
    }
}

// ---------------------------------------------------------------------------
// Output projection GEMM: single fp16 MMA, fp32 epilogue to d_out.
// ---------------------------------------------------------------------------
__global__ __launch_bounds__(512, 2) void gemm_out(
    const __half* __restrict__ Ah, const __half* __restrict__ Bw,
    float* __restrict__ C) {
    extern __shared__ char smem[];
    const uint32_t sbase = smem_to_u32(smem);
    const int tid  = threadIdx.x;
    const int wid  = tid >> 5;
    const int lane = tid & 31;
    const int wm   = wid & 3;
    const int wn   = wid >> 2;
    const int m0   = blockIdx.y * 128;
    const int n0   = blockIdx.x * 128;

    float acc[2][4][4];
    GEMM_MAINLOOP(Ah, Bw)

#pragma unroll
    for (int mt = 0; mt < 2; mt++) {
        const int r = m0 + wm * 32 + mt * 16 + (lane >> 2);
#pragma unroll
        for (int nt = 0; nt < 4; nt++) {
            const int c = n0 + wn * 32 + nt * 8 + (lane & 3) * 2;
            *(float2*)(C + (size_t)r * DMODEL + c) =
                make_float2(acc[mt][nt][0], acc[mt][nt][1]);
            *(float2*)(C + (size_t)(r + 8) * DMODEL + c) =
                make_float2(acc[mt][nt][2], acc[mt][nt][3]);
        }
    }
}

// ---------------------------------------------------------------------------
// HMMA flash attention (unchanged from R11 — passed, known perf).
// ---------------------------------------------------------------------------
#define AROW 272
#define QT_B (64 * AROW)
#define ATTN_SMEM (3 * QT_B)          // Q, K, V

#define MMA2S(s0r, s1r, a, kf)                                                 \
    MMA_F16(s0r, a, (kf)[0], (kf)[2]);                                         \
    MMA_F16(s1r, a, (kf)[1], (kf)[3]);

__global__ __launch_bounds__(128) void attn_mma(const __half* __restrict__ qh,
                                                const __half* __restrict__ kh,
                                                const __half* __restrict__ vh,
                                                __half* __restrict__ oh) {
    extern __shared__ char smem[];
    const uint32_t sbase = smem_to_u32(smem);
    const uint32_t sQ = sbase;
    const uint32_t sK = sbase + QT_B;
    const uint32_t sV = sbase + 2 * QT_B;

    const int h    = blockIdx.y;
    const int q0   = blockIdx.x * 64;
    const int tid  = threadIdx.x;
    const int wid  = tid >> 5;
    const int lane = tid & 31;
    const int lrow = lane & 15;
    const int lcol = (lane >> 4) * 16;
    const float SCALE = 0.088388347648318447f;

    for (int ch = tid; ch < 64 * 16; ch += 128) {
        int row = ch >> 4, c8 = ch & 15;
        size_t g = (size_t)(q0 + row) * DMODEL + h * HDIM + c8 * 8;
        *(uint4*)(smem + (row * AROW + c8 * 16)) = *(const uint4*)(qh + g);
    }

    float O[16][4];
#pragma unroll
    for (int i = 0; i < 16; i++)
#pragma unroll
        for (int r = 0; r < 4; r++) O[i][r] = 0.f;
    float m0 = -1e30f, m1 = -1e30f, l0 = 0.f, l1 = 0.f;

    const int r0g = q0 + wid * 16 + (lane >> 2);
    const int r1g = r0g + 8;
    const int cbeg = max(0, q0 - (WIN - 1)) & ~63;

    for (int c = cbeg; c <= q0; c += 64) {
        __syncthreads();
        for (int ch = tid; ch < 64 * 16; ch += 128) {
            int row = ch >> 4, c8 = ch & 15;
            size_t g = (size_t)(c + row) * DMODEL + h * HDIM + c8 * 8;
            *(uint4*)(smem + QT_B + (row * AROW + c8 * 16))     = *(const uint4*)(kh + g);
            *(uint4*)(smem + 2 * QT_B + (row * AROW + c8 * 16)) = *(const uint4*)(vh + g);
        }
        __syncthreads();

        float S[8][4];
#pragma unroll
        for (int nt = 0; nt < 8; nt++)
#pragma unroll
            for (int r = 0; r < 4; r++) S[nt][r] = 0.f;

#pragma unroll
        for (int ks = 0; ks < 8; ks++) {
            const uint32_t kboff = ks * 32 + lcol;
            uint32_t aQ[4], kC[4], kN[4];
            LDM_X4(aQ, sQ + (wid * 16 + lrow) * AROW + kboff);
            LDM_X4(kC, sK + (lrow) * AROW + kboff);
            LDM_X4(kN, sK + (16 + lrow) * AROW + kboff);
            MMA2S(S[0], S[1], aQ, kC)
            LDM_X4(kC, sK + (32 + lrow) * AROW + kboff);
            MMA2S(S[2], S[3], aQ, kN)
            LDM_X4(kN, sK + (48 + lrow) * AROW + kboff);
            MMA2S(S[4], S[5], aQ, kC)
            MMA2S(S[6], S[7], aQ, kN)
        }

        const bool need_mask = (c + 63 > q0) || (q0 + 63 - c >= WIN);
        if (need_mask) {
#pragma unroll
            for (int nt = 0; nt < 8; nt++) {
                int colb = c + nt * 8 + (lane & 3) * 2;
                if (colb > r0g     || r0g - colb >= WIN)     S[nt][0] = -1e30f;
                if (colb + 1 > r0g || r0g - colb - 1 >= WIN) S[nt][1] = -1e30f;
                if (colb > r1g     || r1g - colb >= WIN)     S[nt][2] = -1e30f;
                if (colb + 1 > r1g || r1g - colb - 1 >= WIN) S[nt][3] = -1e30f;
            }
        }

        float mx0 = -1e30f, mx1 = -1e30f;
#pragma unroll
        for (int nt = 0; nt < 8; nt++) {
            mx0 = fmaxf(mx0, fmaxf(S[nt][0], S[nt][1]));
            mx1 = fmaxf(mx1, fmaxf(S[nt][2], S[nt][3]));
        }
        mx0 = fmaxf(mx0, __shfl_xor_sync(0xffffffffu, mx0, 1));
        mx0 = fmaxf(mx0, __shfl_xor_sync(0xffffffffu, mx0, 2));
        mx1 = fmaxf(mx1, __shfl_xor_sync(0xffffffffu, mx1, 1));
        mx1 = fmaxf(mx1, __shfl_xor_sync(0xffffffffu, mx1, 2));

        float mn0 = fmaxf(m0, mx0 * SCALE);
        float mn1 = fmaxf(m1, mx1 * SCALE);
        float c0 = __expf(m0 - mn0);
        float c1 = __expf(m1 - mn1);
        l0 *= c0; l1 *= c1;
#pragma unroll
        for (int nt = 0; nt < 16; nt++) {
            O[nt][0] *= c0; O[nt][1] *= c0;
            O[nt][2] *= c1; O[nt][3] *= c1;
        }
        m0 = mn0; m1 = mn1;

        uint32_t P[8][2];
#pragma unroll
        for (int nt = 0; nt < 8; nt++) {
            float p0 = __expf(S[nt][0] * SCALE - m0);
            float p1 = __expf(S[nt][1] * SCALE - m0);
            float p2 = __expf(S[nt][2] * SCALE - m1);
            float p3 = __expf(S[nt][3] * SCALE - m1);
            l0 += p0 + p1; l1 += p2 + p3;
            __half2 h01 = __floats2half2_rn(p0, p1);
            __half2 h23 = __floats2half2_rn(p2, p3);
            P[nt][0] = *(uint32_t*)&h01;
            P[nt][1] = *(uint32_t*)&h23;
        }

#pragma unroll
        for (int u = 0; u < 4; u++) {
            uint32_t pa[4] = {P[2 * u][0], P[2 * u][1], P[2 * u + 1][0], P[2 * u + 1][1]};
            const uint32_t vb = sV + (u * 16 + lrow) * AROW + lcol;
            uint32_t vC[4], vN[4];
            LDM_X4_T(vC, vb);
            LDM_X4_T(vN, vb + 32);
            MMA_F16(O[0], pa, vC[0], vC[1]);
            MMA_F16(O[1], pa, vC[2], vC[3]);
            LDM_X4_T(vC, vb + 64);
            MMA_F16(O[2], pa, vN[0], vN[1]);
            MMA_F16(O[3], pa, vN[2], vN[3]);
            LDM_X4_T(vN, vb + 96);
            MMA_F16(O[4], pa, vC[0], vC[1]);
            MMA_F16(O[5], pa, vC[2], vC[3]);
            LDM_X4_T(vC, vb + 128);
            MMA_F16(O[6], pa, vN[0], vN[1]);
            MMA_F16(O[7], pa, vN[2], vN[3]);
            LDM_X4_T(vN, vb + 160);
            MMA_F16(O[8], pa, vC[0], vC[1]);
            MMA_F16(O[9], pa, vC[2], vC[3]);
            LDM_X4_T(vC, vb + 192);
            MMA_F16(O[10], pa, vN[0], vN[1]);
            MMA_F16(O[11], pa, vN[2], vN[3]);
            LDM_X4_T(vN, vb + 224);
            MMA_F16(O[12], pa, vC[0], vC[1]);
            MMA_F16(O[13], pa, vC[2], vC[3]);
            MMA_F16(O[14], pa, vN[0], vN[1]);
            MMA_F16(O[15], pa, vN[2], vN[3]);
        }
    }

    l0 += __shfl_xor_sync(0xffffffffu, l0, 1);
    l0 += __shfl_xor_sync(0xffffffffu, l0, 2);
    l1 += __shfl_xor_sync(0xffffffffu, l1, 1);
    l1 += __shfl_xor_sync(0xffffffffu, l1, 2);
    float inv0 = 1.f / l0;
    float inv1 = 1.f / l1;

#pragma unroll
    for (int nt = 0; nt < 16; nt++) {
        int colb = h * HDIM + nt * 8 + (lane & 3) * 2;
        *(half2*)(oh + (size_t)r0g * DMODEL + colb) =
            __floats2half2_rn(O[nt][0] * inv0, O[nt][1] * inv0);
        *(half2*)(oh + (size_t)r1g * DMODEL + colb) =
            __floats2half2_rn(O[nt][2] * inv1, O[nt][3] * inv1);
    }
}

// ---------------------------------------------------------------------------
// Launch
// ---------------------------------------------------------------------------
extern "C" void kernel_launch(void* const* d_in, const int* in_sizes, int n_in,
                              void* d_out, int out_size) {
    const float* x  = (const float*)d_in[0];
    const float* Wq = (const float*)d_in[1];
    const float* Wk = (const float*)d_in[2];
    const float* Wv = (const float*)d_in[3];
    const float* Wo = (const float*)d_in[4];
    float* out = (float*)d_out;

    __half *xh, *ah, *qhp, *khp, *vhp;
    __half *wq, *wk, *wv, *wo;
    float2* ropetab;
    cudaGetSymbolAddress((void**)&xh, g_xh);
    cudaGetSymbolAddress((void**)&ah, g_ah);
    cudaGetSymbolAddress((void**)&qhp, g_qh);
    cudaGetSymbolAddress((void**)&khp, g_kh);
    cudaGetSymbolAddress((void**)&vhp, g_vh);
    cudaGetSymbolAddress((void**)&wq, g_wq);
    cudaGetSymbolAddress((void**)&wk, g_wk);
    cudaGetSymbolAddress((void**)&wv, g_wv);
    cudaGetSymbolAddress((void**)&wo, g_wo);
    cudaGetSymbolAddress((void**)&ropetab, g_rope);

    cudaFuncSetAttribute(gemm_qkv,
                         cudaFuncAttributeMaxDynamicSharedMemorySize, GEMM_SMEM);
    cudaFuncSetAttribute(gemm_out,
                         cudaFuncAttributeMaxDynamicSharedMemorySize, GEMM_SMEM);
    cudaFuncSetAttribute(attn_mma,
                         cudaFuncAttributeMaxDynamicSharedMemorySize, ATTN_SMEM);

    const int nx8 = S_LEN * DMODEL / 8;
    const int nw8 = DMODEL * DMODEL / 8;
    rope_build<<<(S_LEN * 64 + 255) / 256, 256>>>(ropetab);
    cvt_f16<<<(nx8 + 255) / 256, 256>>>(x, xh, nx8);
    cvt_f16x4<<<dim3((nw8 + 255) / 256, 4), 256>>>(Wq, Wk, Wv, Wo,
                                                   wq, wk, wv, wo, nw8);

    dim3 gqkv(DMODEL / 128, S_LEN / 128, 3);
    gemm_qkv<<<gqkv, 512, GEMM_SMEM>>>(xh, wq, wk, wv, qhp, khp, vhp, ropetab);

    attn_mma<<<dim3(S_LEN / 64, NHEADS), 128, ATTN_SMEM>>>(qhp, khp, vhp, ah);

    dim3 go(DMODEL / 128, S_LEN / 128);
    gemm_out<<<go, 512, GEMM_SMEM>>>(ah, wo, out);
}